// round 13
// baseline (speedup 1.0000x reference)
#include <cuda_runtime.h>
#include <cuda_bf16.h>
#include <cuda_fp16.h>
#include <math.h>
#include <stdint.h>

// ---------------- scratch layout (floats) ----------------
#define OFF_INP      0ul
#define OFF_QKV      2097152ul
#define OFF_Q        5242880ul
#define OFF_K        7340032ul
#define OFF_KRH      7864320ul
#define OFF_VH       8126464ul
#define OFF_V        8388608ul
#define OFF_KHID     8912896ul
#define OFF_VHID     9437184ul
#define OFF_CKRAW    9961472ul
#define OFF_CVRAW    9969664ul
#define OFF_CK       9977856ul
#define OFF_CV       9986304ul
#define OFF_COUT     9994752ul
#define OFF_FOUT    12091904ul
#define OFF_SOUT    14189056ul
#define OFF_IMP     16286208ul
#define OFF_SELVAL  16548352ul
#define OFF_GATES   16564736ul
#define OFF_PM      16663040ul
#define OFF_PART    16663296ul
#define OFF_WQKV_HI 20857600ul
#define OFF_WQKV_LO 21054208ul
#define OFF_WO_HI   21250816ul
#define OFF_WO_LO   21381888ul
#define OFF_INP_HI  21512960ul
#define OFF_INP_LO  22561536ul
#define OFF_KBM_HI  23610112ul
#define OFF_KBM_LO  23872256ul
#define OFF_VBM_HI  24134400ul
#define OFF_VBM_LO  24396544ul
#define OFF_COMB_HI 24658688ul
#define OFF_COMB_LO 25707264ul
#define SCRATCH_SZ  26755840ul

__device__ float g_scratch[SCRATCH_SZ];
__device__ int   g_selidx[2 * 2 * 2048 * 2];

// ================= helpers ============
__device__ __forceinline__ uint32_t smem_u32(const void* p) {
    uint32_t a;
    asm("{ .reg .u64 tmp; cvta.to.shared.u64 tmp, %1; cvt.u32.u64 %0, tmp; }"
        : "=r"(a) : "l"(p));
    return a;
}
__device__ __forceinline__ void ldsm_x4(uint32_t& r0, uint32_t& r1, uint32_t& r2, uint32_t& r3,
                                        uint32_t addr) {
    asm volatile("ldmatrix.sync.aligned.m8n8.x4.shared.b16 {%0,%1,%2,%3}, [%4];"
                 : "=r"(r0), "=r"(r1), "=r"(r2), "=r"(r3) : "r"(addr));
}
__device__ __forceinline__ void ldsm_x4t(uint32_t& r0, uint32_t& r1, uint32_t& r2, uint32_t& r3,
                                         uint32_t addr) {
    asm volatile("ldmatrix.sync.aligned.m8n8.x4.trans.shared.b16 {%0,%1,%2,%3}, [%4];"
                 : "=r"(r0), "=r"(r1), "=r"(r2), "=r"(r3) : "r"(addr));
}
__device__ __forceinline__ void mma16816(float* c, uint32_t a0, uint32_t a1, uint32_t a2,
                                         uint32_t a3, uint32_t b0, uint32_t b1) {
    asm volatile("mma.sync.aligned.m16n8k16.row.col.f32.bf16.bf16.f32 "
                 "{%0,%1,%2,%3}, {%4,%5,%6,%7}, {%8,%9}, {%0,%1,%2,%3};"
                 : "+f"(c[0]), "+f"(c[1]), "+f"(c[2]), "+f"(c[3])
                 : "r"(a0), "r"(a1), "r"(a2), "r"(a3), "r"(b0), "r"(b1));
}
__device__ __forceinline__ void bf_split_pack(float x0, float x1, uint32_t& hp, uint32_t& lp) {
    uint32_t u0 = __float_as_uint(x0), u1 = __float_as_uint(x1);
    hp = __byte_perm(u0, u1, 0x7632);
    float l0 = x0 - __uint_as_float(u0 & 0xFFFF0000u);
    float l1 = x1 - __uint_as_float(u1 & 0xFFFF0000u);
    asm("cvt.rn.bf16x2.f32 %0, %1, %2;" : "=r"(lp) : "f"(l1), "f"(l0));
}
__device__ __forceinline__ void cp16(uint32_t s, const void* g) {
    asm volatile("cp.async.cg.shared.global [%0], [%1], 16;" :: "r"(s), "l"(g));
}

// ---------------- weight conversion (Wqkv + Wo only) ----------------
__global__ void k_cvtw(const float* __restrict__ Wqkv, const float* __restrict__ Wo) {
    size_t q = (size_t)blockIdx.x * 256 + threadIdx.x;   // float4 units
    if (q >= 163840ul) return;
    const float* src;
    uint32_t *hi, *lo;
    size_t local;
    if (q < 98304ul) {
        src = Wqkv; local = q;
        hi = (uint32_t*)(g_scratch + OFF_WQKV_HI); lo = (uint32_t*)(g_scratch + OFF_WQKV_LO);
    } else {
        src = Wo; local = q - 98304ul;
        hi = (uint32_t*)(g_scratch + OFF_WO_HI); lo = (uint32_t*)(g_scratch + OFF_WO_LO);
    }
    float4 v = ((const float4*)src)[local];
    uint32_t h0, l0, h1, l1;
    bf_split_pack(v.x, v.y, h0, l0);
    bf_split_pack(v.z, v.w, h1, l1);
    ((uint2*)hi)[local] = make_uint2(h0, h1);
    ((uint2*)lo)[local] = make_uint2(l0, l1);
}

// ======== cp.async pipelined bf16x3 MMA GEMM, templated N-tile (preconv B) ====
#define APAD 40
extern __shared__ uint16_t mgs[];
template <int NTILES>
__global__ void __launch_bounds__(256, 2)
k_mgemm(const uint16_t* __restrict__ Ahi0, const uint16_t* __restrict__ Alo0,
        const uint16_t* __restrict__ Bhi0, const uint16_t* __restrict__ Blo0,
        float* __restrict__ C0,
        int N, int K, int klen, int nchunks) {
    constexpr int BN = NTILES * 32;
    constexpr int BPADT = BN + 8;
    constexpr int BOFF = 10240;
    constexpr int BLO = BOFF + 32 * BPADT;
    constexpr int BUF = BLO + 32 * BPADT;
    uint32_t sb = smem_u32(mgs);
    int chunk = blockIdx.z;
    float* C = C0 + (size_t)chunk * gridDim.y * 128 * N;
    int kstart = chunk * klen;
    int t = threadIdx.x, wid = t >> 5, lane = t & 31;
    int bx = blockIdx.x, by = blockIdx.y;
    int warp_m = wid >> 2, warp_n = wid & 3;

    float acc[4][NTILES][4];
#pragma unroll
    for (int mt = 0; mt < 4; mt++)
#pragma unroll
        for (int nt = 0; nt < NTILES; nt++)
#pragma unroll
            for (int e = 0; e < 4; e++) acc[mt][nt][e] = 0.f;

    int a_row = (lane & 15), a_kc8 = 8 * (lane >> 4);
    int b_krow = (lane & 15), b_n8 = 8 * (lane >> 4);
    int nch = klen / 32;
    const uint16_t* Ah = Ahi0 + (size_t)(by * 128) * K + kstart;
    const uint16_t* Al = Alo0 + (size_t)(by * 128) * K + kstart;
    const uint16_t* Bh = Bhi0 + (size_t)kstart * N + bx * BN;
    const uint16_t* Bl = Blo0 + (size_t)kstart * N + bx * BN;

    auto stage = [&](int buf, int cc) {
        uint32_t soff = sb + buf * (BUF * 2);
#pragma unroll
        for (int h = 0; h < 2; h++) {
            int u = t + h * 256;
            int row = u >> 2, seg = u & 3;
            size_t go = (size_t)row * K + (size_t)cc * 32 + seg * 8;
            cp16(soff + (row * APAD + seg * 8) * 2, Ah + go);
            cp16(soff + (5120 + row * APAD + seg * 8) * 2, Al + go);
        }
#pragma unroll
        for (int h = 0; h < NTILES / 2; h++) {
            int u = t + h * 256;
            int row, seg;
            if (NTILES == 4) { row = u >> 4; seg = u & 15; }
            else { row = u >> 3; seg = u & 7; }
            size_t go = (size_t)(cc * 32 + row) * N + seg * 8;
            cp16(soff + (BOFF + row * BPADT + seg * 8) * 2, Bh + go);
            cp16(soff + (BLO + row * BPADT + seg * 8) * 2, Bl + go);
        }
        asm volatile("cp.async.commit_group;" ::: "memory");
    };

    stage(0, 0);
    for (int c = 0; c < nch; c++) {
        int buf = c & 1;
        if (c + 1 < nch) {
            stage(buf ^ 1, c + 1);
            asm volatile("cp.async.wait_group 1;" ::: "memory");
        } else {
            asm volatile("cp.async.wait_group 0;" ::: "memory");
        }
        __syncthreads();
        uint32_t abase = sb + buf * (BUF * 2);
#pragma unroll
        for (int ks = 0; ks < 2; ks++) {
            uint32_t af[4][4], bh[NTILES][2], bl[NTILES][2];
#pragma unroll
            for (int mt = 0; mt < 4; mt++) {
                int off = (warp_m * 64 + mt * 16 + a_row) * APAD + ks * 16 + a_kc8;
                ldsm_x4(af[mt][0], af[mt][1], af[mt][2], af[mt][3], abase + off * 2);
            }
#pragma unroll
            for (int n2 = 0; n2 < NTILES / 2; n2++) {
                int off = BOFF + (ks * 16 + b_krow) * BPADT + warp_n * (NTILES * 8) + n2 * 16 + b_n8;
                ldsm_x4t(bh[n2 * 2][0], bh[n2 * 2][1], bh[n2 * 2 + 1][0], bh[n2 * 2 + 1][1],
                         abase + off * 2);
                ldsm_x4t(bl[n2 * 2][0], bl[n2 * 2][1], bl[n2 * 2 + 1][0], bl[n2 * 2 + 1][1],
                         abase + (off + 32 * BPADT) * 2);
            }
#pragma unroll
            for (int mt = 0; mt < 4; mt++)
#pragma unroll
                for (int nt = 0; nt < NTILES; nt++) {
                    mma16816(acc[mt][nt], af[mt][0], af[mt][1], af[mt][2], af[mt][3],
                             bh[nt][0], bh[nt][1]);
                    mma16816(acc[mt][nt], af[mt][0], af[mt][1], af[mt][2], af[mt][3],
                             bl[nt][0], bl[nt][1]);
                }
#pragma unroll
            for (int mt = 0; mt < 4; mt++) {
                int off = 5120 + (warp_m * 64 + mt * 16 + a_row) * APAD + ks * 16 + a_kc8;
                ldsm_x4(af[mt][0], af[mt][1], af[mt][2], af[mt][3], abase + off * 2);
            }
#pragma unroll
            for (int mt = 0; mt < 4; mt++)
#pragma unroll
                for (int nt = 0; nt < NTILES; nt++)
                    mma16816(acc[mt][nt], af[mt][0], af[mt][1], af[mt][2], af[mt][3],
                             bh[nt][0], bh[nt][1]);
        }
        __syncthreads();
    }
    int g = lane >> 2, tid4 = lane & 3;
#pragma unroll
    for (int mt = 0; mt < 4; mt++) {
        int row0 = by * 128 + warp_m * 64 + mt * 16 + g;
#pragma unroll
        for (int nt = 0; nt < NTILES; nt++) {
            int col = bx * BN + warp_n * (NTILES * 8) + nt * 8 + tid4 * 2;
            *(float2*)&C[(size_t)row0 * N + col] = make_float2(acc[mt][nt][0], acc[mt][nt][1]);
            *(float2*)&C[(size_t)(row0 + 8) * N + col] = make_float2(acc[mt][nt][2], acc[mt][nt][3]);
        }
    }
}
#define MG_SMEM2 ((10240 + 2 * 32 * 72) * 4)

// ======== c1 GEMM: A preconv bf16 (cp.async), B fp32 (cp.async + smem convert) ====
#define WG_BPADT 136
#define WG_BOFF  10240
#define WG_BLO   (WG_BOFF + 32 * WG_BPADT)
#define WG_BUF   (WG_BLO + 32 * WG_BPADT)
#define WG_SLOT0 (2 * WG_BUF * 2)
#define WG_SMEM  (WG_SLOT0 + 2 * 16384)
extern __shared__ uint16_t wgs[];
__global__ void __launch_bounds__(256, 2)
k_wgemm(const uint16_t* __restrict__ Ahi0, const uint16_t* __restrict__ Alo0,
        const float* __restrict__ Bf0, float* __restrict__ C0,
        const uint16_t* __restrict__ Ahi1, const uint16_t* __restrict__ Alo1,
        const float* __restrict__ Bf1, float* __restrict__ C1,
        int N, int K, int klen, int nchunks) {
    uint32_t sb = smem_u32(wgs);
    int z = blockIdx.z;
    int comp = z / nchunks, chunk = z - comp * nchunks;
    const uint16_t* Ahi = comp ? Ahi1 : Ahi0;
    const uint16_t* Alo = comp ? Alo1 : Alo0;
    const float* Bf = comp ? Bf1 : Bf0;
    float* C = (comp ? C1 : C0) + (size_t)chunk * 128 * N;
    int kstart = chunk * klen;
    int t = threadIdx.x, wid = t >> 5, lane = t & 31;
    int bx = blockIdx.x;
    int warp_m = wid >> 2, warp_n = wid & 3;

    float acc[4][4][4];
#pragma unroll
    for (int mt = 0; mt < 4; mt++)
#pragma unroll
        for (int nt = 0; nt < 4; nt++)
#pragma unroll
            for (int e = 0; e < 4; e++) acc[mt][nt][e] = 0.f;

    int a_row = (lane & 15), a_kc8 = 8 * (lane >> 4);
    int b_krow = (lane & 15), b_n8 = 8 * (lane >> 4);
    int nch = klen / 32;
    const uint16_t* Ah = Ahi + kstart;
    const uint16_t* Al = Alo + kstart;
    const float* Bb = Bf + (size_t)kstart * N + bx * 128;

    auto stageA = [&](int buf, int cc) {
        uint32_t soff = sb + buf * (WG_BUF * 2);
#pragma unroll
        for (int h = 0; h < 2; h++) {
            int u = t + h * 256;
            int row = u >> 2, seg = u & 3;
            size_t go = (size_t)row * K + (size_t)cc * 32 + seg * 8;
            cp16(soff + (row * APAD + seg * 8) * 2, Ah + go);
            cp16(soff + (5120 + row * APAD + seg * 8) * 2, Al + go);
        }
    };
    auto stageB = [&](int buf, int cc) {
        uint32_t soff = sb + WG_SLOT0 + buf * 16384;
#pragma unroll
        for (int h = 0; h < 4; h++) {
            int u = t + h * 256;
            int row = u >> 5, seg = u & 31;
            cp16(soff + u * 16, Bb + (size_t)(cc * 32 + row) * N + seg * 4);
        }
    };

    stageA(0, 0);
    stageB(0, 0);
    asm volatile("cp.async.commit_group;" ::: "memory");
    for (int c = 0; c < nch; c++) {
        int buf = c & 1;
        asm volatile("cp.async.wait_group 0;" ::: "memory");
        __syncthreads();
        {
            const float2* slot = (const float2*)((char*)wgs + WG_SLOT0 + buf * 16384);
            char* bufp = (char*)wgs + buf * (WG_BUF * 2);
#pragma unroll
            for (int p = 0; p < 8; p++) {
                int u2 = t + p * 256;
                int row = u2 >> 6, c2 = u2 & 63;
                float2 v = slot[u2];
                uint32_t hp, lp;
                bf_split_pack(v.x, v.y, hp, lp);
                *(uint32_t*)(bufp + (WG_BOFF + row * WG_BPADT + c2 * 2) * 2) = hp;
                *(uint32_t*)(bufp + (WG_BLO + row * WG_BPADT + c2 * 2) * 2) = lp;
            }
        }
        __syncthreads();
        if (c + 1 < nch) {
            stageA(buf ^ 1, c + 1);
            stageB(buf ^ 1, c + 1);
            asm volatile("cp.async.commit_group;" ::: "memory");
        }
        uint32_t abase = sb + buf * (WG_BUF * 2);
#pragma unroll
        for (int ks = 0; ks < 2; ks++) {
            uint32_t af[4][4], bh[4][2], bl[4][2];
#pragma unroll
            for (int mt = 0; mt < 4; mt++) {
                int off = (warp_m * 64 + mt * 16 + a_row) * APAD + ks * 16 + a_kc8;
                ldsm_x4(af[mt][0], af[mt][1], af[mt][2], af[mt][3], abase + off * 2);
            }
#pragma unroll
            for (int n2 = 0; n2 < 2; n2++) {
                int off = WG_BOFF + (ks * 16 + b_krow) * WG_BPADT + warp_n * 32 + n2 * 16 + b_n8;
                ldsm_x4t(bh[n2 * 2][0], bh[n2 * 2][1], bh[n2 * 2 + 1][0], bh[n2 * 2 + 1][1],
                         abase + off * 2);
                ldsm_x4t(bl[n2 * 2][0], bl[n2 * 2][1], bl[n2 * 2 + 1][0], bl[n2 * 2 + 1][1],
                         abase + (off + 32 * WG_BPADT) * 2);
            }
#pragma unroll
            for (int mt = 0; mt < 4; mt++)
#pragma unroll
                for (int nt = 0; nt < 4; nt++) {
                    mma16816(acc[mt][nt], af[mt][0], af[mt][1], af[mt][2], af[mt][3],
                             bh[nt][0], bh[nt][1]);
                    mma16816(acc[mt][nt], af[mt][0], af[mt][1], af[mt][2], af[mt][3],
                             bl[nt][0], bl[nt][1]);
                }
#pragma unroll
            for (int mt = 0; mt < 4; mt++) {
                int off = 5120 + (warp_m * 64 + mt * 16 + a_row) * APAD + ks * 16 + a_kc8;
                ldsm_x4(af[mt][0], af[mt][1], af[mt][2], af[mt][3], abase + off * 2);
            }
#pragma unroll
            for (int mt = 0; mt < 4; mt++)
#pragma unroll
                for (int nt = 0; nt < 4; nt++)
                    mma16816(acc[mt][nt], af[mt][0], af[mt][1], af[mt][2], af[mt][3],
                             bh[nt][0], bh[nt][1]);
        }
        __syncthreads();
    }
    int g = lane >> 2, tid4 = lane & 3;
#pragma unroll
    for (int mt = 0; mt < 4; mt++) {
        int row0 = warp_m * 64 + mt * 16 + g;
#pragma unroll
        for (int nt = 0; nt < 4; nt++) {
            int col = bx * 128 + warp_n * 32 + nt * 8 + tid4 * 2;
            *(float2*)&C[(size_t)row0 * N + col] = make_float2(acc[mt][nt][0], acc[mt][nt][1]);
            *(float2*)&C[(size_t)(row0 + 8) * N + col] = make_float2(acc[mt][nt][2], acc[mt][nt][3]);
        }
    }
}

// ---------------- c1 split-K reduce + bias + relu ----------------
__global__ void k_c1red(const float* __restrict__ kcb1, const float* __restrict__ vcb1) {
    int u4 = blockIdx.x * 256 + threadIdx.x;
    int comp = u4 >> 17;
    int loc = u4 & 131071;
    int col4 = loc & 1023;
    const float* P = g_scratch + OFF_PART + (size_t)comp * 2097152 + (size_t)loc * 4;
    float4 s0 = *(const float4*)(P);
    float4 s1 = *(const float4*)(P + 524288);
    float4 s2 = *(const float4*)(P + 1048576);
    float4 s3 = *(const float4*)(P + 1572864);
    const float* bias = comp ? vcb1 : kcb1;
    float4 b = *(const float4*)&bias[col4 * 4];
    float4 o;
    o.x = fmaxf(s0.x + s1.x + s2.x + s3.x + b.x, 0.f);
    o.y = fmaxf(s0.y + s1.y + s2.y + s3.y + b.y, 0.f);
    o.z = fmaxf(s0.z + s1.z + s2.z + s3.z + b.z, 0.f);
    o.w = fmaxf(s0.w + s1.w + s2.w + s3.w + b.w, 0.f);
    float* O = g_scratch + (comp ? OFF_VHID : OFF_KHID) + (size_t)loc * 4;
    *(float4*)O = o;
}

// ---------------- pos block means ----------------
__global__ void k_posmean(const float* __restrict__ pos) {
    int blk = blockIdx.x;
    int t = threadIdx.x;
    __shared__ float s[64 * 3];
    s[t * 3 + 0] = pos[(blk * 64 + t) * 3 + 0];
    s[t * 3 + 1] = pos[(blk * 64 + t) * 3 + 1];
    s[t * 3 + 2] = pos[(blk * 64 + t) * 3 + 2];
    __syncthreads();
    if (t < 3) {
        float sum = 0.f;
        for (int i = 0; i < 64; i++) sum += s[i * 3 + t];
        g_scratch[OFF_PM + blk * 3 + t] = sum / 64.f;
    }
}

// ---------------- PE add + RMSNorm (+ bf16 hi/lo output) ----------------
__global__ void k_pe_norm(const float* __restrict__ x, const float* __restrict__ pos,
                          const float* __restrict__ peW, const float* __restrict__ peb,
                          const float* __restrict__ nsc) {
    int r = blockIdx.x;
    int t = threadIdx.x;
    int blk = r >> 6;
    float r0 = pos[r * 3 + 0] - g_scratch[OFF_PM + blk * 3 + 0];
    float r1 = pos[r * 3 + 1] - g_scratch[OFF_PM + blk * 3 + 1];
    float r2 = pos[r * 3 + 2] - g_scratch[OFF_PM + blk * 3 + 2];
    int c0 = t * 2, c1 = c0 + 1;
    float v0 = x[(size_t)r * 512 + c0] + r0 * peW[c0] + r1 * peW[512 + c0] + r2 * peW[1024 + c0] + peb[c0];
    float v1 = x[(size_t)r * 512 + c1] + r0 * peW[c1] + r1 * peW[512 + c1] + r2 * peW[1024 + c1] + peb[c1];
    __shared__ float red[256];
    red[t] = v0 * v0 + v1 * v1;
    __syncthreads();
    for (int s = 128; s > 0; s >>= 1) {
        if (t < s) red[t] += red[t + s];
        __syncthreads();
    }
    float rms = rsqrtf(red[0] / 512.f + 1e-6f);
    float s0 = v0 * rms * nsc[c0];
    float s1 = v1 * rms * nsc[c1];
    g_scratch[OFF_INP + (size_t)r * 512 + c0] = s0;
    g_scratch[OFF_INP + (size_t)r * 512 + c1] = s1;
    uint32_t hp, lp;
    bf_split_pack(s0, s1, hp, lp);
    ((uint32_t*)(g_scratch + OFF_INP_HI))[(size_t)r * 256 + t] = hp;
    ((uint32_t*)(g_scratch + OFF_INP_LO))[(size_t)r * 256 + t] = lp;
}

// ---------------- c2: 4 rows per block (64 blocks) ----------------
#define C2_SMEM ((16384 + 1024) * 4)
extern __shared__ float c2sm[];
__global__ void k_c2(const float* __restrict__ kcW2, const float* __restrict__ kcb2,
                     const float* __restrict__ vcW2, const float* __restrict__ vcb2) {
    float* sa = c2sm;
    float* red = c2sm + 16384;
    int blk = blockIdx.x;
    int comp = blk >> 5, rg = blk & 31;
    const float* A = g_scratch + (comp ? OFF_VHID : OFF_KHID) + (size_t)(rg * 4) * 4096;
    const float* W = comp ? vcW2 : kcW2;
    const float* bias = comp ? vcb2 : kcb2;
    float* Cout = g_scratch + (comp ? OFF_CVRAW : OFF_CKRAW) + (size_t)(rg * 4) * 64;
    int t = threadIdx.x;
    for (int u = t; u < 16384; u += 256) {
        int r = u >> 12, kk = u & 4095;
        sa[kk * 4 + r] = A[(size_t)r * 4096 + kk];
    }
    __syncthreads();
    int o = t & 63, sub = t >> 6;
    const float* Wp = W + (size_t)(sub * 1024) * 64 + o;
    float acc0 = 0.f, acc1 = 0.f, acc2 = 0.f, acc3 = 0.f;
    const float* ap = sa + sub * 1024 * 4;
#pragma unroll 4
    for (int kk = 0; kk < 1024; kk++) {
        float w = Wp[(size_t)kk * 64];
        float4 a = *(const float4*)(ap + kk * 4);
        acc0 += a.x * w; acc1 += a.y * w; acc2 += a.z * w; acc3 += a.w * w;
    }
    red[t * 4 + 0] = acc0; red[t * 4 + 1] = acc1;
    red[t * 4 + 2] = acc2; red[t * 4 + 3] = acc3;
    __syncthreads();
    if (t < 64) {
        float b = bias[t];
#pragma unroll
        for (int r = 0; r < 4; r++) {
            float v = red[t * 4 + r] + red[(64 + t) * 4 + r] + red[(128 + t) * 4 + r] +
                      red[(192 + t) * 4 + r] + b;
            Cout[r * 64 + t] = v;
        }
    }
}

// ---------------- split qkv + rope ----------------
__global__ void k_split_rope() {
    int r = blockIdx.x;
    int b = r >> 11;
    int i = r & 2047;
    int t = threadIdx.x;          // 384
    const float* qkv = g_scratch + OFF_QKV + (size_t)r * 768;
    if (t < 256) {
        int col = t * 2;
        int head = col >> 6, d = col & 63, j = d >> 1;
        float inv = powf(10000.f, -(float)j / 32.f);
        float cs, sn;
        sincosf((float)i * inv, &sn, &cs);
        float a = qkv[col], bb = qkv[col + 1];
        size_t base = (((size_t)(b * 8 + head) * 2048 + i) * 64 + d);
        g_scratch[OFF_Q + base] = a * cs - bb * sn;
        g_scratch[OFF_Q + base + 1] = bb * cs + a * sn;
    } else if (t < 320) {
        int ci = (t - 256) * 2;
        int g = ci >> 6, d = ci & 63, j = d >> 1;
        float inv = powf(10000.f, -(float)j / 32.f);
        float cs, sn;
        sincosf((float)i * inv, &sn, &cs);
        float a = qkv[512 + ci], bb = qkv[512 + ci + 1];
        size_t base = (((size_t)(b * 2 + g) * 2048 + i) * 64 + d);
        g_scratch[OFF_K + base] = a;
        g_scratch[OFF_K + base + 1] = bb;
        float kr0 = a * cs - bb * sn;
        float kr1 = bb * cs + a * sn;
        ((__half2*)(g_scratch + OFF_KRH))[base >> 1] = __floats2half2_rn(kr0, kr1);
    } else {
        int ci = (t - 320) * 2;
        int g = ci >> 6, d = ci & 63;
        size_t base = (((size_t)(b * 2 + g) * 2048 + i) * 64 + d);
        float v0 = qkv[640 + ci], v1 = qkv[640 + ci + 1];
        g_scratch[OFF_V + base] = v0;
        g_scratch[OFF_V + base + 1] = v1;
        ((__half2*)(g_scratch + OFF_VH))[base >> 1] = __floats2half2_rn(v0, v1);
    }
}

// ---------------- build compressor inputs (bf16 hi/lo) ----------------
__global__ void k_buildmats(const float* __restrict__ k_pos, const float* __restrict__ v_pos) {
    int pid = blockIdx.x * blockDim.x + threadIdx.x;
    if (pid >= 262144) return;
    int row = pid >> 11;
    int pcol = pid & 2047;
    int col0 = pcol * 2;
    int bg = row >> 5, wi = row & 31, g = bg & 1;
    int j = col0 >> 6, d = col0 & 63;
    size_t src = ((size_t)bg * 2048 + wi * 64 + j) * 64 + d;
    int poff = (g * 64 + j) * 64 + d;
    float k0 = g_scratch[OFF_K + src] + k_pos[poff];
    float k1 = g_scratch[OFF_K + src + 1] + k_pos[poff + 1];
    float w0 = g_scratch[OFF_V + src] + v_pos[poff];
    float w1 = g_scratch[OFF_V + src + 1] + v_pos[poff + 1];
    uint32_t hp, lp;
    bf_split_pack(k0, k1, hp, lp);
    ((uint32_t*)(g_scratch + OFF_KBM_HI))[pid] = hp;
    ((uint32_t*)(g_scratch + OFF_KBM_LO))[pid] = lp;
    bf_split_pack(w0, w1, hp, lp);
    ((uint32_t*)(g_scratch + OFF_VBM_HI))[pid] = hp;
    ((uint32_t*)(g_scratch + OFF_VBM_LO))[pid] = lp;
}

// ---------------- pack ck/cv with mem token ----------------
__global__ void k_pack(const float* __restrict__ mem_k, const float* __restrict__ mem_v) {
    int idx = blockIdx.x * blockDim.x + threadIdx.x;
    if (idx >= 2 * 2 * 33 * 64) return;
    int d = idx & 63;
    int rest = idx >> 6;
    int j = rest % 33;
    int bg = rest / 33;
    int g = bg & 1;
    float kv, vv;
    if (j == 0) {
        kv = mem_k[g * 64 + d];
        vv = mem_v[g * 64 + d];
    } else {
        size_t s = ((size_t)bg * 32 + (j - 1)) * 64 + d;
        kv = g_scratch[OFF_CKRAW + s];
        vv = g_scratch[OFF_CVRAW + s];
    }
    g_scratch[OFF_CK + idx] = kv;
    g_scratch[OFF_CV + idx] = vv;
}

// ---------------- coarse attention + importance (16 queries/block) ----------
__global__ void __launch_bounds__(256) k_coarse() {
    __shared__ float sck[33 * 64], scv[33 * 64];
    __shared__ float sq[16 * 4 * 64];        // [iq][hq][d]
    __shared__ float sp[16 * 4 * 36];        // [iq][hq][36]
    int blk = blockIdx.x;                    // 512 = bg*128 + grp
    int bg = blk >> 7, grp = blk & 127;
    int i0 = grp * 16;
    int b = bg >> 1, g = bg & 1;
    int t = threadIdx.x;                     // 256
    for (int u = t; u < 528; u += 256) {
        *(float4*)&sck[u * 4] = *(const float4*)&g_scratch[OFF_CK + (size_t)bg * 2112 + u * 4];
        *(float4*)&scv[u * 4] = *(const float4*)&g_scratch[OFF_CV + (size_t)bg * 2112 + u * 4];
    }
    for (int u = t; u < 4096; u += 256) {
        int iq = u >> 8, hq = (u >> 6) & 3, d = u & 63;
        sq[u] = g_scratch[OFF_Q + (((size_t)(b * 8 + g * 4 + hq) * 2048 + i0 + iq) * 64 + d)];
    }
    __syncthreads();
    // QK: 16*4*33 = 2112 score units
    for (int u = t; u < 2112; u += 256) {
        int iq = u / 132, rr = u % 132;
        int hq = rr / 33, j = rr % 33;
        int i = i0 + iq;
        float s = -1e30f;
        if (j == 0 || j * 64 <= i) {
            float acc = 0.f;
            const float4* qv = (const float4*)&sq[(iq * 4 + hq) * 64];
            const float4* kv = (const float4*)&sck[j * 64];
#pragma unroll
            for (int d4 = 0; d4 < 16; d4++) {
                float4 a = qv[d4], bb = kv[d4];
                acc += a.x * bb.x + a.y * bb.y + a.z * bb.z + a.w * bb.w;
            }
            s = acc * 0.125f;
        }
        sp[(iq * 4 + hq) * 36 + j] = s;
    }
    __syncthreads();
    // softmax: 64 rows, one thread each
    if (t < 64) {
        float* row = sp + t * 36;
        float m = -1e30f;
        for (int j = 0; j < 33; j++) m = fmaxf(m, row[j]);
        float sum = 0.f;
        for (int j = 0; j < 33; j++) {
            float e = __expf(row[j] - m);
            row[j] = e;
            sum += e;
        }
        float inv = 1.f / sum;
        for (int j = 0; j < 33; j++) row[j] *= inv;
    }
    __syncthreads();
    // importance: 16*32 = 512 values
    for (int u = t; u < 512; u += 256) {
        int iq = u >> 5, j = u & 31;
        const float* base = sp + iq * 144;
        g_scratch[OFF_IMP + ((size_t)bg * 2048 + i0 + iq) * 32 + j] =
            0.25f * (base[j + 1] + base[36 + j + 1] + base[72 + j + 1] + base[108 + j + 1]);
    }
    // PV: 16*4*64 = 4096 outputs
    for (int u = t; u < 4096; u += 256) {
        int iq = u >> 8, hq = (u >> 6) & 3, d = u & 63;
        const float* pr = sp + (iq * 4 + hq) * 36;
        float acc = 0.f;
#pragma unroll
        for (int j4 = 0; j4 < 8; j4++) {
            float4 p = *(const float4*)&pr[j4 * 4];
            acc += p.x * scv[(j4 * 4 + 0) * 64 + d] + p.y * scv[(j4 * 4 + 1) * 64 + d] +
                   p.z * scv[(j4 * 4 + 2) * 64 + d] + p.w * scv[(j4 * 4 + 3) * 64 + d];
        }
        acc += pr[32] * scv[32 * 64 + d];
        g_scratch[OFF_COUT + (((size_t)(b * 8 + g * 4 + hq) * 2048 + i0 + iq) * 64 + d)] = acc;
    }
}

// ---------------- top-k (k=2, stable) ----------------
__global__ void k_topk() {
    int idx = blockIdx.x * blockDim.x + threadIdx.x;
    if (idx >= 8192) return;
    const float* imp = g_scratch + OFF_IMP + (size_t)idx * 32;
    int i1 = 0;
    float v1 = imp[0];
    for (int j = 1; j < 32; j++)
        if (imp[j] > v1) { v1 = imp[j]; i1 = j; }
    int i2 = -1;
    float v2 = -1e30f;
    for (int j = 0; j < 32; j++) {
        if (j == i1) continue;
        if (imp[j] > v2) { v2 = imp[j]; i2 = j; }
    }
    g_scratch[OFF_SELVAL + idx * 2 + 0] = v1;
    g_scratch[OFF_SELVAL + idx * 2 + 1] = v2;
    g_selidx[idx * 2 + 0] = i1;
    g_selidx[idx * 2 + 1] = i2;
}

// ---------------- fine gathered attention (fp16 smem, reg-cached Q) ----------
#define FINE_SMEM (13824 * 4)
extern __shared__ float fsm[];
__global__ void __launch_bounds__(256, 2) k_fine() {
    __half* skh = (__half*)fsm;
    __half* svh = (__half*)(fsm + 6144);
    float* sq = fsm + 12288;
    float* sp = fsm + 12544;
    float* spart = fsm + 13312;
    int bi = blockIdx.x;
    int bg = bi >> 11, i = bi & 2047;
    int b = bg >> 1, g = bg & 1;
    int t = threadIdx.x;
    int own = i >> 6;
    __shared__ int blkid[3];
    __shared__ int okf[3];
    if (t < 2) {
        int si = g_selidx[bi * 2 + t];
        float sval = g_scratch[OFF_SELVAL + bi * 2 + t];
        blkid[t] = si;
        okf[t] = (sval > 0.f && si != own) ? 1 : 0;
    }
    if (t == 2) { blkid[2] = own; okf[2] = 1; }
    __syncthreads();
    size_t kbase = (size_t)bg * 2048 * 64;
    const uint4* KRH4 = (const uint4*)(g_scratch + OFF_KRH);
    const uint4* VH4 = (const uint4*)(g_scratch + OFF_VH);
#pragma unroll
    for (int u = t; u < 1536; u += 256) {
        int kk = u >> 3, d8 = u & 7;
        int kb = kk >> 6, j = kk & 63;
        size_t elem = kbase + (size_t)(blkid[kb] * 64 + j) * 64 + d8 * 8;
        ((uint4*)skh)[u] = KRH4[elem >> 3];
        ((uint4*)svh)[u] = VH4[elem >> 3];
    }
    {
        int hq = t >> 6, d = t & 63;
        sq[t] = g_scratch[OFF_Q + (((size_t)(b * 8 + g * 4 + hq) * 2048 + i) * 64 + d)];
    }
    __syncthreads();
    {
        int hq = t >> 6, j0 = t & 63;
        float4 qv[16];
        const float4* qsm = (const float4*)&sq[hq * 64];
#pragma unroll
        for (int p = 0; p < 16; p++) qv[p] = qsm[p];
        int ilocal = i & 63;
#pragma unroll
        for (int s = 0; s < 3; s++) {
            int kk = s * 64 + j0;
            bool valid = (s < 2) ? (okf[s] != 0) : (j0 <= ilocal);
            float score = -1e30f;
            if (valid) {
                float acc = 0.f;
                const uint4* kp = (const uint4*)(skh + kk * 64);
#pragma unroll
                for (int p = 0; p < 8; p++) {
                    uint4 raw = kp[p];
                    float2 f0 = __half22float2(*(__half2*)&raw.x);
                    float2 f1 = __half22float2(*(__half2*)&raw.y);
                    float2 f2 = __half22float2(*(__half2*)&raw.z);
                    float2 f3 = __half22float2(*(__half2*)&raw.w);
                    float4 q0 = qv[p * 2], q1 = qv[p * 2 + 1];
                    acc += q0.x * f0.x + q0.y * f0.y + q0.z * f1.x + q0.w * f1.y;
                    acc += q1.x * f2.x + q1.y * f2.y + q1.z * f3.x + q1.w * f3.y;
                }
                score = acc * 0.125f;
            }
            sp[hq * 192 + kk] = score;
        }
    }
    __syncthreads();
    {
        int w = t >> 5, lane = t & 31;
        if (w < 4) {
            float m = -1e30f;
            for (int kk = lane; kk < 192; kk += 32) m = fmaxf(m, sp[w * 192 + kk]);
            for (int o = 16; o; o >>= 1) m = fmaxf(m, __shfl_xor_sync(~0u, m, o));
            float sum = 0.f;
            for (int kk = lane; kk < 192; kk += 32) {
                float e = __expf(sp[w * 192 + kk] - m);
                sp[w * 192 + kk] = e;
                sum += e;
            }
            for (int o = 16; o; o >>= 1) sum += __shfl_xor_sync(~0u, sum, o);
            float inv = 1.f / sum;
            for (int kk = lane; kk < 192; kk += 32) sp[w * 192 + kk] *= inv;
        }
    }
    __syncthreads();
    {
        int part = t >> 7, r = t & 127;
        int hq = r >> 5, d2 = r & 31;
        float ax = 0.f, ay = 0.f;
        const __half2* vp = (const __half2*)svh;
        const float* pr = sp + hq * 192 + part * 96;
#pragma unroll 4
        for (int kk = 0; kk < 96; kk += 4) {
            float4 p = *(const float4*)&pr[kk];
            int kbase2 = (part * 96 + kk) * 32 + d2;
            float2 v0 = __half22float2(vp[kbase2]);
            float2 v1 = __half22float2(vp[kbase2 + 32]);
            float2 v2 = __half22float2(vp[kbase2 + 64]);
            float2 v3 = __half22float2(vp[kbase2 + 96]);
            ax += p.x * v0.x + p.y * v1.x + p.z * v2.x + p.w * v3.x;
            ay += p.x * v0.y + p.y * v1.y + p.z * v2.y + p.w * v3.y;
        }
        spart[(part * 128 + r) * 2] = ax;
        spart[(part * 128 + r) * 2 + 1] = ay;
    }
    __syncthreads();
    if (t < 128) {
        int hq = t >> 5, d2 = t & 31;
        float ox = spart[t * 2] + spart[(128 + t) * 2];
        float oy = spart[t * 2 + 1] + spart[(128 + t) * 2 + 1];
        *(float2*)&g_scratch[OFF_FOUT + (((size_t)(b * 8 + g * 4 + hq) * 2048 + i) * 64 + d2 * 2)] =
            make_float2(ox, oy);
    }
}

// ---------------- sliding attention: register-tiled (fp16 K/V loads) ----------
#define SLIDE_SMEM ((4352 + 16640 + 17408) * 4)
extern __shared__ float ssm2[];
__global__ void k_slide() {
    float* sQt = ssm2;
    float* sKt = ssm2 + 4352;
    float* sS  = ssm2 + 4352 + 16640;
    int id = blockIdx.x;
    int qc = id & 3;
    int tile = (id >> 2) & 7;
    int hh = (id >> 5) & 7;
    int b = id >> 8;
    int g = hh >> 2;
    int t = threadIdx.x;
    size_t kbase = ((size_t)(b * 2 + g) * 2048 + (size_t)tile * 256) * 64;
    size_t qbase = (((size_t)(b * 8 + hh) * 2048) + tile * 256 + qc * 64) * 64;
    const uint32_t* KRH32 = (const uint32_t*)(g_scratch + OFF_KRH);
    const uint32_t* VH32 = (const uint32_t*)(g_scratch + OFF_VH);
    for (int u2 = t; u2 < 8192; u2 += 256) {
        int kk = u2 >> 5, d2 = u2 & 31;
        uint32_t raw = KRH32[(kbase >> 1) + kk * 32 + d2];
        float2 f = __half22float2(*(__half2*)&raw);
        sKt[(2 * d2) * 260 + kk] = f.x;
        sKt[(2 * d2 + 1) * 260 + kk] = f.y;
    }
    for (int u = t; u < 4096; u += 256) {
        int q = u >> 6, d = u & 63;
        sQt[d * 68 + q] = g_scratch[OFF_Q + qbase + u];
    }
    __syncthreads();
    {
        int q0 = (t & 7) * 8, kk0 = (t >> 3) * 8;
        float acc[8][8];
#pragma unroll
        for (int i = 0; i < 8; i++)
#pragma unroll
            for (int j = 0; j < 8; j++) acc[i][j] = 0.f;
        for (int d = 0; d < 64; d++) {
            float a[8], bb[8];
            *(float4*)&a[0] = *(float4*)&sQt[d * 68 + q0];
            *(float4*)&a[4] = *(float4*)&sQt[d * 68 + q0 + 4];
            *(float4*)&bb[0] = *(float4*)&sKt[d * 260 + kk0];
            *(float4*)&bb[4] = *(float4*)&sKt[d * 260 + kk0 + 4];
#pragma unroll
            for (int i = 0; i < 8; i++)
#pragma unroll
                for (int j = 0; j < 8; j++) acc[i][j] += bb[i] * a[j];
        }
#pragma unroll
        for (int i = 0; i < 8; i++)
#pragma unroll
            for (int j = 0; j < 8; j += 4) {
                float4 v = make_float4(acc[i][j] * 0.125f, acc[i][j + 1] * 0.125f,
                                       acc[i][j + 2] * 0.125f, acc[i][j + 3] * 0.125f);
                *(float4*)&sS[(kk0 + i) * 68 + q0 + j] = v;
            }
    }
    __syncthreads();
    {
        int w = t >> 5, lane = t & 31;
#pragma unroll
        for (int qq = 0; qq < 8; qq++) {
            int q = w * 8 + qq;
            float vals[8];
#pragma unroll
            for (int j = 0; j < 8; j++) vals[j] = sS[(lane + j * 32) * 68 + q];
            float m = vals[0];
#pragma unroll
            for (int j = 1; j < 8; j++) m = fmaxf(m, vals[j]);
            for (int o = 16; o; o >>= 1) m = fmaxf(m, __shfl_xor_sync(~0u, m, o));
            float sum = 0.f;
#pragma unroll
            for (int j = 0; j < 8; j++) { vals[j] = __expf(vals[j] - m); sum += vals[j]; }
            for (int o = 16; o; o >>= 1) sum += __shfl_xor_sync(~0u, sum, o);
            float inv = 1.f / sum;
#pragma unroll
            for (int j = 0; j < 8; j++) sS[(lane + j * 32) * 68 + q] = vals[j] * inv;
        }
    }
    __syncthreads();
    for (int u2 = t; u2 < 8192; u2 += 256) {
        uint32_t raw = VH32[(kbase >> 1) + u2];
        *(float2*)&sKt[u2 * 2] = __half22float2(*(__half2*)&raw);
    }
    __syncthreads();
    {
        int pq = (t >> 4) * 4, pd = (t & 15) * 4;
        float o[4][4];
#pragma unroll
        for (int i = 0; i < 4; i++)
#pragma unroll
            for (int j = 0; j < 4; j++) o[i][j] = 0.f;
        for (int kk = 0; kk < 256; kk++) {
            float a[4], bb[4];
            *(float4*)&a[0] = *(float4*)&sS[kk * 68 + pq];
            *(float4*)&bb[0] = *(float4*)&sKt[kk * 64 + pd];
#pragma unroll
            for (int i = 0; i < 4; i++)
#pragma unroll
                for (int j = 0; j < 4; j++) o[i][j] += a[i] * bb[j];
        }
#pragma unroll
        for (int i = 0; i < 4; i++) {
            float4 v = make_float4(o[i][0], o[i][1], o[i][2], o[i][3]);
            *(float4*)&g_scratch[OFF_SOUT + qbase + (size_t)(pq + i) * 64 + pd] = v;
        }
    }
}

// ---------------- gates ----------------
__global__ void k_gates(const float* __restrict__ Wg, const float* __restrict__ bgv) {
    int r = blockIdx.x;
    int t = threadIdx.x;
    __shared__ float sx[512];
    for (int u = t; u < 512; u += 128) sx[u] = g_scratch[OFF_INP + (size_t)r * 512 + u];
    __syncthreads();
    int w = t >> 5, lane = t & 31;
    for (int o = w; o < 24; o += 4) {
        float acc = 0.f;
        for (int kk = lane; kk < 512; kk += 32) acc += sx[kk] * Wg[(size_t)kk * 24 + o];
        for (int off = 16; off; off >>= 1) acc += __shfl_xor_sync(~0u, acc, off);
        if (lane == 0)
            g_scratch[OFF_GATES + (size_t)r * 24 + o] = 1.f / (1.f + __expf(-(acc + bgv[o])));
    }
}

// ---------------- combine (bf16 hi/lo output) ----------------
__global__ void k_combine() {
    int pid = blockIdx.x * blockDim.x + threadIdx.x;
    if (pid >= 1048576) return;
    int idx0 = pid * 2;
    int d = idx0 & 63;
    int hh = (idx0 >> 6) & 7;
    int ri = idx0 >> 9;
    int b = ri >> 11, i = ri & 2047;
    size_t hidx = (((size_t)(b * 8 + hh) * 2048 + i) * 64 + d);
    const float* gg = g_scratch + OFF_GATES + (size_t)ri * 24 + hh * 3;
    float o0 = gg[0] * g_scratch[OFF_COUT + hidx] + gg[1] * g_scratch[OFF_FOUT + hidx] +
               gg[2] * g_scratch[OFF_SOUT + hidx];
    float o1 = gg[0] * g_scratch[OFF_COUT + hidx + 1] + gg[1] * g_scratch[OFF_FOUT + hidx + 1] +
               gg[2] * g_scratch[OFF_SOUT + hidx + 1];
    uint32_t hp, lp;
    bf_split_pack(o0, o1, hp, lp);
    ((uint32_t*)(g_scratch + OFF_COMB_HI))[pid] = hp;
    ((uint32_t*)(g_scratch + OFF_COMB_LO))[pid] = lp;
}

// ---------------- host ----------------
extern "C" void kernel_launch(void* const* d_in, const int* in_sizes, int n_in,
                              void* d_out, int out_size) {
    const float* x     = (const float*)d_in[0];
    const float* pos   = (const float*)d_in[1];
    const float* pe_W  = (const float*)d_in[2];
    const float* pe_b  = (const float*)d_in[3];
    const float* nsc   = (const float*)d_in[4];
    const float* Wqkv  = (const float*)d_in[5];
    const float* k_pos = (const float*)d_in[6];
    const float* v_pos = (const float*)d_in[7];
    const float* kcW1  = (const float*)d_in[8];
    const float* kcb1  = (const float*)d_in[9];
    const float* kcW2  = (const float*)d_in[10];
    const float* kcb2  = (const float*)d_in[11];
    const float* vcW1  = (const float*)d_in[12];
    const float* vcb1  = (const float*)d_in[13];
    const float* vcW2  = (const float*)d_in[14];
    const float* vcb2  = (const float*)d_in[15];
    const float* mem_k = (const float*)d_in[16];
    const float* mem_v = (const float*)d_in[17];
    const float* Wg    = (const float*)d_in[18];
    const float* bgv   = (const float*)d_in[19];
    const float* Wo    = (const float*)d_in[20];
    float* out = (float*)d_out;

    float* S = nullptr;
    cudaGetSymbolAddress((void**)&S, g_scratch);
    const uint16_t* WQKV_HI = (const uint16_t*)(S + OFF_WQKV_HI);
    const uint16_t* WQKV_LO = (const uint16_t*)(S + OFF_WQKV_LO);
    const uint16_t* WOHI    = (const uint16_t*)(S + OFF_WO_HI);
    const uint16_t* WOLO    = (const uint16_t*)(S + OFF_WO_LO);
    const uint16_t* INP_HI  = (const uint16_t*)(S + OFF_INP_HI);
    const uint16_t* INP_LO  = (const uint16_t*)(S + OFF_INP_LO);
    const uint16_t* KBM_HI  = (const uint16_t*)(S + OFF_KBM_HI);
    const uint16_t* KBM_LO  = (const uint16_t*)(S + OFF_KBM_LO);
    const uint16_t* VBM_HI  = (const uint16_t*)(S + OFF_VBM_HI);
    const uint16_t* VBM_LO  = (const uint16_t*)(S + OFF_VBM_LO);
    const uint16_t* COMB_HI = (const uint16_t*)(S + OFF_COMB_HI);
    const uint16_t* COMB_LO = (const uint16_t*)(S + OFF_COMB_LO);

    cudaFuncSetAttribute(k_fine, cudaFuncAttributeMaxDynamicSharedMemorySize, FINE_SMEM);
    cudaFuncSetAttribute(k_slide, cudaFuncAttributeMaxDynamicSharedMemorySize, SLIDE_SMEM);
    cudaFuncSetAttribute(k_c2, cudaFuncAttributeMaxDynamicSharedMemorySize, C2_SMEM);
    cudaFuncSetAttribute(k_mgemm<2>, cudaFuncAttributeMaxDynamicSharedMemorySize, MG_SMEM2);
    cudaFuncSetAttribute(k_wgemm, cudaFuncAttributeMaxDynamicSharedMemorySize, WG_SMEM);

    k_cvtw<<<640, 256>>>(Wqkv, Wo);
    k_posmean<<<64, 64>>>(pos);
    k_pe_norm<<<4096, 256>>>(x, pos, pe_W, pe_b, nsc);

    // qkv = inp @ Wqkv : M=4096 N=768 K=512  (launch #4 -> ncu capture)
    k_mgemm<2><<<dim3(12, 32, 1), 256, MG_SMEM2>>>(INP_HI, INP_LO, WQKV_HI, WQKV_LO, S + OFF_QKV,
                                                   768, 512, 512, 1);
    k_split_rope<<<4096, 384>>>();
    k_buildmats<<<1024, 256>>>(k_pos, v_pos);

    // fused kc1+vc1, split-K 4, fp32 weights converted in-kernel
    k_wgemm<<<dim3(32, 1, 8), 256, WG_SMEM>>>(KBM_HI, KBM_LO, kcW1, S + OFF_PART,
                                              VBM_HI, VBM_LO, vcW1, S + OFF_PART + 2097152,
                                              4096, 4096, 1024, 4);
    k_c1red<<<1024, 256>>>(kcb1, vcb1);
    k_c2<<<64, 256, C2_SMEM>>>(kcW2, kcb2, vcW2, vcb2);
    k_pack<<<(8448 + 255) / 256, 256>>>(mem_k, mem_v);

    k_coarse<<<512, 256>>>();
    k_topk<<<32, 256>>>();
    k_fine<<<8192, 256, FINE_SMEM>>>();
    k_slide<<<512, 256, SLIDE_SMEM>>>();
    k_gates<<<4096, 128>>>(Wg, bgv);
    k_combine<<<4096, 256>>>();

    // out = comb @ Wo : M=4096 N=512 K=512
    k_mgemm<2><<<dim3(8, 32, 1), 256, MG_SMEM2>>>(COMB_HI, COMB_LO, WOHI, WOLO, out,
                                                  512, 512, 512, 1);
}

// round 14
// speedup vs baseline: 1.0637x; 1.0637x over previous
#include <cuda_runtime.h>
#include <cuda_bf16.h>
#include <cuda_fp16.h>
#include <math.h>
#include <stdint.h>

// ---------------- scratch layout (floats) ----------------
#define OFF_INP      0ul
#define OFF_QKV      2097152ul
#define OFF_Q        5242880ul
#define OFF_K        7340032ul
#define OFF_KRH      7864320ul
#define OFF_VH       8126464ul
#define OFF_V        8388608ul
#define OFF_KHID     8912896ul
#define OFF_VHID     9437184ul
#define OFF_CKRAW    9961472ul
#define OFF_CVRAW    9969664ul
#define OFF_CK       9977856ul
#define OFF_CV       9986304ul
#define OFF_COUT     9994752ul
#define OFF_FOUT    12091904ul
#define OFF_SOUT    14189056ul
#define OFF_IMP     16286208ul
#define OFF_SELVAL  16548352ul
#define OFF_GATES   16564736ul
#define OFF_PM      16663040ul
#define OFF_PART    16663296ul
#define OFF_WQKV_HI 20857600ul
#define OFF_WQKV_LO 21054208ul
#define OFF_WO_HI   21250816ul
#define OFF_WO_LO   21381888ul
#define OFF_INP_HI  21512960ul
#define OFF_INP_LO  22561536ul
#define OFF_KBM_HI  23610112ul
#define OFF_KBM_LO  23872256ul
#define OFF_VBM_HI  24134400ul
#define OFF_VBM_LO  24396544ul
#define OFF_COMB_HI 24658688ul
#define OFF_COMB_LO 25707264ul
#define SCRATCH_SZ  26755840ul

__device__ float g_scratch[SCRATCH_SZ];
__device__ int   g_selidx[2 * 2 * 2048 * 2];

// ================= helpers ============
__device__ __forceinline__ uint32_t smem_u32(const void* p) {
    uint32_t a;
    asm("{ .reg .u64 tmp; cvta.to.shared.u64 tmp, %1; cvt.u32.u64 %0, tmp; }"
        : "=r"(a) : "l"(p));
    return a;
}
__device__ __forceinline__ void ldsm_x4(uint32_t& r0, uint32_t& r1, uint32_t& r2, uint32_t& r3,
                                        uint32_t addr) {
    asm volatile("ldmatrix.sync.aligned.m8n8.x4.shared.b16 {%0,%1,%2,%3}, [%4];"
                 : "=r"(r0), "=r"(r1), "=r"(r2), "=r"(r3) : "r"(addr));
}
__device__ __forceinline__ void ldsm_x4t(uint32_t& r0, uint32_t& r1, uint32_t& r2, uint32_t& r3,
                                         uint32_t addr) {
    asm volatile("ldmatrix.sync.aligned.m8n8.x4.trans.shared.b16 {%0,%1,%2,%3}, [%4];"
                 : "=r"(r0), "=r"(r1), "=r"(r2), "=r"(r3) : "r"(addr));
}
__device__ __forceinline__ void mma16816(float* c, uint32_t a0, uint32_t a1, uint32_t a2,
                                         uint32_t a3, uint32_t b0, uint32_t b1) {
    asm volatile("mma.sync.aligned.m16n8k16.row.col.f32.bf16.bf16.f32 "
                 "{%0,%1,%2,%3}, {%4,%5,%6,%7}, {%8,%9}, {%0,%1,%2,%3};"
                 : "+f"(c[0]), "+f"(c[1]), "+f"(c[2]), "+f"(c[3])
                 : "r"(a0), "r"(a1), "r"(a2), "r"(a3), "r"(b0), "r"(b1));
}
__device__ __forceinline__ void bf_split_pack(float x0, float x1, uint32_t& hp, uint32_t& lp) {
    uint32_t u0 = __float_as_uint(x0), u1 = __float_as_uint(x1);
    hp = __byte_perm(u0, u1, 0x7632);
    float l0 = x0 - __uint_as_float(u0 & 0xFFFF0000u);
    float l1 = x1 - __uint_as_float(u1 & 0xFFFF0000u);
    asm("cvt.rn.bf16x2.f32 %0, %1, %2;" : "=r"(lp) : "f"(l1), "f"(l0));
}
__device__ __forceinline__ void cp16(uint32_t s, const void* g) {
    asm volatile("cp.async.cg.shared.global [%0], [%1], 16;" :: "r"(s), "l"(g));
}

// ---------------- weight conversion (Wqkv + Wo only) ----------------
__global__ void k_cvtw(const float* __restrict__ Wqkv, const float* __restrict__ Wo) {
    size_t q = (size_t)blockIdx.x * 256 + threadIdx.x;   // float4 units
    if (q >= 163840ul) return;
    const float* src;
    uint32_t *hi, *lo;
    size_t local;
    if (q < 98304ul) {
        src = Wqkv; local = q;
        hi = (uint32_t*)(g_scratch + OFF_WQKV_HI); lo = (uint32_t*)(g_scratch + OFF_WQKV_LO);
    } else {
        src = Wo; local = q - 98304ul;
        hi = (uint32_t*)(g_scratch + OFF_WO_HI); lo = (uint32_t*)(g_scratch + OFF_WO_LO);
    }
    float4 v = ((const float4*)src)[local];
    uint32_t h0, l0, h1, l1;
    bf_split_pack(v.x, v.y, h0, l0);
    bf_split_pack(v.z, v.w, h1, l1);
    ((uint2*)hi)[local] = make_uint2(h0, h1);
    ((uint2*)lo)[local] = make_uint2(l0, l1);
}

// ======== cp.async pipelined bf16x3 MMA GEMM, templated N-tile (preconv B) ====
#define APAD 40
extern __shared__ uint16_t mgs[];
template <int NTILES>
__global__ void __launch_bounds__(256, 2)
k_mgemm(const uint16_t* __restrict__ Ahi0, const uint16_t* __restrict__ Alo0,
        const uint16_t* __restrict__ Bhi0, const uint16_t* __restrict__ Blo0,
        float* __restrict__ C0,
        int N, int K, int klen, int nchunks) {
    constexpr int BN = NTILES * 32;
    constexpr int BPADT = BN + 8;
    constexpr int BOFF = 10240;
    constexpr int BLO = BOFF + 32 * BPADT;
    constexpr int BUF = BLO + 32 * BPADT;
    uint32_t sb = smem_u32(mgs);
    int chunk = blockIdx.z;
    float* C = C0 + (size_t)chunk * gridDim.y * 128 * N;
    int kstart = chunk * klen;
    int t = threadIdx.x, wid = t >> 5, lane = t & 31;
    int bx = blockIdx.x, by = blockIdx.y;
    int warp_m = wid >> 2, warp_n = wid & 3;

    float acc[4][NTILES][4];
#pragma unroll
    for (int mt = 0; mt < 4; mt++)
#pragma unroll
        for (int nt = 0; nt < NTILES; nt++)
#pragma unroll
            for (int e = 0; e < 4; e++) acc[mt][nt][e] = 0.f;

    int a_row = (lane & 15), a_kc8 = 8 * (lane >> 4);
    int b_krow = (lane & 15), b_n8 = 8 * (lane >> 4);
    int nch = klen / 32;
    const uint16_t* Ah = Ahi0 + (size_t)(by * 128) * K + kstart;
    const uint16_t* Al = Alo0 + (size_t)(by * 128) * K + kstart;
    const uint16_t* Bh = Bhi0 + (size_t)kstart * N + bx * BN;
    const uint16_t* Bl = Blo0 + (size_t)kstart * N + bx * BN;

    auto stage = [&](int buf, int cc) {
        uint32_t soff = sb + buf * (BUF * 2);
#pragma unroll
        for (int h = 0; h < 2; h++) {
            int u = t + h * 256;
            int row = u >> 2, seg = u & 3;
            size_t go = (size_t)row * K + (size_t)cc * 32 + seg * 8;
            cp16(soff + (row * APAD + seg * 8) * 2, Ah + go);
            cp16(soff + (5120 + row * APAD + seg * 8) * 2, Al + go);
        }
#pragma unroll
        for (int h = 0; h < NTILES / 2; h++) {
            int u = t + h * 256;
            int row, seg;
            if (NTILES == 4) { row = u >> 4; seg = u & 15; }
            else { row = u >> 3; seg = u & 7; }
            size_t go = (size_t)(cc * 32 + row) * N + seg * 8;
            cp16(soff + (BOFF + row * BPADT + seg * 8) * 2, Bh + go);
            cp16(soff + (BLO + row * BPADT + seg * 8) * 2, Bl + go);
        }
        asm volatile("cp.async.commit_group;" ::: "memory");
    };

    stage(0, 0);
    for (int c = 0; c < nch; c++) {
        int buf = c & 1;
        if (c + 1 < nch) {
            stage(buf ^ 1, c + 1);
            asm volatile("cp.async.wait_group 1;" ::: "memory");
        } else {
            asm volatile("cp.async.wait_group 0;" ::: "memory");
        }
        __syncthreads();
        uint32_t abase = sb + buf * (BUF * 2);
#pragma unroll
        for (int ks = 0; ks < 2; ks++) {
            uint32_t af[4][4], bh[NTILES][2], bl[NTILES][2];
#pragma unroll
            for (int mt = 0; mt < 4; mt++) {
                int off = (warp_m * 64 + mt * 16 + a_row) * APAD + ks * 16 + a_kc8;
                ldsm_x4(af[mt][0], af[mt][1], af[mt][2], af[mt][3], abase + off * 2);
            }
#pragma unroll
            for (int n2 = 0; n2 < NTILES / 2; n2++) {
                int off = BOFF + (ks * 16 + b_krow) * BPADT + warp_n * (NTILES * 8) + n2 * 16 + b_n8;
                ldsm_x4t(bh[n2 * 2][0], bh[n2 * 2][1], bh[n2 * 2 + 1][0], bh[n2 * 2 + 1][1],
                         abase + off * 2);
                ldsm_x4t(bl[n2 * 2][0], bl[n2 * 2][1], bl[n2 * 2 + 1][0], bl[n2 * 2 + 1][1],
                         abase + (off + 32 * BPADT) * 2);
            }
#pragma unroll
            for (int mt = 0; mt < 4; mt++)
#pragma unroll
                for (int nt = 0; nt < NTILES; nt++) {
                    mma16816(acc[mt][nt], af[mt][0], af[mt][1], af[mt][2], af[mt][3],
                             bh[nt][0], bh[nt][1]);
                    mma16816(acc[mt][nt], af[mt][0], af[mt][1], af[mt][2], af[mt][3],
                             bl[nt][0], bl[nt][1]);
                }
#pragma unroll
            for (int mt = 0; mt < 4; mt++) {
                int off = 5120 + (warp_m * 64 + mt * 16 + a_row) * APAD + ks * 16 + a_kc8;
                ldsm_x4(af[mt][0], af[mt][1], af[mt][2], af[mt][3], abase + off * 2);
            }
#pragma unroll
            for (int mt = 0; mt < 4; mt++)
#pragma unroll
                for (int nt = 0; nt < NTILES; nt++)
                    mma16816(acc[mt][nt], af[mt][0], af[mt][1], af[mt][2], af[mt][3],
                             bh[nt][0], bh[nt][1]);
        }
        __syncthreads();
    }
    int g = lane >> 2, tid4 = lane & 3;
#pragma unroll
    for (int mt = 0; mt < 4; mt++) {
        int row0 = by * 128 + warp_m * 64 + mt * 16 + g;
#pragma unroll
        for (int nt = 0; nt < NTILES; nt++) {
            int col = bx * BN + warp_n * (NTILES * 8) + nt * 8 + tid4 * 2;
            *(float2*)&C[(size_t)row0 * N + col] = make_float2(acc[mt][nt][0], acc[mt][nt][1]);
            *(float2*)&C[(size_t)(row0 + 8) * N + col] = make_float2(acc[mt][nt][2], acc[mt][nt][3]);
        }
    }
}
#define MG_SMEM2 ((10240 + 2 * 32 * 72) * 4)

// ======== c1 GEMM: A preconv bf16 (cp.async), B fp32 (cp.async + smem convert) ====
#define WG_BPADT 136
#define WG_BOFF  10240
#define WG_BLO   (WG_BOFF + 32 * WG_BPADT)
#define WG_BUF   (WG_BLO + 32 * WG_BPADT)
#define WG_SLOT0 (2 * WG_BUF * 2)
#define WG_SMEM  (WG_SLOT0 + 2 * 16384)
extern __shared__ uint16_t wgs[];
__global__ void __launch_bounds__(256, 2)
k_wgemm(const uint16_t* __restrict__ Ahi0, const uint16_t* __restrict__ Alo0,
        const float* __restrict__ Bf0, float* __restrict__ C0,
        const uint16_t* __restrict__ Ahi1, const uint16_t* __restrict__ Alo1,
        const float* __restrict__ Bf1, float* __restrict__ C1,
        int N, int K, int klen, int nchunks) {
    uint32_t sb = smem_u32(wgs);
    int z = blockIdx.z;
    int comp = z / nchunks, chunk = z - comp * nchunks;
    const uint16_t* Ahi = comp ? Ahi1 : Ahi0;
    const uint16_t* Alo = comp ? Alo1 : Alo0;
    const float* Bf = comp ? Bf1 : Bf0;
    float* C = (comp ? C1 : C0) + (size_t)chunk * 128 * N;
    int kstart = chunk * klen;
    int t = threadIdx.x, wid = t >> 5, lane = t & 31;
    int bx = blockIdx.x;
    int warp_m = wid >> 2, warp_n = wid & 3;

    float acc[4][4][4];
#pragma unroll
    for (int mt = 0; mt < 4; mt++)
#pragma unroll
        for (int nt = 0; nt < 4; nt++)
#pragma unroll
            for (int e = 0; e < 4; e++) acc[mt][nt][e] = 0.f;

    int a_row = (lane & 15), a_kc8 = 8 * (lane >> 4);
    int b_krow = (lane & 15), b_n8 = 8 * (lane >> 4);
    int nch = klen / 32;
    const uint16_t* Ah = Ahi + kstart;
    const uint16_t* Al = Alo + kstart;
    const float* Bb = Bf + (size_t)kstart * N + bx * 128;

    auto stageA = [&](int buf, int cc) {
        uint32_t soff = sb + buf * (WG_BUF * 2);
#pragma unroll
        for (int h = 0; h < 2; h++) {
            int u = t + h * 256;
            int row = u >> 2, seg = u & 3;
            size_t go = (size_t)row * K + (size_t)cc * 32 + seg * 8;
            cp16(soff + (row * APAD + seg * 8) * 2, Ah + go);
            cp16(soff + (5120 + row * APAD + seg * 8) * 2, Al + go);
        }
    };
    auto stageB = [&](int buf, int cc) {
        uint32_t soff = sb + WG_SLOT0 + buf * 16384;
#pragma unroll
        for (int h = 0; h < 4; h++) {
            int u = t + h * 256;
            int row = u >> 5, seg = u & 31;
            cp16(soff + u * 16, Bb + (size_t)(cc * 32 + row) * N + seg * 4);
        }
    };

    stageA(0, 0);
    stageB(0, 0);
    asm volatile("cp.async.commit_group;" ::: "memory");
    for (int c = 0; c < nch; c++) {
        int buf = c & 1;
        asm volatile("cp.async.wait_group 0;" ::: "memory");
        __syncthreads();
        {
            const float2* slot = (const float2*)((char*)wgs + WG_SLOT0 + buf * 16384);
            char* bufp = (char*)wgs + buf * (WG_BUF * 2);
#pragma unroll
            for (int p = 0; p < 8; p++) {
                int u2 = t + p * 256;
                int row = u2 >> 6, c2 = u2 & 63;
                float2 v = slot[u2];
                uint32_t hp, lp;
                bf_split_pack(v.x, v.y, hp, lp);
                *(uint32_t*)(bufp + (WG_BOFF + row * WG_BPADT + c2 * 2) * 2) = hp;
                *(uint32_t*)(bufp + (WG_BLO + row * WG_BPADT + c2 * 2) * 2) = lp;
            }
        }
        __syncthreads();
        if (c + 1 < nch) {
            stageA(buf ^ 1, c + 1);
            stageB(buf ^ 1, c + 1);
            asm volatile("cp.async.commit_group;" ::: "memory");
        }
        uint32_t abase = sb + buf * (WG_BUF * 2);
#pragma unroll
        for (int ks = 0; ks < 2; ks++) {
            uint32_t af[4][4], bh[4][2], bl[4][2];
#pragma unroll
            for (int mt = 0; mt < 4; mt++) {
                int off = (warp_m * 64 + mt * 16 + a_row) * APAD + ks * 16 + a_kc8;
                ldsm_x4(af[mt][0], af[mt][1], af[mt][2], af[mt][3], abase + off * 2);
            }
#pragma unroll
            for (int n2 = 0; n2 < 2; n2++) {
                int off = WG_BOFF + (ks * 16 + b_krow) * WG_BPADT + warp_n * 32 + n2 * 16 + b_n8;
                ldsm_x4t(bh[n2 * 2][0], bh[n2 * 2][1], bh[n2 * 2 + 1][0], bh[n2 * 2 + 1][1],
                         abase + off * 2);
                ldsm_x4t(bl[n2 * 2][0], bl[n2 * 2][1], bl[n2 * 2 + 1][0], bl[n2 * 2 + 1][1],
                         abase + (off + 32 * WG_BPADT) * 2);
            }
#pragma unroll
            for (int mt = 0; mt < 4; mt++)
#pragma unroll
                for (int nt = 0; nt < 4; nt++) {
                    mma16816(acc[mt][nt], af[mt][0], af[mt][1], af[mt][2], af[mt][3],
                             bh[nt][0], bh[nt][1]);
                    mma16816(acc[mt][nt], af[mt][0], af[mt][1], af[mt][2], af[mt][3],
                             bl[nt][0], bl[nt][1]);
                }
#pragma unroll
            for (int mt = 0; mt < 4; mt++) {
                int off = 5120 + (warp_m * 64 + mt * 16 + a_row) * APAD + ks * 16 + a_kc8;
                ldsm_x4(af[mt][0], af[mt][1], af[mt][2], af[mt][3], abase + off * 2);
            }
#pragma unroll
            for (int mt = 0; mt < 4; mt++)
#pragma unroll
                for (int nt = 0; nt < 4; nt++)
                    mma16816(acc[mt][nt], af[mt][0], af[mt][1], af[mt][2], af[mt][3],
                             bh[nt][0], bh[nt][1]);
        }
        __syncthreads();
    }
    int g = lane >> 2, tid4 = lane & 3;
#pragma unroll
    for (int mt = 0; mt < 4; mt++) {
        int row0 = warp_m * 64 + mt * 16 + g;
#pragma unroll
        for (int nt = 0; nt < 4; nt++) {
            int col = bx * 128 + warp_n * 32 + nt * 8 + tid4 * 2;
            *(float2*)&C[(size_t)row0 * N + col] = make_float2(acc[mt][nt][0], acc[mt][nt][1]);
            *(float2*)&C[(size_t)(row0 + 8) * N + col] = make_float2(acc[mt][nt][2], acc[mt][nt][3]);
        }
    }
}

// ---------------- c1 split-K reduce + bias + relu ----------------
__global__ void k_c1red(const float* __restrict__ kcb1, const float* __restrict__ vcb1) {
    int u4 = blockIdx.x * 256 + threadIdx.x;
    int comp = u4 >> 17;
    int loc = u4 & 131071;
    int col4 = loc & 1023;
    const float* P = g_scratch + OFF_PART + (size_t)comp * 2097152 + (size_t)loc * 4;
    float4 s0 = *(const float4*)(P);
    float4 s1 = *(const float4*)(P + 524288);
    float4 s2 = *(const float4*)(P + 1048576);
    float4 s3 = *(const float4*)(P + 1572864);
    const float* bias = comp ? vcb1 : kcb1;
    float4 b = *(const float4*)&bias[col4 * 4];
    float4 o;
    o.x = fmaxf(s0.x + s1.x + s2.x + s3.x + b.x, 0.f);
    o.y = fmaxf(s0.y + s1.y + s2.y + s3.y + b.y, 0.f);
    o.z = fmaxf(s0.z + s1.z + s2.z + s3.z + b.z, 0.f);
    o.w = fmaxf(s0.w + s1.w + s2.w + s3.w + b.w, 0.f);
    float* O = g_scratch + (comp ? OFF_VHID : OFF_KHID) + (size_t)loc * 4;
    *(float4*)O = o;
}

// ---------------- pos block means ----------------
__global__ void k_posmean(const float* __restrict__ pos) {
    int blk = blockIdx.x;
    int t = threadIdx.x;
    __shared__ float s[64 * 3];
    s[t * 3 + 0] = pos[(blk * 64 + t) * 3 + 0];
    s[t * 3 + 1] = pos[(blk * 64 + t) * 3 + 1];
    s[t * 3 + 2] = pos[(blk * 64 + t) * 3 + 2];
    __syncthreads();
    if (t < 3) {
        float sum = 0.f;
        for (int i = 0; i < 64; i++) sum += s[i * 3 + t];
        g_scratch[OFF_PM + blk * 3 + t] = sum / 64.f;
    }
}

// ---------------- PE add + RMSNorm (+ bf16 hi/lo output) ----------------
__global__ void k_pe_norm(const float* __restrict__ x, const float* __restrict__ pos,
                          const float* __restrict__ peW, const float* __restrict__ peb,
                          const float* __restrict__ nsc) {
    int r = blockIdx.x;
    int t = threadIdx.x;
    int blk = r >> 6;
    float r0 = pos[r * 3 + 0] - g_scratch[OFF_PM + blk * 3 + 0];
    float r1 = pos[r * 3 + 1] - g_scratch[OFF_PM + blk * 3 + 1];
    float r2 = pos[r * 3 + 2] - g_scratch[OFF_PM + blk * 3 + 2];
    int c0 = t * 2, c1 = c0 + 1;
    float v0 = x[(size_t)r * 512 + c0] + r0 * peW[c0] + r1 * peW[512 + c0] + r2 * peW[1024 + c0] + peb[c0];
    float v1 = x[(size_t)r * 512 + c1] + r0 * peW[c1] + r1 * peW[512 + c1] + r2 * peW[1024 + c1] + peb[c1];
    __shared__ float red[256];
    red[t] = v0 * v0 + v1 * v1;
    __syncthreads();
    for (int s = 128; s > 0; s >>= 1) {
        if (t < s) red[t] += red[t + s];
        __syncthreads();
    }
    float rms = rsqrtf(red[0] / 512.f + 1e-6f);
    float s0 = v0 * rms * nsc[c0];
    float s1 = v1 * rms * nsc[c1];
    g_scratch[OFF_INP + (size_t)r * 512 + c0] = s0;
    g_scratch[OFF_INP + (size_t)r * 512 + c1] = s1;
    uint32_t hp, lp;
    bf_split_pack(s0, s1, hp, lp);
    ((uint32_t*)(g_scratch + OFF_INP_HI))[(size_t)r * 256 + t] = hp;
    ((uint32_t*)(g_scratch + OFF_INP_LO))[(size_t)r * 256 + t] = lp;
}

// ---------------- c2: 4 rows per block (64 blocks) ----------------
#define C2_SMEM ((16384 + 1024) * 4)
extern __shared__ float c2sm[];
__global__ void k_c2(const float* __restrict__ kcW2, const float* __restrict__ kcb2,
                     const float* __restrict__ vcW2, const float* __restrict__ vcb2) {
    float* sa = c2sm;
    float* red = c2sm + 16384;
    int blk = blockIdx.x;
    int comp = blk >> 5, rg = blk & 31;
    const float* A = g_scratch + (comp ? OFF_VHID : OFF_KHID) + (size_t)(rg * 4) * 4096;
    const float* W = comp ? vcW2 : kcW2;
    const float* bias = comp ? vcb2 : kcb2;
    float* Cout = g_scratch + (comp ? OFF_CVRAW : OFF_CKRAW) + (size_t)(rg * 4) * 64;
    int t = threadIdx.x;
    for (int u = t; u < 16384; u += 256) {
        int r = u >> 12, kk = u & 4095;
        sa[kk * 4 + r] = A[(size_t)r * 4096 + kk];
    }
    __syncthreads();
    int o = t & 63, sub = t >> 6;
    const float* Wp = W + (size_t)(sub * 1024) * 64 + o;
    float acc0 = 0.f, acc1 = 0.f, acc2 = 0.f, acc3 = 0.f;
    const float* ap = sa + sub * 1024 * 4;
#pragma unroll 4
    for (int kk = 0; kk < 1024; kk++) {
        float w = Wp[(size_t)kk * 64];
        float4 a = *(const float4*)(ap + kk * 4);
        acc0 += a.x * w; acc1 += a.y * w; acc2 += a.z * w; acc3 += a.w * w;
    }
    red[t * 4 + 0] = acc0; red[t * 4 + 1] = acc1;
    red[t * 4 + 2] = acc2; red[t * 4 + 3] = acc3;
    __syncthreads();
    if (t < 64) {
        float b = bias[t];
#pragma unroll
        for (int r = 0; r < 4; r++) {
            float v = red[t * 4 + r] + red[(64 + t) * 4 + r] + red[(128 + t) * 4 + r] +
                      red[(192 + t) * 4 + r] + b;
            Cout[r * 64 + t] = v;
        }
    }
}

// ---------------- split qkv + rope ----------------
__global__ void k_split_rope() {
    int r = blockIdx.x;
    int b = r >> 11;
    int i = r & 2047;
    int t = threadIdx.x;          // 384
    const float* qkv = g_scratch + OFF_QKV + (size_t)r * 768;
    if (t < 256) {
        int col = t * 2;
        int head = col >> 6, d = col & 63, j = d >> 1;
        float inv = powf(10000.f, -(float)j / 32.f);
        float cs, sn;
        sincosf((float)i * inv, &sn, &cs);
        float a = qkv[col], bb = qkv[col + 1];
        size_t base = (((size_t)(b * 8 + head) * 2048 + i) * 64 + d);
        g_scratch[OFF_Q + base] = a * cs - bb * sn;
        g_scratch[OFF_Q + base + 1] = bb * cs + a * sn;
    } else if (t < 320) {
        int ci = (t - 256) * 2;
        int g = ci >> 6, d = ci & 63, j = d >> 1;
        float inv = powf(10000.f, -(float)j / 32.f);
        float cs, sn;
        sincosf((float)i * inv, &sn, &cs);
        float a = qkv[512 + ci], bb = qkv[512 + ci + 1];
        size_t base = (((size_t)(b * 2 + g) * 2048 + i) * 64 + d);
        g_scratch[OFF_K + base] = a;
        g_scratch[OFF_K + base + 1] = bb;
        float kr0 = a * cs - bb * sn;
        float kr1 = bb * cs + a * sn;
        ((__half2*)(g_scratch + OFF_KRH))[base >> 1] = __floats2half2_rn(kr0, kr1);
    } else {
        int ci = (t - 320) * 2;
        int g = ci >> 6, d = ci & 63;
        size_t base = (((size_t)(b * 2 + g) * 2048 + i) * 64 + d);
        float v0 = qkv[640 + ci], v1 = qkv[640 + ci + 1];
        g_scratch[OFF_V + base] = v0;
        g_scratch[OFF_V + base + 1] = v1;
        ((__half2*)(g_scratch + OFF_VH))[base >> 1] = __floats2half2_rn(v0, v1);
    }
}

// ---------------- build compressor inputs (bf16 hi/lo) ----------------
__global__ void k_buildmats(const float* __restrict__ k_pos, const float* __restrict__ v_pos) {
    int pid = blockIdx.x * blockDim.x + threadIdx.x;
    if (pid >= 262144) return;
    int row = pid >> 11;
    int pcol = pid & 2047;
    int col0 = pcol * 2;
    int bg = row >> 5, wi = row & 31, g = bg & 1;
    int j = col0 >> 6, d = col0 & 63;
    size_t src = ((size_t)bg * 2048 + wi * 64 + j) * 64 + d;
    int poff = (g * 64 + j) * 64 + d;
    float k0 = g_scratch[OFF_K + src] + k_pos[poff];
    float k1 = g_scratch[OFF_K + src + 1] + k_pos[poff + 1];
    float w0 = g_scratch[OFF_V + src] + v_pos[poff];
    float w1 = g_scratch[OFF_V + src + 1] + v_pos[poff + 1];
    uint32_t hp, lp;
    bf_split_pack(k0, k1, hp, lp);
    ((uint32_t*)(g_scratch + OFF_KBM_HI))[pid] = hp;
    ((uint32_t*)(g_scratch + OFF_KBM_LO))[pid] = lp;
    bf_split_pack(w0, w1, hp, lp);
    ((uint32_t*)(g_scratch + OFF_VBM_HI))[pid] = hp;
    ((uint32_t*)(g_scratch + OFF_VBM_LO))[pid] = lp;
}

// ---------------- pack ck/cv with mem token ----------------
__global__ void k_pack(const float* __restrict__ mem_k, const float* __restrict__ mem_v) {
    int idx = blockIdx.x * blockDim.x + threadIdx.x;
    if (idx >= 2 * 2 * 33 * 64) return;
    int d = idx & 63;
    int rest = idx >> 6;
    int j = rest % 33;
    int bg = rest / 33;
    int g = bg & 1;
    float kv, vv;
    if (j == 0) {
        kv = mem_k[g * 64 + d];
        vv = mem_v[g * 64 + d];
    } else {
        size_t s = ((size_t)bg * 32 + (j - 1)) * 64 + d;
        kv = g_scratch[OFF_CKRAW + s];
        vv = g_scratch[OFF_CVRAW + s];
    }
    g_scratch[OFF_CK + idx] = kv;
    g_scratch[OFF_CV + idx] = vv;
}

// ---------------- coarse attention + importance (per-query, round-12) --------
__global__ void k_coarse() {
    int bi = blockIdx.x;
    int bg = bi >> 11, i = bi & 2047;
    int b = bg >> 1, g = bg & 1;
    int t = threadIdx.x;          // 128
    __shared__ float sck[33 * 64], scv[33 * 64], sq[4 * 64], sp[4 * 36];
    for (int u = t; u < 528; u += 128) {
        *(float4*)&sck[u * 4] = *(const float4*)&g_scratch[OFF_CK + (size_t)bg * 2112 + u * 4];
        *(float4*)&scv[u * 4] = *(const float4*)&g_scratch[OFF_CV + (size_t)bg * 2112 + u * 4];
    }
    for (int u = t; u < 256; u += 128) {
        int hq = u >> 6, d = u & 63;
        sq[u] = g_scratch[OFF_Q + (((size_t)(b * 8 + g * 4 + hq) * 2048 + i) * 64 + d)];
    }
    __syncthreads();
    for (int u = t; u < 132; u += 128) {
        int hq = u / 33, j = u % 33;
        float s = -1e30f;
        if (j == 0 || j * 64 <= i) {
            float acc = 0.f;
            const float4* qv = (const float4*)&sq[hq * 64];
            const float4* kv = (const float4*)&sck[j * 64];
#pragma unroll
            for (int d4 = 0; d4 < 16; d4++) {
                float4 a = qv[d4], bb = kv[d4];
                acc += a.x * bb.x + a.y * bb.y + a.z * bb.z + a.w * bb.w;
            }
            s = acc * 0.125f;
        }
        sp[hq * 36 + j] = s;
    }
    __syncthreads();
    if (t < 4) {
        float m = -1e30f;
        for (int j = 0; j < 33; j++) m = fmaxf(m, sp[t * 36 + j]);
        float sum = 0.f;
        for (int j = 0; j < 33; j++) {
            float e = __expf(sp[t * 36 + j] - m);
            sp[t * 36 + j] = e;
            sum += e;
        }
        float inv = 1.f / sum;
        for (int j = 0; j < 33; j++) sp[t * 36 + j] *= inv;
    }
    __syncthreads();
    if (t < 32) {
        g_scratch[OFF_IMP + ((size_t)bg * 2048 + i) * 32 + t] =
            0.25f * (sp[t + 1] + sp[36 + t + 1] + sp[72 + t + 1] + sp[108 + t + 1]);
    }
    for (int u = t; u < 256; u += 128) {
        int hq = u >> 6, d = u & 63;
        float acc = 0.f;
#pragma unroll
        for (int j4 = 0; j4 < 8; j4++) {
            float4 p = *(const float4*)&sp[hq * 36 + j4 * 4];
            acc += p.x * scv[(j4 * 4 + 0) * 64 + d] + p.y * scv[(j4 * 4 + 1) * 64 + d] +
                   p.z * scv[(j4 * 4 + 2) * 64 + d] + p.w * scv[(j4 * 4 + 3) * 64 + d];
        }
        acc += sp[hq * 36 + 32] * scv[32 * 64 + d];
        g_scratch[OFF_COUT + (((size_t)(b * 8 + g * 4 + hq) * 2048 + i) * 64 + d)] = acc;
    }
}

// ---------------- top-k (k=2, stable) ----------------
__global__ void k_topk() {
    int idx = blockIdx.x * blockDim.x + threadIdx.x;
    if (idx >= 8192) return;
    const float* imp = g_scratch + OFF_IMP + (size_t)idx * 32;
    int i1 = 0;
    float v1 = imp[0];
    for (int j = 1; j < 32; j++)
        if (imp[j] > v1) { v1 = imp[j]; i1 = j; }
    int i2 = -1;
    float v2 = -1e30f;
    for (int j = 0; j < 32; j++) {
        if (j == i1) continue;
        if (imp[j] > v2) { v2 = imp[j]; i2 = j; }
    }
    g_scratch[OFF_SELVAL + idx * 2 + 0] = v1;
    g_scratch[OFF_SELVAL + idx * 2 + 1] = v2;
    g_selidx[idx * 2 + 0] = i1;
    g_selidx[idx * 2 + 1] = i2;
}

// ---------------- fine gathered attention (fp16 smem, reg-cached Q) ----------
#define FINE_SMEM (13824 * 4)
extern __shared__ float fsm[];
__global__ void __launch_bounds__(256, 2) k_fine() {
    __half* skh = (__half*)fsm;
    __half* svh = (__half*)(fsm + 6144);
    float* sq = fsm + 12288;
    float* sp = fsm + 12544;
    float* spart = fsm + 13312;
    int bi = blockIdx.x;
    int bg = bi >> 11, i = bi & 2047;
    int b = bg >> 1, g = bg & 1;
    int t = threadIdx.x;
    int own = i >> 6;
    __shared__ int blkid[3];
    __shared__ int okf[3];
    if (t < 2) {
        int si = g_selidx[bi * 2 + t];
        float sval = g_scratch[OFF_SELVAL + bi * 2 + t];
        blkid[t] = si;
        okf[t] = (sval > 0.f && si != own) ? 1 : 0;
    }
    if (t == 2) { blkid[2] = own; okf[2] = 1; }
    __syncthreads();
    size_t kbase = (size_t)bg * 2048 * 64;
    const uint4* KRH4 = (const uint4*)(g_scratch + OFF_KRH);
    const uint4* VH4 = (const uint4*)(g_scratch + OFF_VH);
#pragma unroll
    for (int u = t; u < 1536; u += 256) {
        int kk = u >> 3, d8 = u & 7;
        int kb = kk >> 6, j = kk & 63;
        size_t elem = kbase + (size_t)(blkid[kb] * 64 + j) * 64 + d8 * 8;
        ((uint4*)skh)[u] = KRH4[elem >> 3];
        ((uint4*)svh)[u] = VH4[elem >> 3];
    }
    {
        int hq = t >> 6, d = t & 63;
        sq[t] = g_scratch[OFF_Q + (((size_t)(b * 8 + g * 4 + hq) * 2048 + i) * 64 + d)];
    }
    __syncthreads();
    {
        int hq = t >> 6, j0 = t & 63;
        float4 qv[16];
        const float4* qsm = (const float4*)&sq[hq * 64];
#pragma unroll
        for (int p = 0; p < 16; p++) qv[p] = qsm[p];
        int ilocal = i & 63;
#pragma unroll
        for (int s = 0; s < 3; s++) {
            int kk = s * 64 + j0;
            bool valid = (s < 2) ? (okf[s] != 0) : (j0 <= ilocal);
            float score = -1e30f;
            if (valid) {
                float acc = 0.f;
                const uint4* kp = (const uint4*)(skh + kk * 64);
#pragma unroll
                for (int p = 0; p < 8; p++) {
                    uint4 raw = kp[p];
                    float2 f0 = __half22float2(*(__half2*)&raw.x);
                    float2 f1 = __half22float2(*(__half2*)&raw.y);
                    float2 f2 = __half22float2(*(__half2*)&raw.z);
                    float2 f3 = __half22float2(*(__half2*)&raw.w);
                    float4 q0 = qv[p * 2], q1 = qv[p * 2 + 1];
                    acc += q0.x * f0.x + q0.y * f0.y + q0.z * f1.x + q0.w * f1.y;
                    acc += q1.x * f2.x + q1.y * f2.y + q1.z * f3.x + q1.w * f3.y;
                }
                score = acc * 0.125f;
            }
            sp[hq * 192 + kk] = score;
        }
    }
    __syncthreads();
    {
        int w = t >> 5, lane = t & 31;
        if (w < 4) {
            float m = -1e30f;
            for (int kk = lane; kk < 192; kk += 32) m = fmaxf(m, sp[w * 192 + kk]);
            for (int o = 16; o; o >>= 1) m = fmaxf(m, __shfl_xor_sync(~0u, m, o));
            float sum = 0.f;
            for (int kk = lane; kk < 192; kk += 32) {
                float e = __expf(sp[w * 192 + kk] - m);
                sp[w * 192 + kk] = e;
                sum += e;
            }
            for (int o = 16; o; o >>= 1) sum += __shfl_xor_sync(~0u, sum, o);
            float inv = 1.f / sum;
            for (int kk = lane; kk < 192; kk += 32) sp[w * 192 + kk] *= inv;
        }
    }
    __syncthreads();
    {
        int part = t >> 7, r = t & 127;
        int hq = r >> 5, d2 = r & 31;
        float ax = 0.f, ay = 0.f;
        const __half2* vp = (const __half2*)svh;
        const float* pr = sp + hq * 192 + part * 96;
#pragma unroll 4
        for (int kk = 0; kk < 96; kk += 4) {
            float4 p = *(const float4*)&pr[kk];
            int kbase2 = (part * 96 + kk) * 32 + d2;
            float2 v0 = __half22float2(vp[kbase2]);
            float2 v1 = __half22float2(vp[kbase2 + 32]);
            float2 v2 = __half22float2(vp[kbase2 + 64]);
            float2 v3 = __half22float2(vp[kbase2 + 96]);
            ax += p.x * v0.x + p.y * v1.x + p.z * v2.x + p.w * v3.x;
            ay += p.x * v0.y + p.y * v1.y + p.z * v2.y + p.w * v3.y;
        }
        spart[(part * 128 + r) * 2] = ax;
        spart[(part * 128 + r) * 2 + 1] = ay;
    }
    __syncthreads();
    if (t < 128) {
        int hq = t >> 5, d2 = t & 31;
        float ox = spart[t * 2] + spart[(128 + t) * 2];
        float oy = spart[t * 2 + 1] + spart[(128 + t) * 2 + 1];
        *(float2*)&g_scratch[OFF_FOUT + (((size_t)(b * 8 + g * 4 + hq) * 2048 + i) * 64 + d2 * 2)] =
            make_float2(ox, oy);
    }
}

// ---------------- sliding attention: register-tiled (fp16 K/V loads) ----------
#define SLIDE_SMEM ((4352 + 16640 + 17408) * 4)
extern __shared__ float ssm2[];
__global__ void k_slide() {
    float* sQt = ssm2;
    float* sKt = ssm2 + 4352;
    float* sS  = ssm2 + 4352 + 16640;
    int id = blockIdx.x;
    int qc = id & 3;
    int tile = (id >> 2) & 7;
    int hh = (id >> 5) & 7;
    int b = id >> 8;
    int g = hh >> 2;
    int t = threadIdx.x;
    size_t kbase = ((size_t)(b * 2 + g) * 2048 + (size_t)tile * 256) * 64;
    size_t qbase = (((size_t)(b * 8 + hh) * 2048) + tile * 256 + qc * 64) * 64;
    const uint32_t* KRH32 = (const uint32_t*)(g_scratch + OFF_KRH);
    const uint32_t* VH32 = (const uint32_t*)(g_scratch + OFF_VH);
    for (int u2 = t; u2 < 8192; u2 += 256) {
        int kk = u2 >> 5, d2 = u2 & 31;
        uint32_t raw = KRH32[(kbase >> 1) + kk * 32 + d2];
        float2 f = __half22float2(*(__half2*)&raw);
        sKt[(2 * d2) * 260 + kk] = f.x;
        sKt[(2 * d2 + 1) * 260 + kk] = f.y;
    }
    for (int u = t; u < 4096; u += 256) {
        int q = u >> 6, d = u & 63;
        sQt[d * 68 + q] = g_scratch[OFF_Q + qbase + u];
    }
    __syncthreads();
    {
        int q0 = (t & 7) * 8, kk0 = (t >> 3) * 8;
        float acc[8][8];
#pragma unroll
        for (int i = 0; i < 8; i++)
#pragma unroll
            for (int j = 0; j < 8; j++) acc[i][j] = 0.f;
        for (int d = 0; d < 64; d++) {
            float a[8], bb[8];
            *(float4*)&a[0] = *(float4*)&sQt[d * 68 + q0];
            *(float4*)&a[4] = *(float4*)&sQt[d * 68 + q0 + 4];
            *(float4*)&bb[0] = *(float4*)&sKt[d * 260 + kk0];
            *(float4*)&bb[4] = *(float4*)&sKt[d * 260 + kk0 + 4];
#pragma unroll
            for (int i = 0; i < 8; i++)
#pragma unroll
                for (int j = 0; j < 8; j++) acc[i][j] += bb[i] * a[j];
        }
#pragma unroll
        for (int i = 0; i < 8; i++)
#pragma unroll
            for (int j = 0; j < 8; j += 4) {
                float4 v = make_float4(acc[i][j] * 0.125f, acc[i][j + 1] * 0.125f,
                                       acc[i][j + 2] * 0.125f, acc[i][j + 3] * 0.125f);
                *(float4*)&sS[(kk0 + i) * 68 + q0 + j] = v;
            }
    }
    __syncthreads();
    {
        int w = t >> 5, lane = t & 31;
#pragma unroll
        for (int qq = 0; qq < 8; qq++) {
            int q = w * 8 + qq;
            float vals[8];
#pragma unroll
            for (int j = 0; j < 8; j++) vals[j] = sS[(lane + j * 32) * 68 + q];
            float m = vals[0];
#pragma unroll
            for (int j = 1; j < 8; j++) m = fmaxf(m, vals[j]);
            for (int o = 16; o; o >>= 1) m = fmaxf(m, __shfl_xor_sync(~0u, m, o));
            float sum = 0.f;
#pragma unroll
            for (int j = 0; j < 8; j++) { vals[j] = __expf(vals[j] - m); sum += vals[j]; }
            for (int o = 16; o; o >>= 1) sum += __shfl_xor_sync(~0u, sum, o);
            float inv = 1.f / sum;
#pragma unroll
            for (int j = 0; j < 8; j++) sS[(lane + j * 32) * 68 + q] = vals[j] * inv;
        }
    }
    __syncthreads();
    for (int u2 = t; u2 < 8192; u2 += 256) {
        uint32_t raw = VH32[(kbase >> 1) + u2];
        *(float2*)&sKt[u2 * 2] = __half22float2(*(__half2*)&raw);
    }
    __syncthreads();
    {
        int pq = (t >> 4) * 4, pd = (t & 15) * 4;
        float o[4][4];
#pragma unroll
        for (int i = 0; i < 4; i++)
#pragma unroll
            for (int j = 0; j < 4; j++) o[i][j] = 0.f;
        for (int kk = 0; kk < 256; kk++) {
            float a[4], bb[4];
            *(float4*)&a[0] = *(float4*)&sS[kk * 68 + pq];
            *(float4*)&bb[0] = *(float4*)&sKt[kk * 64 + pd];
#pragma unroll
            for (int i = 0; i < 4; i++)
#pragma unroll
                for (int j = 0; j < 4; j++) o[i][j] += a[i] * bb[j];
        }
#pragma unroll
        for (int i = 0; i < 4; i++) {
            float4 v = make_float4(o[i][0], o[i][1], o[i][2], o[i][3]);
            *(float4*)&g_scratch[OFF_SOUT + qbase + (size_t)(pq + i) * 64 + pd] = v;
        }
    }
}

// ---------------- gates: 16 rows per block, Wg register-cached ----------------
__global__ void __launch_bounds__(256) k_gates(const float* __restrict__ Wg,
                                               const float* __restrict__ bgv) {
    __shared__ float sx[16 * 512];     // 32 KB
    int r0 = blockIdx.x * 16;
    int t = threadIdx.x;
    for (int u = t; u < 8192; u += 256)
        sx[u] = g_scratch[OFF_INP + (size_t)r0 * 512 + u];
    __syncthreads();
    int w = t >> 5, lane = t & 31;
    for (int o = w; o < 24; o += 8) {
        float wreg[16];
#pragma unroll
        for (int j = 0; j < 16; j++) wreg[j] = Wg[(size_t)(lane + j * 32) * 24 + o];
        float bo = bgv[o];
#pragma unroll
        for (int row = 0; row < 16; row++) {
            float acc = 0.f;
            const float* xr = sx + row * 512 + lane;
#pragma unroll
            for (int j = 0; j < 16; j++) acc += wreg[j] * xr[j * 32];
            for (int off = 16; off; off >>= 1) acc += __shfl_xor_sync(~0u, acc, off);
            if (lane == 0)
                g_scratch[OFF_GATES + (size_t)(r0 + row) * 24 + o] =
                    1.f / (1.f + __expf(-(acc + bo)));
        }
    }
}

// ---------------- combine (bf16 hi/lo output) ----------------
__global__ void k_combine() {
    int pid = blockIdx.x * blockDim.x + threadIdx.x;
    if (pid >= 1048576) return;
    int idx0 = pid * 2;
    int d = idx0 & 63;
    int hh = (idx0 >> 6) & 7;
    int ri = idx0 >> 9;
    int b = ri >> 11, i = ri & 2047;
    size_t hidx = (((size_t)(b * 8 + hh) * 2048 + i) * 64 + d);
    const float* gg = g_scratch + OFF_GATES + (size_t)ri * 24 + hh * 3;
    float o0 = gg[0] * g_scratch[OFF_COUT + hidx] + gg[1] * g_scratch[OFF_FOUT + hidx] +
               gg[2] * g_scratch[OFF_SOUT + hidx];
    float o1 = gg[0] * g_scratch[OFF_COUT + hidx + 1] + gg[1] * g_scratch[OFF_FOUT + hidx + 1] +
               gg[2] * g_scratch[OFF_SOUT + hidx + 1];
    uint32_t hp, lp;
    bf_split_pack(o0, o1, hp, lp);
    ((uint32_t*)(g_scratch + OFF_COMB_HI))[pid] = hp;
    ((uint32_t*)(g_scratch + OFF_COMB_LO))[pid] = lp;
}

// ---------------- host ----------------
extern "C" void kernel_launch(void* const* d_in, const int* in_sizes, int n_in,
                              void* d_out, int out_size) {
    const float* x     = (const float*)d_in[0];
    const float* pos   = (const float*)d_in[1];
    const float* pe_W  = (const float*)d_in[2];
    const float* pe_b  = (const float*)d_in[3];
    const float* nsc   = (const float*)d_in[4];
    const float* Wqkv  = (const float*)d_in[5];
    const float* k_pos = (const float*)d_in[6];
    const float* v_pos = (const float*)d_in[7];
    const float* kcW1  = (const float*)d_in[8];
    const float* kcb1  = (const float*)d_in[9];
    const float* kcW2  = (const float*)d_in[10];
    const float* kcb2  = (const float*)d_in[11];
    const float* vcW1  = (const float*)d_in[12];
    const float* vcb1  = (const float*)d_in[13];
    const float* vcW2  = (const float*)d_in[14];
    const float* vcb2  = (const float*)d_in[15];
    const float* mem_k = (const float*)d_in[16];
    const float* mem_v = (const float*)d_in[17];
    const float* Wg    = (const float*)d_in[18];
    const float* bgv   = (const float*)d_in[19];
    const float* Wo    = (const float*)d_in[20];
    float* out = (float*)d_out;

    float* S = nullptr;
    cudaGetSymbolAddress((void**)&S, g_scratch);
    const uint16_t* WQKV_HI = (const uint16_t*)(S + OFF_WQKV_HI);
    const uint16_t* WQKV_LO = (const uint16_t*)(S + OFF_WQKV_LO);
    const uint16_t* WOHI    = (const uint16_t*)(S + OFF_WO_HI);
    const uint16_t* WOLO    = (const uint16_t*)(S + OFF_WO_LO);
    const uint16_t* INP_HI  = (const uint16_t*)(S + OFF_INP_HI);
    const uint16_t* INP_LO  = (const uint16_t*)(S + OFF_INP_LO);
    const uint16_t* KBM_HI  = (const uint16_t*)(S + OFF_KBM_HI);
    const uint16_t* KBM_LO  = (const uint16_t*)(S + OFF_KBM_LO);
    const uint16_t* VBM_HI  = (const uint16_t*)(S + OFF_VBM_HI);
    const uint16_t* VBM_LO  = (const uint16_t*)(S + OFF_VBM_LO);
    const uint16_t* COMB_HI = (const uint16_t*)(S + OFF_COMB_HI);
    const uint16_t* COMB_LO = (const uint16_t*)(S + OFF_COMB_LO);

    cudaFuncSetAttribute(k_fine, cudaFuncAttributeMaxDynamicSharedMemorySize, FINE_SMEM);
    cudaFuncSetAttribute(k_slide, cudaFuncAttributeMaxDynamicSharedMemorySize, SLIDE_SMEM);
    cudaFuncSetAttribute(k_c2, cudaFuncAttributeMaxDynamicSharedMemorySize, C2_SMEM);
    cudaFuncSetAttribute(k_mgemm<2>, cudaFuncAttributeMaxDynamicSharedMemorySize, MG_SMEM2);
    cudaFuncSetAttribute(k_wgemm, cudaFuncAttributeMaxDynamicSharedMemorySize, WG_SMEM);

    k_cvtw<<<640, 256>>>(Wqkv, Wo);
    k_posmean<<<64, 64>>>(pos);
    k_pe_norm<<<4096, 256>>>(x, pos, pe_W, pe_b, nsc);

    // qkv = inp @ Wqkv : M=4096 N=768 K=512  (launch #4 -> ncu capture)
    k_mgemm<2><<<dim3(12, 32, 1), 256, MG_SMEM2>>>(INP_HI, INP_LO, WQKV_HI, WQKV_LO, S + OFF_QKV,
                                                   768, 512, 512, 1);
    k_split_rope<<<4096, 384>>>();
    k_buildmats<<<1024, 256>>>(k_pos, v_pos);

    // fused kc1+vc1, split-K 4, fp32 weights converted in-kernel
    k_wgemm<<<dim3(32, 1, 8), 256, WG_SMEM>>>(KBM_HI, KBM_LO, kcW1, S + OFF_PART,
                                              VBM_HI, VBM_LO, vcW1, S + OFF_PART + 2097152,
                                              4096, 4096, 1024, 4);
    k_c1red<<<1024, 256>>>(kcb1, vcb1);
    k_c2<<<64, 256, C2_SMEM>>>(kcW2, kcb2, vcW2, vcb2);
    k_pack<<<(8448 + 255) / 256, 256>>>(mem_k, mem_v);

    k_coarse<<<8192, 128>>>();
    k_topk<<<32, 256>>>();
    k_fine<<<8192, 256, FINE_SMEM>>>();
    k_slide<<<512, 256, SLIDE_SMEM>>>();
    k_gates<<<256, 256>>>(Wg, bgv);
    k_combine<<<4096, 256>>>();

    // out = comb @ Wo : M=4096 N=512 K=512
    k_mgemm<2><<<dim3(8, 32, 1), 256, MG_SMEM2>>>(COMB_HI, COMB_LO, WOHI, WOLO, out,
                                                  512, 512, 512, 1);
}

// round 15
// speedup vs baseline: 1.1922x; 1.1208x over previous
#include <cuda_runtime.h>
#include <cuda_bf16.h>
#include <cuda_fp16.h>
#include <math.h>
#include <stdint.h>

// ---------------- scratch layout (floats) ----------------
#define OFF_INP      0ul
#define OFF_QKV      2097152ul
#define OFF_Q        5242880ul
#define OFF_K        7340032ul
#define OFF_KRH      7864320ul
#define OFF_VH       8126464ul
#define OFF_V        8388608ul
#define OFF_KHID     8912896ul
#define OFF_VHID     9437184ul
#define OFF_CKRAW    9961472ul
#define OFF_CVRAW    9969664ul
#define OFF_CK       9977856ul
#define OFF_CV       9986304ul
#define OFF_COUT     9994752ul
#define OFF_FOUT    12091904ul
#define OFF_SOUT    14189056ul
#define OFF_IMP     16286208ul
#define OFF_SELVAL  16548352ul
#define OFF_GATES   16564736ul
#define OFF_PM      16663040ul
#define OFF_PART    16663296ul
#define OFF_WQKV_HI 20857600ul
#define OFF_WQKV_LO 21054208ul
#define OFF_WO_HI   21250816ul
#define OFF_WO_LO   21381888ul
#define OFF_INP_HI  21512960ul
#define OFF_INP_LO  22561536ul
#define OFF_KBM_HI  23610112ul
#define OFF_KBM_LO  23872256ul
#define OFF_VBM_HI  24134400ul
#define OFF_VBM_LO  24396544ul
#define OFF_COMB_HI 24658688ul
#define OFF_COMB_LO 25707264ul
#define OFF_QH      26755840ul   /* Q as half: 2097152 halves */
#define SCRATCH_SZ  27804416ul

__device__ float g_scratch[SCRATCH_SZ];
__device__ int   g_selidx[2 * 2 * 2048 * 2];

// ================= helpers ============
__device__ __forceinline__ uint32_t smem_u32(const void* p) {
    uint32_t a;
    asm("{ .reg .u64 tmp; cvta.to.shared.u64 tmp, %1; cvt.u32.u64 %0, tmp; }"
        : "=r"(a) : "l"(p));
    return a;
}
__device__ __forceinline__ void ldsm_x4(uint32_t& r0, uint32_t& r1, uint32_t& r2, uint32_t& r3,
                                        uint32_t addr) {
    asm volatile("ldmatrix.sync.aligned.m8n8.x4.shared.b16 {%0,%1,%2,%3}, [%4];"
                 : "=r"(r0), "=r"(r1), "=r"(r2), "=r"(r3) : "r"(addr));
}
__device__ __forceinline__ void ldsm_x4t(uint32_t& r0, uint32_t& r1, uint32_t& r2, uint32_t& r3,
                                         uint32_t addr) {
    asm volatile("ldmatrix.sync.aligned.m8n8.x4.trans.shared.b16 {%0,%1,%2,%3}, [%4];"
                 : "=r"(r0), "=r"(r1), "=r"(r2), "=r"(r3) : "r"(addr));
}
__device__ __forceinline__ void mma16816(float* c, uint32_t a0, uint32_t a1, uint32_t a2,
                                         uint32_t a3, uint32_t b0, uint32_t b1) {
    asm volatile("mma.sync.aligned.m16n8k16.row.col.f32.bf16.bf16.f32 "
                 "{%0,%1,%2,%3}, {%4,%5,%6,%7}, {%8,%9}, {%0,%1,%2,%3};"
                 : "+f"(c[0]), "+f"(c[1]), "+f"(c[2]), "+f"(c[3])
                 : "r"(a0), "r"(a1), "r"(a2), "r"(a3), "r"(b0), "r"(b1));
}
__device__ __forceinline__ void mma16816h(float* c, uint32_t a0, uint32_t a1, uint32_t a2,
                                          uint32_t a3, uint32_t b0, uint32_t b1) {
    asm volatile("mma.sync.aligned.m16n8k16.row.col.f32.f16.f16.f32 "
                 "{%0,%1,%2,%3}, {%4,%5,%6,%7}, {%8,%9}, {%0,%1,%2,%3};"
                 : "+f"(c[0]), "+f"(c[1]), "+f"(c[2]), "+f"(c[3])
                 : "r"(a0), "r"(a1), "r"(a2), "r"(a3), "r"(b0), "r"(b1));
}
__device__ __forceinline__ void bf_split_pack(float x0, float x1, uint32_t& hp, uint32_t& lp) {
    uint32_t u0 = __float_as_uint(x0), u1 = __float_as_uint(x1);
    hp = __byte_perm(u0, u1, 0x7632);
    float l0 = x0 - __uint_as_float(u0 & 0xFFFF0000u);
    float l1 = x1 - __uint_as_float(u1 & 0xFFFF0000u);
    asm("cvt.rn.bf16x2.f32 %0, %1, %2;" : "=r"(lp) : "f"(l1), "f"(l0));
}
__device__ __forceinline__ void cp16(uint32_t s, const void* g) {
    asm volatile("cp.async.cg.shared.global [%0], [%1], 16;" :: "r"(s), "l"(g));
}

// ---------------- weight conversion (Wqkv + Wo only) ----------------
__global__ void k_cvtw(const float* __restrict__ Wqkv, const float* __restrict__ Wo) {
    size_t q = (size_t)blockIdx.x * 256 + threadIdx.x;
    if (q >= 163840ul) return;
    const float* src;
    uint32_t *hi, *lo;
    size_t local;
    if (q < 98304ul) {
        src = Wqkv; local = q;
        hi = (uint32_t*)(g_scratch + OFF_WQKV_HI); lo = (uint32_t*)(g_scratch + OFF_WQKV_LO);
    } else {
        src = Wo; local = q - 98304ul;
        hi = (uint32_t*)(g_scratch + OFF_WO_HI); lo = (uint32_t*)(g_scratch + OFF_WO_LO);
    }
    float4 v = ((const float4*)src)[local];
    uint32_t h0, l0, h1, l1;
    bf_split_pack(v.x, v.y, h0, l0);
    bf_split_pack(v.z, v.w, h1, l1);
    ((uint2*)hi)[local] = make_uint2(h0, h1);
    ((uint2*)lo)[local] = make_uint2(l0, l1);
}

// ======== cp.async pipelined bf16x3 MMA GEMM, templated N-tile (preconv B) ====
#define APAD 40
extern __shared__ uint16_t mgs[];
template <int NTILES>
__global__ void __launch_bounds__(256, 2)
k_mgemm(const uint16_t* __restrict__ Ahi0, const uint16_t* __restrict__ Alo0,
        const uint16_t* __restrict__ Bhi0, const uint16_t* __restrict__ Blo0,
        float* __restrict__ C0,
        int N, int K, int klen, int nchunks) {
    constexpr int BN = NTILES * 32;
    constexpr int BPADT = BN + 8;
    constexpr int BOFF = 10240;
    constexpr int BLO = BOFF + 32 * BPADT;
    constexpr int BUF = BLO + 32 * BPADT;
    uint32_t sb = smem_u32(mgs);
    int chunk = blockIdx.z;
    float* C = C0 + (size_t)chunk * gridDim.y * 128 * N;
    int kstart = chunk * klen;
    int t = threadIdx.x, wid = t >> 5, lane = t & 31;
    int bx = blockIdx.x, by = blockIdx.y;
    int warp_m = wid >> 2, warp_n = wid & 3;

    float acc[4][NTILES][4];
#pragma unroll
    for (int mt = 0; mt < 4; mt++)
#pragma unroll
        for (int nt = 0; nt < NTILES; nt++)
#pragma unroll
            for (int e = 0; e < 4; e++) acc[mt][nt][e] = 0.f;

    int a_row = (lane & 15), a_kc8 = 8 * (lane >> 4);
    int b_krow = (lane & 15), b_n8 = 8 * (lane >> 4);
    int nch = klen / 32;
    const uint16_t* Ah = Ahi0 + (size_t)(by * 128) * K + kstart;
    const uint16_t* Al = Alo0 + (size_t)(by * 128) * K + kstart;
    const uint16_t* Bh = Bhi0 + (size_t)kstart * N + bx * BN;
    const uint16_t* Bl = Blo0 + (size_t)kstart * N + bx * BN;

    auto stage = [&](int buf, int cc) {
        uint32_t soff = sb + buf * (BUF * 2);
#pragma unroll
        for (int h = 0; h < 2; h++) {
            int u = t + h * 256;
            int row = u >> 2, seg = u & 3;
            size_t go = (size_t)row * K + (size_t)cc * 32 + seg * 8;
            cp16(soff + (row * APAD + seg * 8) * 2, Ah + go);
            cp16(soff + (5120 + row * APAD + seg * 8) * 2, Al + go);
        }
#pragma unroll
        for (int h = 0; h < NTILES / 2; h++) {
            int u = t + h * 256;
            int row, seg;
            if (NTILES == 4) { row = u >> 4; seg = u & 15; }
            else { row = u >> 3; seg = u & 7; }
            size_t go = (size_t)(cc * 32 + row) * N + seg * 8;
            cp16(soff + (BOFF + row * BPADT + seg * 8) * 2, Bh + go);
            cp16(soff + (BLO + row * BPADT + seg * 8) * 2, Bl + go);
        }
        asm volatile("cp.async.commit_group;" ::: "memory");
    };

    stage(0, 0);
    for (int c = 0; c < nch; c++) {
        int buf = c & 1;
        if (c + 1 < nch) {
            stage(buf ^ 1, c + 1);
            asm volatile("cp.async.wait_group 1;" ::: "memory");
        } else {
            asm volatile("cp.async.wait_group 0;" ::: "memory");
        }
        __syncthreads();
        uint32_t abase = sb + buf * (BUF * 2);
#pragma unroll
        for (int ks = 0; ks < 2; ks++) {
            uint32_t af[4][4], bh[NTILES][2], bl[NTILES][2];
#pragma unroll
            for (int mt = 0; mt < 4; mt++) {
                int off = (warp_m * 64 + mt * 16 + a_row) * APAD + ks * 16 + a_kc8;
                ldsm_x4(af[mt][0], af[mt][1], af[mt][2], af[mt][3], abase + off * 2);
            }
#pragma unroll
            for (int n2 = 0; n2 < NTILES / 2; n2++) {
                int off = BOFF + (ks * 16 + b_krow) * BPADT + warp_n * (NTILES * 8) + n2 * 16 + b_n8;
                ldsm_x4t(bh[n2 * 2][0], bh[n2 * 2][1], bh[n2 * 2 + 1][0], bh[n2 * 2 + 1][1],
                         abase + off * 2);
                ldsm_x4t(bl[n2 * 2][0], bl[n2 * 2][1], bl[n2 * 2 + 1][0], bl[n2 * 2 + 1][1],
                         abase + (off + 32 * BPADT) * 2);
            }
#pragma unroll
            for (int mt = 0; mt < 4; mt++)
#pragma unroll
                for (int nt = 0; nt < NTILES; nt++) {
                    mma16816(acc[mt][nt], af[mt][0], af[mt][1], af[mt][2], af[mt][3],
                             bh[nt][0], bh[nt][1]);
                    mma16816(acc[mt][nt], af[mt][0], af[mt][1], af[mt][2], af[mt][3],
                             bl[nt][0], bl[nt][1]);
                }
#pragma unroll
            for (int mt = 0; mt < 4; mt++) {
                int off = 5120 + (warp_m * 64 + mt * 16 + a_row) * APAD + ks * 16 + a_kc8;
                ldsm_x4(af[mt][0], af[mt][1], af[mt][2], af[mt][3], abase + off * 2);
            }
#pragma unroll
            for (int mt = 0; mt < 4; mt++)
#pragma unroll
                for (int nt = 0; nt < NTILES; nt++)
                    mma16816(acc[mt][nt], af[mt][0], af[mt][1], af[mt][2], af[mt][3],
                             bh[nt][0], bh[nt][1]);
        }
        __syncthreads();
    }
    int g = lane >> 2, tid4 = lane & 3;
#pragma unroll
    for (int mt = 0; mt < 4; mt++) {
        int row0 = by * 128 + warp_m * 64 + mt * 16 + g;
#pragma unroll
        for (int nt = 0; nt < NTILES; nt++) {
            int col = bx * BN + warp_n * (NTILES * 8) + nt * 8 + tid4 * 2;
            *(float2*)&C[(size_t)row0 * N + col] = make_float2(acc[mt][nt][0], acc[mt][nt][1]);
            *(float2*)&C[(size_t)(row0 + 8) * N + col] = make_float2(acc[mt][nt][2], acc[mt][nt][3]);
        }
    }
}
#define MG_SMEM2 ((10240 + 2 * 32 * 72) * 4)

// ======== c1 GEMM: A preconv bf16 (cp.async), B fp32 (cp.async + smem convert) ====
#define WG_BPADT 136
#define WG_BOFF  10240
#define WG_BLO   (WG_BOFF + 32 * WG_BPADT)
#define WG_BUF   (WG_BLO + 32 * WG_BPADT)
#define WG_SLOT0 (2 * WG_BUF * 2)
#define WG_SMEM  (WG_SLOT0 + 2 * 16384)
extern __shared__ uint16_t wgs[];
__global__ void __launch_bounds__(256, 2)
k_wgemm(const uint16_t* __restrict__ Ahi0, const uint16_t* __restrict__ Alo0,
        const float* __restrict__ Bf0, float* __restrict__ C0,
        const uint16_t* __restrict__ Ahi1, const uint16_t* __restrict__ Alo1,
        const float* __restrict__ Bf1, float* __restrict__ C1,
        int N, int K, int klen, int nchunks) {
    uint32_t sb = smem_u32(wgs);
    int z = blockIdx.z;
    int comp = z / nchunks, chunk = z - comp * nchunks;
    const uint16_t* Ahi = comp ? Ahi1 : Ahi0;
    const uint16_t* Alo = comp ? Alo1 : Alo0;
    const float* Bf = comp ? Bf1 : Bf0;
    float* C = (comp ? C1 : C0) + (size_t)chunk * 128 * N;
    int kstart = chunk * klen;
    int t = threadIdx.x, wid = t >> 5, lane = t & 31;
    int bx = blockIdx.x;
    int warp_m = wid >> 2, warp_n = wid & 3;

    float acc[4][4][4];
#pragma unroll
    for (int mt = 0; mt < 4; mt++)
#pragma unroll
        for (int nt = 0; nt < 4; nt++)
#pragma unroll
            for (int e = 0; e < 4; e++) acc[mt][nt][e] = 0.f;

    int a_row = (lane & 15), a_kc8 = 8 * (lane >> 4);
    int b_krow = (lane & 15), b_n8 = 8 * (lane >> 4);
    int nch = klen / 32;
    const uint16_t* Ah = Ahi + kstart;
    const uint16_t* Al = Alo + kstart;
    const float* Bb = Bf + (size_t)kstart * N + bx * 128;

    auto stageA = [&](int buf, int cc) {
        uint32_t soff = sb + buf * (WG_BUF * 2);
#pragma unroll
        for (int h = 0; h < 2; h++) {
            int u = t + h * 256;
            int row = u >> 2, seg = u & 3;
            size_t go = (size_t)row * K + (size_t)cc * 32 + seg * 8;
            cp16(soff + (row * APAD + seg * 8) * 2, Ah + go);
            cp16(soff + (5120 + row * APAD + seg * 8) * 2, Al + go);
        }
    };
    auto stageB = [&](int buf, int cc) {
        uint32_t soff = sb + WG_SLOT0 + buf * 16384;
#pragma unroll
        for (int h = 0; h < 4; h++) {
            int u = t + h * 256;
            int row = u >> 5, seg = u & 31;
            cp16(soff + u * 16, Bb + (size_t)(cc * 32 + row) * N + seg * 4);
        }
    };

    stageA(0, 0);
    stageB(0, 0);
    asm volatile("cp.async.commit_group;" ::: "memory");
    for (int c = 0; c < nch; c++) {
        int buf = c & 1;
        asm volatile("cp.async.wait_group 0;" ::: "memory");
        __syncthreads();
        {
            const float2* slot = (const float2*)((char*)wgs + WG_SLOT0 + buf * 16384);
            char* bufp = (char*)wgs + buf * (WG_BUF * 2);
#pragma unroll
            for (int p = 0; p < 8; p++) {
                int u2 = t + p * 256;
                int row = u2 >> 6, c2 = u2 & 63;
                float2 v = slot[u2];
                uint32_t hp, lp;
                bf_split_pack(v.x, v.y, hp, lp);
                *(uint32_t*)(bufp + (WG_BOFF + row * WG_BPADT + c2 * 2) * 2) = hp;
                *(uint32_t*)(bufp + (WG_BLO + row * WG_BPADT + c2 * 2) * 2) = lp;
            }
        }
        __syncthreads();
        if (c + 1 < nch) {
            stageA(buf ^ 1, c + 1);
            stageB(buf ^ 1, c + 1);
            asm volatile("cp.async.commit_group;" ::: "memory");
        }
        uint32_t abase = sb + buf * (WG_BUF * 2);
#pragma unroll
        for (int ks = 0; ks < 2; ks++) {
            uint32_t af[4][4], bh[4][2], bl[4][2];
#pragma unroll
            for (int mt = 0; mt < 4; mt++) {
                int off = (warp_m * 64 + mt * 16 + a_row) * APAD + ks * 16 + a_kc8;
                ldsm_x4(af[mt][0], af[mt][1], af[mt][2], af[mt][3], abase + off * 2);
            }
#pragma unroll
            for (int n2 = 0; n2 < 2; n2++) {
                int off = WG_BOFF + (ks * 16 + b_krow) * WG_BPADT + warp_n * 32 + n2 * 16 + b_n8;
                ldsm_x4t(bh[n2 * 2][0], bh[n2 * 2][1], bh[n2 * 2 + 1][0], bh[n2 * 2 + 1][1],
                         abase + off * 2);
                ldsm_x4t(bl[n2 * 2][0], bl[n2 * 2][1], bl[n2 * 2 + 1][0], bl[n2 * 2 + 1][1],
                         abase + (off + 32 * WG_BPADT) * 2);
            }
#pragma unroll
            for (int mt = 0; mt < 4; mt++)
#pragma unroll
                for (int nt = 0; nt < 4; nt++) {
                    mma16816(acc[mt][nt], af[mt][0], af[mt][1], af[mt][2], af[mt][3],
                             bh[nt][0], bh[nt][1]);
                    mma16816(acc[mt][nt], af[mt][0], af[mt][1], af[mt][2], af[mt][3],
                             bl[nt][0], bl[nt][1]);
                }
#pragma unroll
            for (int mt = 0; mt < 4; mt++) {
                int off = 5120 + (warp_m * 64 + mt * 16 + a_row) * APAD + ks * 16 + a_kc8;
                ldsm_x4(af[mt][0], af[mt][1], af[mt][2], af[mt][3], abase + off * 2);
            }
#pragma unroll
            for (int mt = 0; mt < 4; mt++)
#pragma unroll
                for (int nt = 0; nt < 4; nt++)
                    mma16816(acc[mt][nt], af[mt][0], af[mt][1], af[mt][2], af[mt][3],
                             bh[nt][0], bh[nt][1]);
        }
        __syncthreads();
    }
    int g = lane >> 2, tid4 = lane & 3;
#pragma unroll
    for (int mt = 0; mt < 4; mt++) {
        int row0 = warp_m * 64 + mt * 16 + g;
#pragma unroll
        for (int nt = 0; nt < 4; nt++) {
            int col = bx * 128 + warp_n * 32 + nt * 8 + tid4 * 2;
            *(float2*)&C[(size_t)row0 * N + col] = make_float2(acc[mt][nt][0], acc[mt][nt][1]);
            *(float2*)&C[(size_t)(row0 + 8) * N + col] = make_float2(acc[mt][nt][2], acc[mt][nt][3]);
        }
    }
}

// ---------------- c1 split-K reduce + bias + relu ----------------
__global__ void k_c1red(const float* __restrict__ kcb1, const float* __restrict__ vcb1) {
    int u4 = blockIdx.x * 256 + threadIdx.x;
    int comp = u4 >> 17;
    int loc = u4 & 131071;
    int col4 = loc & 1023;
    const float* P = g_scratch + OFF_PART + (size_t)comp * 2097152 + (size_t)loc * 4;
    float4 s0 = *(const float4*)(P);
    float4 s1 = *(const float4*)(P + 524288);
    float4 s2 = *(const float4*)(P + 1048576);
    float4 s3 = *(const float4*)(P + 1572864);
    const float* bias = comp ? vcb1 : kcb1;
    float4 b = *(const float4*)&bias[col4 * 4];
    float4 o;
    o.x = fmaxf(s0.x + s1.x + s2.x + s3.x + b.x, 0.f);
    o.y = fmaxf(s0.y + s1.y + s2.y + s3.y + b.y, 0.f);
    o.z = fmaxf(s0.z + s1.z + s2.z + s3.z + b.z, 0.f);
    o.w = fmaxf(s0.w + s1.w + s2.w + s3.w + b.w, 0.f);
    float* O = g_scratch + (comp ? OFF_VHID : OFF_KHID) + (size_t)loc * 4;
    *(float4*)O = o;
}

// ---------------- pos block means ----------------
__global__ void k_posmean(const float* __restrict__ pos) {
    int blk = blockIdx.x;
    int t = threadIdx.x;
    __shared__ float s[64 * 3];
    s[t * 3 + 0] = pos[(blk * 64 + t) * 3 + 0];
    s[t * 3 + 1] = pos[(blk * 64 + t) * 3 + 1];
    s[t * 3 + 2] = pos[(blk * 64 + t) * 3 + 2];
    __syncthreads();
    if (t < 3) {
        float sum = 0.f;
        for (int i = 0; i < 64; i++) sum += s[i * 3 + t];
        g_scratch[OFF_PM + blk * 3 + t] = sum / 64.f;
    }
}

// ---------------- PE add + RMSNorm (+ bf16 hi/lo output) ----------------
__global__ void k_pe_norm(const float* __restrict__ x, const float* __restrict__ pos,
                          const float* __restrict__ peW, const float* __restrict__ peb,
                          const float* __restrict__ nsc) {
    int r = blockIdx.x;
    int t = threadIdx.x;
    int blk = r >> 6;
    float r0 = pos[r * 3 + 0] - g_scratch[OFF_PM + blk * 3 + 0];
    float r1 = pos[r * 3 + 1] - g_scratch[OFF_PM + blk * 3 + 1];
    float r2 = pos[r * 3 + 2] - g_scratch[OFF_PM + blk * 3 + 2];
    int c0 = t * 2, c1 = c0 + 1;
    float v0 = x[(size_t)r * 512 + c0] + r0 * peW[c0] + r1 * peW[512 + c0] + r2 * peW[1024 + c0] + peb[c0];
    float v1 = x[(size_t)r * 512 + c1] + r0 * peW[c1] + r1 * peW[512 + c1] + r2 * peW[1024 + c1] + peb[c1];
    __shared__ float red[256];
    red[t] = v0 * v0 + v1 * v1;
    __syncthreads();
    for (int s = 128; s > 0; s >>= 1) {
        if (t < s) red[t] += red[t + s];
        __syncthreads();
    }
    float rms = rsqrtf(red[0] / 512.f + 1e-6f);
    float s0 = v0 * rms * nsc[c0];
    float s1 = v1 * rms * nsc[c1];
    g_scratch[OFF_INP + (size_t)r * 512 + c0] = s0;
    g_scratch[OFF_INP + (size_t)r * 512 + c1] = s1;
    uint32_t hp, lp;
    bf_split_pack(s0, s1, hp, lp);
    ((uint32_t*)(g_scratch + OFF_INP_HI))[(size_t)r * 256 + t] = hp;
    ((uint32_t*)(g_scratch + OFF_INP_LO))[(size_t)r * 256 + t] = lp;
}

// ---------------- c2: 4 rows per block (64 blocks) ----------------
#define C2_SMEM ((16384 + 1024) * 4)
extern __shared__ float c2sm[];
__global__ void k_c2(const float* __restrict__ kcW2, const float* __restrict__ kcb2,
                     const float* __restrict__ vcW2, const float* __restrict__ vcb2) {
    float* sa = c2sm;
    float* red = c2sm + 16384;
    int blk = blockIdx.x;
    int comp = blk >> 5, rg = blk & 31;
    const float* A = g_scratch + (comp ? OFF_VHID : OFF_KHID) + (size_t)(rg * 4) * 4096;
    const float* W = comp ? vcW2 : kcW2;
    const float* bias = comp ? vcb2 : kcb2;
    float* Cout = g_scratch + (comp ? OFF_CVRAW : OFF_CKRAW) + (size_t)(rg * 4) * 64;
    int t = threadIdx.x;
    for (int u = t; u < 16384; u += 256) {
        int r = u >> 12, kk = u & 4095;
        sa[kk * 4 + r] = A[(size_t)r * 4096 + kk];
    }
    __syncthreads();
    int o = t & 63, sub = t >> 6;
    const float* Wp = W + (size_t)(sub * 1024) * 64 + o;
    float acc0 = 0.f, acc1 = 0.f, acc2 = 0.f, acc3 = 0.f;
    const float* ap = sa + sub * 1024 * 4;
#pragma unroll 4
    for (int kk = 0; kk < 1024; kk++) {
        float w = Wp[(size_t)kk * 64];
        float4 a = *(const float4*)(ap + kk * 4);
        acc0 += a.x * w; acc1 += a.y * w; acc2 += a.z * w; acc3 += a.w * w;
    }
    red[t * 4 + 0] = acc0; red[t * 4 + 1] = acc1;
    red[t * 4 + 2] = acc2; red[t * 4 + 3] = acc3;
    __syncthreads();
    if (t < 64) {
        float b = bias[t];
#pragma unroll
        for (int r = 0; r < 4; r++) {
            float v = red[t * 4 + r] + red[(64 + t) * 4 + r] + red[(128 + t) * 4 + r] +
                      red[(192 + t) * 4 + r] + b;
            Cout[r * 64 + t] = v;
        }
    }
}

// ---------------- split qkv + rope (+ half Q) ----------------
__global__ void k_split_rope() {
    int r = blockIdx.x;
    int b = r >> 11;
    int i = r & 2047;
    int t = threadIdx.x;          // 384
    const float* qkv = g_scratch + OFF_QKV + (size_t)r * 768;
    if (t < 256) {
        int col = t * 2;
        int head = col >> 6, d = col & 63, j = d >> 1;
        float inv = powf(10000.f, -(float)j / 32.f);
        float cs, sn;
        sincosf((float)i * inv, &sn, &cs);
        float a = qkv[col], bb = qkv[col + 1];
        float o0 = a * cs - bb * sn;
        float o1 = bb * cs + a * sn;
        size_t base = (((size_t)(b * 8 + head) * 2048 + i) * 64 + d);
        g_scratch[OFF_Q + base] = o0;
        g_scratch[OFF_Q + base + 1] = o1;
        ((__half2*)(g_scratch + OFF_QH))[base >> 1] = __floats2half2_rn(o0, o1);
    } else if (t < 320) {
        int ci = (t - 256) * 2;
        int g = ci >> 6, d = ci & 63, j = d >> 1;
        float inv = powf(10000.f, -(float)j / 32.f);
        float cs, sn;
        sincosf((float)i * inv, &sn, &cs);
        float a = qkv[512 + ci], bb = qkv[512 + ci + 1];
        size_t base = (((size_t)(b * 2 + g) * 2048 + i) * 64 + d);
        g_scratch[OFF_K + base] = a;
        g_scratch[OFF_K + base + 1] = bb;
        float kr0 = a * cs - bb * sn;
        float kr1 = bb * cs + a * sn;
        ((__half2*)(g_scratch + OFF_KRH))[base >> 1] = __floats2half2_rn(kr0, kr1);
    } else {
        int ci = (t - 320) * 2;
        int g = ci >> 6, d = ci & 63;
        size_t base = (((size_t)(b * 2 + g) * 2048 + i) * 64 + d);
        float v0 = qkv[640 + ci], v1 = qkv[640 + ci + 1];
        g_scratch[OFF_V + base] = v0;
        g_scratch[OFF_V + base + 1] = v1;
        ((__half2*)(g_scratch + OFF_VH))[base >> 1] = __floats2half2_rn(v0, v1);
    }
}

// ---------------- build compressor inputs (bf16 hi/lo) ----------------
__global__ void k_buildmats(const float* __restrict__ k_pos, const float* __restrict__ v_pos) {
    int pid = blockIdx.x * blockDim.x + threadIdx.x;
    if (pid >= 262144) return;
    int row = pid >> 11;
    int pcol = pid & 2047;
    int col0 = pcol * 2;
    int bg = row >> 5, wi = row & 31, g = bg & 1;
    int j = col0 >> 6, d = col0 & 63;
    size_t src = ((size_t)bg * 2048 + wi * 64 + j) * 64 + d;
    int poff = (g * 64 + j) * 64 + d;
    float k0 = g_scratch[OFF_K + src] + k_pos[poff];
    float k1 = g_scratch[OFF_K + src + 1] + k_pos[poff + 1];
    float w0 = g_scratch[OFF_V + src] + v_pos[poff];
    float w1 = g_scratch[OFF_V + src + 1] + v_pos[poff + 1];
    uint32_t hp, lp;
    bf_split_pack(k0, k1, hp, lp);
    ((uint32_t*)(g_scratch + OFF_KBM_HI))[pid] = hp;
    ((uint32_t*)(g_scratch + OFF_KBM_LO))[pid] = lp;
    bf_split_pack(w0, w1, hp, lp);
    ((uint32_t*)(g_scratch + OFF_VBM_HI))[pid] = hp;
    ((uint32_t*)(g_scratch + OFF_VBM_LO))[pid] = lp;
}

// ---------------- pack ck/cv with mem token ----------------
__global__ void k_pack(const float* __restrict__ mem_k, const float* __restrict__ mem_v) {
    int idx = blockIdx.x * blockDim.x + threadIdx.x;
    if (idx >= 2 * 2 * 33 * 64) return;
    int d = idx & 63;
    int rest = idx >> 6;
    int j = rest % 33;
    int bg = rest / 33;
    int g = bg & 1;
    float kv, vv;
    if (j == 0) {
        kv = mem_k[g * 64 + d];
        vv = mem_v[g * 64 + d];
    } else {
        size_t s = ((size_t)bg * 32 + (j - 1)) * 64 + d;
        kv = g_scratch[OFF_CKRAW + s];
        vv = g_scratch[OFF_CVRAW + s];
    }
    g_scratch[OFF_CK + idx] = kv;
    g_scratch[OFF_CV + idx] = vv;
}

// ---------------- coarse attention + importance (per-query) ----------
__global__ void k_coarse() {
    int bi = blockIdx.x;
    int bg = bi >> 11, i = bi & 2047;
    int b = bg >> 1, g = bg & 1;
    int t = threadIdx.x;          // 128
    __shared__ float sck[33 * 64], scv[33 * 64], sq[4 * 64], sp[4 * 36];
    for (int u = t; u < 528; u += 128) {
        *(float4*)&sck[u * 4] = *(const float4*)&g_scratch[OFF_CK + (size_t)bg * 2112 + u * 4];
        *(float4*)&scv[u * 4] = *(const float4*)&g_scratch[OFF_CV + (size_t)bg * 2112 + u * 4];
    }
    for (int u = t; u < 256; u += 128) {
        int hq = u >> 6, d = u & 63;
        sq[u] = g_scratch[OFF_Q + (((size_t)(b * 8 + g * 4 + hq) * 2048 + i) * 64 + d)];
    }
    __syncthreads();
    for (int u = t; u < 132; u += 128) {
        int hq = u / 33, j = u % 33;
        float s = -1e30f;
        if (j == 0 || j * 64 <= i) {
            float acc = 0.f;
            const float4* qv = (const float4*)&sq[hq * 64];
            const float4* kv = (const float4*)&sck[j * 64];
#pragma unroll
            for (int d4 = 0; d4 < 16; d4++) {
                float4 a = qv[d4], bb = kv[d4];
                acc += a.x * bb.x + a.y * bb.y + a.z * bb.z + a.w * bb.w;
            }
            s = acc * 0.125f;
        }
        sp[hq * 36 + j] = s;
    }
    __syncthreads();
    if (t < 4) {
        float m = -1e30f;
        for (int j = 0; j < 33; j++) m = fmaxf(m, sp[t * 36 + j]);
        float sum = 0.f;
        for (int j = 0; j < 33; j++) {
            float e = __expf(sp[t * 36 + j] - m);
            sp[t * 36 + j] = e;
            sum += e;
        }
        float inv = 1.f / sum;
        for (int j = 0; j < 33; j++) sp[t * 36 + j] *= inv;
    }
    __syncthreads();
    if (t < 32) {
        g_scratch[OFF_IMP + ((size_t)bg * 2048 + i) * 32 + t] =
            0.25f * (sp[t + 1] + sp[36 + t + 1] + sp[72 + t + 1] + sp[108 + t + 1]);
    }
    for (int u = t; u < 256; u += 128) {
        int hq = u >> 6, d = u & 63;
        float acc = 0.f;
#pragma unroll
        for (int j4 = 0; j4 < 8; j4++) {
            float4 p = *(const float4*)&sp[hq * 36 + j4 * 4];
            acc += p.x * scv[(j4 * 4 + 0) * 64 + d] + p.y * scv[(j4 * 4 + 1) * 64 + d] +
                   p.z * scv[(j4 * 4 + 2) * 64 + d] + p.w * scv[(j4 * 4 + 3) * 64 + d];
        }
        acc += sp[hq * 36 + 32] * scv[32 * 64 + d];
        g_scratch[OFF_COUT + (((size_t)(b * 8 + g * 4 + hq) * 2048 + i) * 64 + d)] = acc;
    }
}

// ---------------- top-k (k=2, stable) ----------------
__global__ void k_topk() {
    int idx = blockIdx.x * blockDim.x + threadIdx.x;
    if (idx >= 8192) return;
    const float* imp = g_scratch + OFF_IMP + (size_t)idx * 32;
    int i1 = 0;
    float v1 = imp[0];
    for (int j = 1; j < 32; j++)
        if (imp[j] > v1) { v1 = imp[j]; i1 = j; }
    int i2 = -1;
    float v2 = -1e30f;
    for (int j = 0; j < 32; j++) {
        if (j == i1) continue;
        if (imp[j] > v2) { v2 = imp[j]; i2 = j; }
    }
    g_scratch[OFF_SELVAL + idx * 2 + 0] = v1;
    g_scratch[OFF_SELVAL + idx * 2 + 1] = v2;
    g_selidx[idx * 2 + 0] = i1;
    g_selidx[idx * 2 + 1] = i2;
}

// ---------------- fine gathered attention (fp16 smem, reg-cached Q) ----------
#define FINE_SMEM (13824 * 4)
extern __shared__ float fsm[];
__global__ void __launch_bounds__(256, 2) k_fine() {
    __half* skh = (__half*)fsm;
    __half* svh = (__half*)(fsm + 6144);
    float* sq = fsm + 12288;
    float* sp = fsm + 12544;
    float* spart = fsm + 13312;
    int bi = blockIdx.x;
    int bg = bi >> 11, i = bi & 2047;
    int b = bg >> 1, g = bg & 1;
    int t = threadIdx.x;
    int own = i >> 6;
    __shared__ int blkid[3];
    __shared__ int okf[3];
    if (t < 2) {
        int si = g_selidx[bi * 2 + t];
        float sval = g_scratch[OFF_SELVAL + bi * 2 + t];
        blkid[t] = si;
        okf[t] = (sval > 0.f && si != own) ? 1 : 0;
    }
    if (t == 2) { blkid[2] = own; okf[2] = 1; }
    __syncthreads();
    size_t kbase = (size_t)bg * 2048 * 64;
    const uint4* KRH4 = (const uint4*)(g_scratch + OFF_KRH);
    const uint4* VH4 = (const uint4*)(g_scratch + OFF_VH);
#pragma unroll
    for (int u = t; u < 1536; u += 256) {
        int kk = u >> 3, d8 = u & 7;
        int kb = kk >> 6, j = kk & 63;
        size_t elem = kbase + (size_t)(blkid[kb] * 64 + j) * 64 + d8 * 8;
        ((uint4*)skh)[u] = KRH4[elem >> 3];
        ((uint4*)svh)[u] = VH4[elem >> 3];
    }
    {
        int hq = t >> 6, d = t & 63;
        sq[t] = g_scratch[OFF_Q + (((size_t)(b * 8 + g * 4 + hq) * 2048 + i) * 64 + d)];
    }
    __syncthreads();
    {
        int hq = t >> 6, j0 = t & 63;
        float4 qv[16];
        const float4* qsm = (const float4*)&sq[hq * 64];
#pragma unroll
        for (int p = 0; p < 16; p++) qv[p] = qsm[p];
        int ilocal = i & 63;
#pragma unroll
        for (int s = 0; s < 3; s++) {
            int kk = s * 64 + j0;
            bool valid = (s < 2) ? (okf[s] != 0) : (j0 <= ilocal);
            float score = -1e30f;
            if (valid) {
                float acc = 0.f;
                const uint4* kp = (const uint4*)(skh + kk * 64);
#pragma unroll
                for (int p = 0; p < 8; p++) {
                    uint4 raw = kp[p];
                    float2 f0 = __half22float2(*(__half2*)&raw.x);
                    float2 f1 = __half22float2(*(__half2*)&raw.y);
                    float2 f2 = __half22float2(*(__half2*)&raw.z);
                    float2 f3 = __half22float2(*(__half2*)&raw.w);
                    float4 q0 = qv[p * 2], q1 = qv[p * 2 + 1];
                    acc += q0.x * f0.x + q0.y * f0.y + q0.z * f1.x + q0.w * f1.y;
                    acc += q1.x * f2.x + q1.y * f2.y + q1.z * f3.x + q1.w * f3.y;
                }
                score = acc * 0.125f;
            }
            sp[hq * 192 + kk] = score;
        }
    }
    __syncthreads();
    {
        int w = t >> 5, lane = t & 31;
        if (w < 4) {
            float m = -1e30f;
            for (int kk = lane; kk < 192; kk += 32) m = fmaxf(m, sp[w * 192 + kk]);
            for (int o = 16; o; o >>= 1) m = fmaxf(m, __shfl_xor_sync(~0u, m, o));
            float sum = 0.f;
            for (int kk = lane; kk < 192; kk += 32) {
                float e = __expf(sp[w * 192 + kk] - m);
                sp[w * 192 + kk] = e;
                sum += e;
            }
            for (int o = 16; o; o >>= 1) sum += __shfl_xor_sync(~0u, sum, o);
            float inv = 1.f / sum;
            for (int kk = lane; kk < 192; kk += 32) sp[w * 192 + kk] *= inv;
        }
    }
    __syncthreads();
    {
        int part = t >> 7, r = t & 127;
        int hq = r >> 5, d2 = r & 31;
        float ax = 0.f, ay = 0.f;
        const __half2* vp = (const __half2*)svh;
        const float* pr = sp + hq * 192 + part * 96;
#pragma unroll 4
        for (int kk = 0; kk < 96; kk += 4) {
            float4 p = *(const float4*)&pr[kk];
            int kbase2 = (part * 96 + kk) * 32 + d2;
            float2 v0 = __half22float2(vp[kbase2]);
            float2 v1 = __half22float2(vp[kbase2 + 32]);
            float2 v2 = __half22float2(vp[kbase2 + 64]);
            float2 v3 = __half22float2(vp[kbase2 + 96]);
            ax += p.x * v0.x + p.y * v1.x + p.z * v2.x + p.w * v3.x;
            ay += p.x * v0.y + p.y * v1.y + p.z * v2.y + p.w * v3.y;
        }
        spart[(part * 128 + r) * 2] = ax;
        spart[(part * 128 + r) * 2 + 1] = ay;
    }
    __syncthreads();
    if (t < 128) {
        int hq = t >> 5, d2 = t & 31;
        float ox = spart[t * 2] + spart[(128 + t) * 2];
        float oy = spart[t * 2 + 1] + spart[(128 + t) * 2 + 1];
        *(float2*)&g_scratch[OFF_FOUT + (((size_t)(b * 8 + g * 4 + hq) * 2048 + i) * 64 + d2 * 2)] =
            make_float2(ox, oy);
    }
}

// ---------------- sliding attention: fp16 mma, registers-resident scores ------
// smem bytes: Ph[64][272] @0 (34816) | KV[256][72] @34816 (36864, K then V)
//             | Qh[64][72] @71680 (9216) | red[64][8] @80896 (2048)
//             | gmax[64] @82944 (256) | gsum[64] @83200 (256)   total 83456
#define SLIDE_SMEM 83456
extern __shared__ char ssm3[];
__global__ void __launch_bounds__(256, 2) k_slide() {
    const int PH = 0, KV = 34816, QS = 71680, RED = 80896, GMX = 82944, GSM = 83200;
    uint32_t sb = smem_u32(ssm3);
    __half* sKV = (__half*)(ssm3 + KV);
    __half* sQh = (__half*)(ssm3 + QS);
    __half* sPh = (__half*)(ssm3 + PH);
    float* red = (float*)(ssm3 + RED);
    float* gmax = (float*)(ssm3 + GMX);
    float* gsum = (float*)(ssm3 + GSM);
    int id = blockIdx.x;
    int qc = id & 3;
    int tile = (id >> 2) & 7;
    int hh = (id >> 5) & 7;
    int b = id >> 8;
    int g = hh >> 2;
    int t = threadIdx.x, wid = t >> 5, lane = t & 31;
    size_t kbase = ((size_t)(b * 2 + g) * 2048 + (size_t)tile * 256) * 64;
    size_t qbase = (((size_t)(b * 8 + hh) * 2048) + tile * 256 + qc * 64) * 64;
    const uint4* QH4 = (const uint4*)(g_scratch + OFF_QH);
    const uint4* KRH4 = (const uint4*)(g_scratch + OFF_KRH);
    const uint4* VH4 = (const uint4*)(g_scratch + OFF_VH);
    // stage Q (64x64 half) and K (256x64 half)
    for (int u = t; u < 512; u += 256) {
        int row = u >> 3, d8 = u & 7;
        *(uint4*)(sQh + row * 72 + d8 * 8) = QH4[(qbase >> 3) + u];
    }
    for (int u = t; u < 2048; u += 256) {
        int row = u >> 3, d8 = u & 7;
        *(uint4*)(sKV + row * 72 + d8 * 8) = KRH4[(kbase >> 3) + u];
    }
    __syncthreads();
    // QK: warp wid -> kk chunk [wid*32, wid*32+32); scores stay in registers
    float acc[4][4][4];
#pragma unroll
    for (int mt = 0; mt < 4; mt++)
#pragma unroll
        for (int nt = 0; nt < 4; nt++)
#pragma unroll
            for (int e = 0; e < 4; e++) acc[mt][nt][e] = 0.f;
    {
        int a_row = lane & 15, a_kc8 = 8 * (lane >> 4);
        int row_in = lane & 7, khalf = (lane >> 3) & 1, ntl = lane >> 4;
#pragma unroll
        for (int ks = 0; ks < 4; ks++) {
            uint32_t af[4][4], bf[4][2];
#pragma unroll
            for (int mt = 0; mt < 4; mt++)
                ldsm_x4(af[mt][0], af[mt][1], af[mt][2], af[mt][3],
                        sb + QS + ((mt * 16 + a_row) * 72 + ks * 16 + a_kc8) * 2);
#pragma unroll
            for (int n2 = 0; n2 < 2; n2++) {
                uint32_t addr = sb + KV +
                    ((wid * 32 + n2 * 16 + ntl * 8 + row_in) * 72 + ks * 16 + khalf * 8) * 2;
                ldsm_x4(bf[n2 * 2][0], bf[n2 * 2][1], bf[n2 * 2 + 1][0], bf[n2 * 2 + 1][1], addr);
            }
#pragma unroll
            for (int mt = 0; mt < 4; mt++)
#pragma unroll
                for (int nt = 0; nt < 4; nt++)
                    mma16816h(acc[mt][nt], af[mt][0], af[mt][1], af[mt][2], af[mt][3],
                              bf[nt][0], bf[nt][1]);
        }
    }
    // softmax pass 1: row maxima (raw scores; scale folded into exp later)
    int r0 = lane >> 2, c0 = (lane & 3) * 2;
#pragma unroll
    for (int mt = 0; mt < 4; mt++) {
        float ma = -1e30f, mb = -1e30f;
#pragma unroll
        for (int nt = 0; nt < 4; nt++) {
            ma = fmaxf(ma, fmaxf(acc[mt][nt][0], acc[mt][nt][1]));
            mb = fmaxf(mb, fmaxf(acc[mt][nt][2], acc[mt][nt][3]));
        }
        ma = fmaxf(ma, __shfl_xor_sync(~0u, ma, 1));
        ma = fmaxf(ma, __shfl_xor_sync(~0u, ma, 2));
        mb = fmaxf(mb, __shfl_xor_sync(~0u, mb, 1));
        mb = fmaxf(mb, __shfl_xor_sync(~0u, mb, 2));
        if ((lane & 3) == 0) {
            red[(mt * 16 + r0) * 8 + wid] = ma;
            red[(mt * 16 + 8 + r0) * 8 + wid] = mb;
        }
    }
    __syncthreads();
    if (t < 64) {
        float m = -1e30f;
#pragma unroll
        for (int w = 0; w < 8; w++) m = fmaxf(m, red[t * 8 + w]);
        gmax[t] = m;
    }
    __syncthreads();
    // softmax pass 2: exp, partial sums, write Ph (unnormalized)
#pragma unroll
    for (int mt = 0; mt < 4; mt++) {
        int qa = mt * 16 + r0, qb = qa + 8;
        float ma = gmax[qa], mb = gmax[qb];
        float sa = 0.f, sb2 = 0.f;
#pragma unroll
        for (int nt = 0; nt < 4; nt++) {
            int kk0 = wid * 32 + nt * 8 + c0;
            float e0 = __expf((acc[mt][nt][0] - ma) * 0.125f);
            float e1 = __expf((acc[mt][nt][1] - ma) * 0.125f);
            float e2 = __expf((acc[mt][nt][2] - mb) * 0.125f);
            float e3 = __expf((acc[mt][nt][3] - mb) * 0.125f);
            sa += e0 + e1;
            sb2 += e2 + e3;
            *(__half2*)&sPh[qa * 272 + kk0] = __floats2half2_rn(e0, e1);
            *(__half2*)&sPh[qb * 272 + kk0] = __floats2half2_rn(e2, e3);
        }
        sa += __shfl_xor_sync(~0u, sa, 1);
        sa += __shfl_xor_sync(~0u, sa, 2);
        sb2 += __shfl_xor_sync(~0u, sb2, 1);
        sb2 += __shfl_xor_sync(~0u, sb2, 2);
        if ((lane & 3) == 0) {
            red[qa * 8 + wid] = sa;
            red[qb * 8 + wid] = sb2;
        }
    }
    __syncthreads();
    if (t < 64) {
        float s = 0.f;
#pragma unroll
        for (int w = 0; w < 8; w++) s += red[t * 8 + w];
        gsum[t] = 1.f / s;
    }
    // stage V into the K region (K fully consumed)
    for (int u = t; u < 2048; u += 256) {
        int row = u >> 3, d8 = u & 7;
        *(uint4*)(sKV + row * 72 + d8 * 8) = VH4[(kbase >> 3) + u];
    }
    __syncthreads();
    // PV: warp_m = wid>>2 (2 x 32 q), warp_n = wid&3 (4 x 16 d)
    {
        int warp_m = wid >> 2, warp_n = wid & 3;
        int a_row = lane & 15, a_kc8 = 8 * (lane >> 4);
        int b_krow = lane & 15, b_n8 = 8 * (lane >> 4);
        float acc2[2][2][4];
#pragma unroll
        for (int mt = 0; mt < 2; mt++)
#pragma unroll
            for (int nt = 0; nt < 2; nt++)
#pragma unroll
                for (int e = 0; e < 4; e++) acc2[mt][nt][e] = 0.f;
#pragma unroll
        for (int kc = 0; kc < 16; kc++) {
            uint32_t afr[2][4], bfr[2][2];
#pragma unroll
            for (int mt = 0; mt < 2; mt++)
                ldsm_x4(afr[mt][0], afr[mt][1], afr[mt][2], afr[mt][3],
                        sb + PH + (((warp_m * 2 + mt) * 16 + a_row) * 272 + kc * 16 + a_kc8) * 2);
            ldsm_x4t(bfr[0][0], bfr[0][1], bfr[1][0], bfr[1][1],
                     sb + KV + ((kc * 16 + b_krow) * 72 + warp_n * 16 + b_n8) * 2);
#pragma unroll
            for (int mt = 0; mt < 2; mt++)
#pragma unroll
                for (int nt = 0; nt < 2; nt++)
                    mma16816h(acc2[mt][nt], afr[mt][0], afr[mt][1], afr[mt][2], afr[mt][3],
                              bfr[nt][0], bfr[nt][1]);
        }
#pragma unroll
        for (int mt = 0; mt < 2; mt++) {
            int q = (warp_m * 2 + mt) * 16 + r0;
            float inv_a = gsum[q], inv_b = gsum[q + 8];
#pragma unroll
            for (int nt = 0; nt < 2; nt++) {
                int d = warp_n * 16 + nt * 8 + c0;
                *(float2*)&g_scratch[OFF_SOUT + qbase + (size_t)q * 64 + d] =
                    make_float2(acc2[mt][nt][0] * inv_a, acc2[mt][nt][1] * inv_a);
                *(float2*)&g_scratch[OFF_SOUT + qbase + (size_t)(q + 8) * 64 + d] =
                    make_float2(acc2[mt][nt][2] * inv_b, acc2[mt][nt][3] * inv_b);
            }
        }
    }
}

// ---------------- gates: 16 rows per block, Wg register-cached ----------------
__global__ void __launch_bounds__(256) k_gates(const float* __restrict__ Wg,
                                               const float* __restrict__ bgv) {
    __shared__ float sx[16 * 512];
    int r0 = blockIdx.x * 16;
    int t = threadIdx.x;
    for (int u = t; u < 8192; u += 256)
        sx[u] = g_scratch[OFF_INP + (size_t)r0 * 512 + u];
    __syncthreads();
    int w = t >> 5, lane = t & 31;
    for (int o = w; o < 24; o += 8) {
        float wreg[16];
#pragma unroll
        for (int j = 0; j < 16; j++) wreg[j] = Wg[(size_t)(lane + j * 32) * 24 + o];
        float bo = bgv[o];
#pragma unroll
        for (int row = 0; row < 16; row++) {
            float acc = 0.f;
            const float* xr = sx + row * 512 + lane;
#pragma unroll
            for (int j = 0; j < 16; j++) acc += wreg[j] * xr[j * 32];
            for (int off = 16; off; off >>= 1) acc += __shfl_xor_sync(~0u, acc, off);
            if (lane == 0)
                g_scratch[OFF_GATES + (size_t)(r0 + row) * 24 + o] =
                    1.f / (1.f + __expf(-(acc + bo)));
        }
    }
}

// ---------------- combine (bf16 hi/lo output) ----------------
__global__ void k_combine() {
    int pid = blockIdx.x * blockDim.x + threadIdx.x;
    if (pid >= 1048576) return;
    int idx0 = pid * 2;
    int d = idx0 & 63;
    int hh = (idx0 >> 6) & 7;
    int ri = idx0 >> 9;
    int b = ri >> 11, i = ri & 2047;
    size_t hidx = (((size_t)(b * 8 + hh) * 2048 + i) * 64 + d);
    const float* gg = g_scratch + OFF_GATES + (size_t)ri * 24 + hh * 3;
    float o0 = gg[0] * g_scratch[OFF_COUT + hidx] + gg[1] * g_scratch[OFF_FOUT + hidx] +
               gg[2] * g_scratch[OFF_SOUT + hidx];
    float o1 = gg[0] * g_scratch[OFF_COUT + hidx + 1] + gg[1] * g_scratch[OFF_FOUT + hidx + 1] +
               gg[2] * g_scratch[OFF_SOUT + hidx + 1];
    uint32_t hp, lp;
    bf_split_pack(o0, o1, hp, lp);
    ((uint32_t*)(g_scratch + OFF_COMB_HI))[pid] = hp;
    ((uint32_t*)(g_scratch + OFF_COMB_LO))[pid] = lp;
}

// ---------------- host ----------------
extern "C" void kernel_launch(void* const* d_in, const int* in_sizes, int n_in,
                              void* d_out, int out_size) {
    const float* x     = (const float*)d_in[0];
    const float* pos   = (const float*)d_in[1];
    const float* pe_W  = (const float*)d_in[2];
    const float* pe_b  = (const float*)d_in[3];
    const float* nsc   = (const float*)d_in[4];
    const float* Wqkv  = (const float*)d_in[5];
    const float* k_pos = (const float*)d_in[6];
    const float* v_pos = (const float*)d_in[7];
    const float* kcW1  = (const float*)d_in[8];
    const float* kcb1  = (const float*)d_in[9];
    const float* kcW2  = (const float*)d_in[10];
    const float* kcb2  = (const float*)d_in[11];
    const float* vcW1  = (const float*)d_in[12];
    const float* vcb1  = (const float*)d_in[13];
    const float* vcW2  = (const float*)d_in[14];
    const float* vcb2  = (const float*)d_in[15];
    const float* mem_k = (const float*)d_in[16];
    const float* mem_v = (const float*)d_in[17];
    const float* Wg    = (const float*)d_in[18];
    const float* bgv   = (const float*)d_in[19];
    const float* Wo    = (const float*)d_in[20];
    float* out = (float*)d_out;

    float* S = nullptr;
    cudaGetSymbolAddress((void**)&S, g_scratch);
    const uint16_t* WQKV_HI = (const uint16_t*)(S + OFF_WQKV_HI);
    const uint16_t* WQKV_LO = (const uint16_t*)(S + OFF_WQKV_LO);
    const uint16_t* WOHI    = (const uint16_t*)(S + OFF_WO_HI);
    const uint16_t* WOLO    = (const uint16_t*)(S + OFF_WO_LO);
    const uint16_t* INP_HI  = (const uint16_t*)(S + OFF_INP_HI);
    const uint16_t* INP_LO  = (const uint16_t*)(S + OFF_INP_LO);
    const uint16_t* KBM_HI  = (const uint16_t*)(S + OFF_KBM_HI);
    const uint16_t* KBM_LO  = (const uint16_t*)(S + OFF_KBM_LO);
    const uint16_t* VBM_HI  = (const uint16_t*)(S + OFF_VBM_HI);
    const uint16_t* VBM_LO  = (const uint16_t*)(S + OFF_VBM_LO);
    const uint16_t* COMB_HI = (const uint16_t*)(S + OFF_COMB_HI);
    const uint16_t* COMB_LO = (const uint16_t*)(S + OFF_COMB_LO);

    cudaFuncSetAttribute(k_fine, cudaFuncAttributeMaxDynamicSharedMemorySize, FINE_SMEM);
    cudaFuncSetAttribute(k_slide, cudaFuncAttributeMaxDynamicSharedMemorySize, SLIDE_SMEM);
    cudaFuncSetAttribute(k_c2, cudaFuncAttributeMaxDynamicSharedMemorySize, C2_SMEM);
    cudaFuncSetAttribute(k_mgemm<2>, cudaFuncAttributeMaxDynamicSharedMemorySize, MG_SMEM2);
    cudaFuncSetAttribute(k_wgemm, cudaFuncAttributeMaxDynamicSharedMemorySize, WG_SMEM);

    k_cvtw<<<640, 256>>>(Wqkv, Wo);
    k_posmean<<<64, 64>>>(pos);
    k_pe_norm<<<4096, 256>>>(x, pos, pe_W, pe_b, nsc);

    // qkv = inp @ Wqkv : M=4096 N=768 K=512  (launch #4 -> ncu capture)
    k_mgemm<2><<<dim3(12, 32, 1), 256, MG_SMEM2>>>(INP_HI, INP_LO, WQKV_HI, WQKV_LO, S + OFF_QKV,
                                                   768, 512, 512, 1);
    k_split_rope<<<4096, 384>>>();
    k_buildmats<<<1024, 256>>>(k_pos, v_pos);

    // fused kc1+vc1, split-K 4, fp32 weights converted in-kernel
    k_wgemm<<<dim3(32, 1, 8), 256, WG_SMEM>>>(KBM_HI, KBM_LO, kcW1, S + OFF_PART,
                                              VBM_HI, VBM_LO, vcW1, S + OFF_PART + 2097152,
                                              4096, 4096, 1024, 4);
    k_c1red<<<1024, 256>>>(kcb1, vcb1);
    k_c2<<<64, 256, C2_SMEM>>>(kcW2, kcb2, vcW2, vcb2);
    k_pack<<<(8448 + 255) / 256, 256>>>(mem_k, mem_v);

    k_coarse<<<8192, 128>>>();
    k_topk<<<32, 256>>>();
    k_fine<<<8192, 256, FINE_SMEM>>>();
    k_slide<<<512, 256, SLIDE_SMEM>>>();
    k_gates<<<256, 256>>>(Wg, bgv);
    k_combine<<<4096, 256>>>();

    // out = comb @ Wo : M=4096 N=512 K=512
    k_mgemm<2><<<dim3(8, 32, 1), 256, MG_SMEM2>>>(COMB_HI, COMB_LO, WOHI, WOLO, out,
                                                  512, 512, 512, 1);
}

// round 16
// speedup vs baseline: 1.1957x; 1.0029x over previous
#include <cuda_runtime.h>
#include <cuda_bf16.h>
#include <cuda_fp16.h>
#include <math.h>
#include <stdint.h>

// ---------------- scratch layout (floats) ----------------
#define OFF_INP      0ul
#define OFF_QKV      2097152ul
#define OFF_Q        5242880ul
#define OFF_K        7340032ul
#define OFF_KRH      7864320ul
#define OFF_VH       8126464ul
#define OFF_V        8388608ul
#define OFF_KHID     8912896ul
#define OFF_VHID     9437184ul
#define OFF_CKRAW    9961472ul
#define OFF_CVRAW    9969664ul
#define OFF_CK       9977856ul
#define OFF_CV       9986304ul
#define OFF_COUT     9994752ul
#define OFF_FOUT    12091904ul
#define OFF_SOUT    14189056ul
#define OFF_IMP     16286208ul
#define OFF_SELVAL  16548352ul
#define OFF_GATES   16564736ul
#define OFF_PM      16663040ul
#define OFF_PART    16663296ul
#define OFF_WQKV_HI 20857600ul
#define OFF_WQKV_LO 21054208ul
#define OFF_WO_HI   21250816ul
#define OFF_WO_LO   21381888ul
#define OFF_INP_HI  21512960ul
#define OFF_INP_LO  22561536ul
#define OFF_KBM_HI  23610112ul
#define OFF_KBM_LO  23872256ul
#define OFF_VBM_HI  24134400ul
#define OFF_VBM_LO  24396544ul
#define OFF_COMB_HI 24658688ul
#define OFF_COMB_LO 25707264ul
#define OFF_QH      26755840ul
#define SCRATCH_SZ  27804416ul

__device__ float g_scratch[SCRATCH_SZ];
__device__ int   g_selidx[2 * 2 * 2048 * 2];

// ================= helpers ============
__device__ __forceinline__ uint32_t smem_u32(const void* p) {
    uint32_t a;
    asm("{ .reg .u64 tmp; cvta.to.shared.u64 tmp, %1; cvt.u32.u64 %0, tmp; }"
        : "=r"(a) : "l"(p));
    return a;
}
__device__ __forceinline__ void ldsm_x4(uint32_t& r0, uint32_t& r1, uint32_t& r2, uint32_t& r3,
                                        uint32_t addr) {
    asm volatile("ldmatrix.sync.aligned.m8n8.x4.shared.b16 {%0,%1,%2,%3}, [%4];"
                 : "=r"(r0), "=r"(r1), "=r"(r2), "=r"(r3) : "r"(addr));
}
__device__ __forceinline__ void ldsm_x4t(uint32_t& r0, uint32_t& r1, uint32_t& r2, uint32_t& r3,
                                         uint32_t addr) {
    asm volatile("ldmatrix.sync.aligned.m8n8.x4.trans.shared.b16 {%0,%1,%2,%3}, [%4];"
                 : "=r"(r0), "=r"(r1), "=r"(r2), "=r"(r3) : "r"(addr));
}
__device__ __forceinline__ void mma16816(float* c, uint32_t a0, uint32_t a1, uint32_t a2,
                                         uint32_t a3, uint32_t b0, uint32_t b1) {
    asm volatile("mma.sync.aligned.m16n8k16.row.col.f32.bf16.bf16.f32 "
                 "{%0,%1,%2,%3}, {%4,%5,%6,%7}, {%8,%9}, {%0,%1,%2,%3};"
                 : "+f"(c[0]), "+f"(c[1]), "+f"(c[2]), "+f"(c[3])
                 : "r"(a0), "r"(a1), "r"(a2), "r"(a3), "r"(b0), "r"(b1));
}
__device__ __forceinline__ void mma16816h(float* c, uint32_t a0, uint32_t a1, uint32_t a2,
                                          uint32_t a3, uint32_t b0, uint32_t b1) {
    asm volatile("mma.sync.aligned.m16n8k16.row.col.f32.f16.f16.f32 "
                 "{%0,%1,%2,%3}, {%4,%5,%6,%7}, {%8,%9}, {%0,%1,%2,%3};"
                 : "+f"(c[0]), "+f"(c[1]), "+f"(c[2]), "+f"(c[3])
                 : "r"(a0), "r"(a1), "r"(a2), "r"(a3), "r"(b0), "r"(b1));
}
__device__ __forceinline__ void bf_split_pack(float x0, float x1, uint32_t& hp, uint32_t& lp) {
    uint32_t u0 = __float_as_uint(x0), u1 = __float_as_uint(x1);
    hp = __byte_perm(u0, u1, 0x7632);
    float l0 = x0 - __uint_as_float(u0 & 0xFFFF0000u);
    float l1 = x1 - __uint_as_float(u1 & 0xFFFF0000u);
    asm("cvt.rn.bf16x2.f32 %0, %1, %2;" : "=r"(lp) : "f"(l1), "f"(l0));
}
__device__ __forceinline__ void cp16(uint32_t s, const void* g) {
    asm volatile("cp.async.cg.shared.global [%0], [%1], 16;" :: "r"(s), "l"(g));
}

// ---------------- weight conversion (Wqkv + Wo only) ----------------
__global__ void k_cvtw(const float* __restrict__ Wqkv, const float* __restrict__ Wo) {
    size_t q = (size_t)blockIdx.x * 256 + threadIdx.x;
    if (q >= 163840ul) return;
    const float* src;
    uint32_t *hi, *lo;
    size_t local;
    if (q < 98304ul) {
        src = Wqkv; local = q;
        hi = (uint32_t*)(g_scratch + OFF_WQKV_HI); lo = (uint32_t*)(g_scratch + OFF_WQKV_LO);
    } else {
        src = Wo; local = q - 98304ul;
        hi = (uint32_t*)(g_scratch + OFF_WO_HI); lo = (uint32_t*)(g_scratch + OFF_WO_LO);
    }
    float4 v = ((const float4*)src)[local];
    uint32_t h0, l0, h1, l1;
    bf_split_pack(v.x, v.y, h0, l0);
    bf_split_pack(v.z, v.w, h1, l1);
    ((uint2*)hi)[local] = make_uint2(h0, h1);
    ((uint2*)lo)[local] = make_uint2(l0, l1);
}

// ======== 3-stage cp.async pipelined bf16x3 MMA GEMM (NTILES=2, single sync) ====
#define APAD 40
extern __shared__ uint16_t mgs[];
template <int NTILES>
__global__ void __launch_bounds__(256, 2)
k_mgemm(const uint16_t* __restrict__ Ahi0, const uint16_t* __restrict__ Alo0,
        const uint16_t* __restrict__ Bhi0, const uint16_t* __restrict__ Blo0,
        float* __restrict__ C0,
        int N, int K, int klen, int nchunks) {
    constexpr int BN = NTILES * 32;
    constexpr int BPADT = BN + 8;
    constexpr int BOFF = 10240;
    constexpr int BLO = BOFF + 32 * BPADT;
    constexpr int BUF = BLO + 32 * BPADT;
    uint32_t sb = smem_u32(mgs);
    int chunk = blockIdx.z;
    float* C = C0 + (size_t)chunk * gridDim.y * 128 * N;
    int kstart = chunk * klen;
    int t = threadIdx.x, wid = t >> 5, lane = t & 31;
    int bx = blockIdx.x, by = blockIdx.y;
    int warp_m = wid >> 2, warp_n = wid & 3;

    float acc[4][NTILES][4];
#pragma unroll
    for (int mt = 0; mt < 4; mt++)
#pragma unroll
        for (int nt = 0; nt < NTILES; nt++)
#pragma unroll
            for (int e = 0; e < 4; e++) acc[mt][nt][e] = 0.f;

    int a_row = (lane & 15), a_kc8 = 8 * (lane >> 4);
    int b_krow = (lane & 15), b_n8 = 8 * (lane >> 4);
    int nch = klen / 32;
    const uint16_t* Ah = Ahi0 + (size_t)(by * 128) * K + kstart;
    const uint16_t* Al = Alo0 + (size_t)(by * 128) * K + kstart;
    const uint16_t* Bh = Bhi0 + (size_t)kstart * N + bx * BN;
    const uint16_t* Bl = Blo0 + (size_t)kstart * N + bx * BN;

    auto stage = [&](int buf, int cc) {
        uint32_t soff = sb + buf * (BUF * 2);
#pragma unroll
        for (int h = 0; h < 2; h++) {
            int u = t + h * 256;
            int row = u >> 2, seg = u & 3;
            size_t go = (size_t)row * K + (size_t)cc * 32 + seg * 8;
            cp16(soff + (row * APAD + seg * 8) * 2, Ah + go);
            cp16(soff + (5120 + row * APAD + seg * 8) * 2, Al + go);
        }
#pragma unroll
        for (int h = 0; h < NTILES / 2; h++) {
            int u = t + h * 256;
            int row, seg;
            if (NTILES == 4) { row = u >> 4; seg = u & 15; }
            else { row = u >> 3; seg = u & 7; }
            size_t go = (size_t)(cc * 32 + row) * N + seg * 8;
            cp16(soff + (BOFF + row * BPADT + seg * 8) * 2, Bh + go);
            cp16(soff + (BLO + row * BPADT + seg * 8) * 2, Bl + go);
        }
        asm volatile("cp.async.commit_group;" ::: "memory");
    };

    stage(0, 0);
    if (nch > 1) stage(1, 1);
    for (int c = 0; c < nch; c++) {
        int buf = c % 3;
        if (c + 1 < nch) {
            asm volatile("cp.async.wait_group 1;" ::: "memory");
        } else {
            asm volatile("cp.async.wait_group 0;" ::: "memory");
        }
        __syncthreads();
        // safe: every warp has passed compute(c-1), the last reader of buffer (c+2)%3
        if (c + 2 < nch) stage((c + 2) % 3, c + 2);
        uint32_t abase = sb + buf * (BUF * 2);
#pragma unroll
        for (int ks = 0; ks < 2; ks++) {
            uint32_t af[4][4], bh[NTILES][2], bl[NTILES][2];
#pragma unroll
            for (int mt = 0; mt < 4; mt++) {
                int off = (warp_m * 64 + mt * 16 + a_row) * APAD + ks * 16 + a_kc8;
                ldsm_x4(af[mt][0], af[mt][1], af[mt][2], af[mt][3], abase + off * 2);
            }
#pragma unroll
            for (int n2 = 0; n2 < NTILES / 2; n2++) {
                int off = BOFF + (ks * 16 + b_krow) * BPADT + warp_n * (NTILES * 8) + n2 * 16 + b_n8;
                ldsm_x4t(bh[n2 * 2][0], bh[n2 * 2][1], bh[n2 * 2 + 1][0], bh[n2 * 2 + 1][1],
                         abase + off * 2);
                ldsm_x4t(bl[n2 * 2][0], bl[n2 * 2][1], bl[n2 * 2 + 1][0], bl[n2 * 2 + 1][1],
                         abase + (off + 32 * BPADT) * 2);
            }
#pragma unroll
            for (int mt = 0; mt < 4; mt++)
#pragma unroll
                for (int nt = 0; nt < NTILES; nt++) {
                    mma16816(acc[mt][nt], af[mt][0], af[mt][1], af[mt][2], af[mt][3],
                             bh[nt][0], bh[nt][1]);
                    mma16816(acc[mt][nt], af[mt][0], af[mt][1], af[mt][2], af[mt][3],
                             bl[nt][0], bl[nt][1]);
                }
#pragma unroll
            for (int mt = 0; mt < 4; mt++) {
                int off = 5120 + (warp_m * 64 + mt * 16 + a_row) * APAD + ks * 16 + a_kc8;
                ldsm_x4(af[mt][0], af[mt][1], af[mt][2], af[mt][3], abase + off * 2);
            }
#pragma unroll
            for (int mt = 0; mt < 4; mt++)
#pragma unroll
                for (int nt = 0; nt < NTILES; nt++)
                    mma16816(acc[mt][nt], af[mt][0], af[mt][1], af[mt][2], af[mt][3],
                             bh[nt][0], bh[nt][1]);
        }
    }
    int g = lane >> 2, tid4 = lane & 3;
#pragma unroll
    for (int mt = 0; mt < 4; mt++) {
        int row0 = by * 128 + warp_m * 64 + mt * 16 + g;
#pragma unroll
        for (int nt = 0; nt < NTILES; nt++) {
            int col = bx * BN + warp_n * (NTILES * 8) + nt * 8 + tid4 * 2;
            *(float2*)&C[(size_t)row0 * N + col] = make_float2(acc[mt][nt][0], acc[mt][nt][1]);
            *(float2*)&C[(size_t)(row0 + 8) * N + col] = make_float2(acc[mt][nt][2], acc[mt][nt][3]);
        }
    }
}
#define MG_SMEM2 (3 * (10240 + 2 * 32 * 72) * 2)

// ======== c1 GEMM: A preconv bf16 (cp.async), B fp32 (cp.async + smem convert) ====
#define WG_BPADT 136
#define WG_BOFF  10240
#define WG_BLO   (WG_BOFF + 32 * WG_BPADT)
#define WG_BUF   (WG_BLO + 32 * WG_BPADT)
#define WG_SLOT0 (2 * WG_BUF * 2)
#define WG_SMEM  (WG_SLOT0 + 2 * 16384)
extern __shared__ uint16_t wgs[];
__global__ void __launch_bounds__(256, 2)
k_wgemm(const uint16_t* __restrict__ Ahi0, const uint16_t* __restrict__ Alo0,
        const float* __restrict__ Bf0, float* __restrict__ C0,
        const uint16_t* __restrict__ Ahi1, const uint16_t* __restrict__ Alo1,
        const float* __restrict__ Bf1, float* __restrict__ C1,
        int N, int K, int klen, int nchunks) {
    uint32_t sb = smem_u32(wgs);
    int z = blockIdx.z;
    int comp = z / nchunks, chunk = z - comp * nchunks;
    const uint16_t* Ahi = comp ? Ahi1 : Ahi0;
    const uint16_t* Alo = comp ? Alo1 : Alo0;
    const float* Bf = comp ? Bf1 : Bf0;
    float* C = (comp ? C1 : C0) + (size_t)chunk * 128 * N;
    int kstart = chunk * klen;
    int t = threadIdx.x, wid = t >> 5, lane = t & 31;
    int bx = blockIdx.x;
    int warp_m = wid >> 2, warp_n = wid & 3;

    float acc[4][4][4];
#pragma unroll
    for (int mt = 0; mt < 4; mt++)
#pragma unroll
        for (int nt = 0; nt < 4; nt++)
#pragma unroll
            for (int e = 0; e < 4; e++) acc[mt][nt][e] = 0.f;

    int a_row = (lane & 15), a_kc8 = 8 * (lane >> 4);
    int b_krow = (lane & 15), b_n8 = 8 * (lane >> 4);
    int nch = klen / 32;
    const uint16_t* Ah = Ahi + kstart;
    const uint16_t* Al = Alo + kstart;
    const float* Bb = Bf + (size_t)kstart * N + bx * 128;

    auto stageA = [&](int buf, int cc) {
        uint32_t soff = sb + buf * (WG_BUF * 2);
#pragma unroll
        for (int h = 0; h < 2; h++) {
            int u = t + h * 256;
            int row = u >> 2, seg = u & 3;
            size_t go = (size_t)row * K + (size_t)cc * 32 + seg * 8;
            cp16(soff + (row * APAD + seg * 8) * 2, Ah + go);
            cp16(soff + (5120 + row * APAD + seg * 8) * 2, Al + go);
        }
    };
    auto stageB = [&](int buf, int cc) {
        uint32_t soff = sb + WG_SLOT0 + buf * 16384;
#pragma unroll
        for (int h = 0; h < 4; h++) {
            int u = t + h * 256;
            int row = u >> 5, seg = u & 31;
            cp16(soff + u * 16, Bb + (size_t)(cc * 32 + row) * N + seg * 4);
        }
    };

    stageA(0, 0);
    stageB(0, 0);
    asm volatile("cp.async.commit_group;" ::: "memory");
    for (int c = 0; c < nch; c++) {
        int buf = c & 1;
        asm volatile("cp.async.wait_group 0;" ::: "memory");
        __syncthreads();
        {
            const float2* slot = (const float2*)((char*)wgs + WG_SLOT0 + buf * 16384);
            char* bufp = (char*)wgs + buf * (WG_BUF * 2);
#pragma unroll
            for (int p = 0; p < 8; p++) {
                int u2 = t + p * 256;
                int row = u2 >> 6, c2 = u2 & 63;
                float2 v = slot[u2];
                uint32_t hp, lp;
                bf_split_pack(v.x, v.y, hp, lp);
                *(uint32_t*)(bufp + (WG_BOFF + row * WG_BPADT + c2 * 2) * 2) = hp;
                *(uint32_t*)(bufp + (WG_BLO + row * WG_BPADT + c2 * 2) * 2) = lp;
            }
        }
        __syncthreads();
        if (c + 1 < nch) {
            stageA(buf ^ 1, c + 1);
            stageB(buf ^ 1, c + 1);
            asm volatile("cp.async.commit_group;" ::: "memory");
        }
        uint32_t abase = sb + buf * (WG_BUF * 2);
#pragma unroll
        for (int ks = 0; ks < 2; ks++) {
            uint32_t af[4][4], bh[4][2], bl[4][2];
#pragma unroll
            for (int mt = 0; mt < 4; mt++) {
                int off = (warp_m * 64 + mt * 16 + a_row) * APAD + ks * 16 + a_kc8;
                ldsm_x4(af[mt][0], af[mt][1], af[mt][2], af[mt][3], abase + off * 2);
            }
#pragma unroll
            for (int n2 = 0; n2 < 2; n2++) {
                int off = WG_BOFF + (ks * 16 + b_krow) * WG_BPADT + warp_n * 32 + n2 * 16 + b_n8;
                ldsm_x4t(bh[n2 * 2][0], bh[n2 * 2][1], bh[n2 * 2 + 1][0], bh[n2 * 2 + 1][1],
                         abase + off * 2);
                ldsm_x4t(bl[n2 * 2][0], bl[n2 * 2][1], bl[n2 * 2 + 1][0], bl[n2 * 2 + 1][1],
                         abase + (off + 32 * WG_BPADT) * 2);
            }
#pragma unroll
            for (int mt = 0; mt < 4; mt++)
#pragma unroll
                for (int nt = 0; nt < 4; nt++) {
                    mma16816(acc[mt][nt], af[mt][0], af[mt][1], af[mt][2], af[mt][3],
                             bh[nt][0], bh[nt][1]);
                    mma16816(acc[mt][nt], af[mt][0], af[mt][1], af[mt][2], af[mt][3],
                             bl[nt][0], bl[nt][1]);
                }
#pragma unroll
            for (int mt = 0; mt < 4; mt++) {
                int off = 5120 + (warp_m * 64 + mt * 16 + a_row) * APAD + ks * 16 + a_kc8;
                ldsm_x4(af[mt][0], af[mt][1], af[mt][2], af[mt][3], abase + off * 2);
            }
#pragma unroll
            for (int mt = 0; mt < 4; mt++)
#pragma unroll
                for (int nt = 0; nt < 4; nt++)
                    mma16816(acc[mt][nt], af[mt][0], af[mt][1], af[mt][2], af[mt][3],
                             bh[nt][0], bh[nt][1]);
        }
        __syncthreads();
    }
    int g = lane >> 2, tid4 = lane & 3;
#pragma unroll
    for (int mt = 0; mt < 4; mt++) {
        int row0 = warp_m * 64 + mt * 16 + g;
#pragma unroll
        for (int nt = 0; nt < 4; nt++) {
            int col = bx * 128 + warp_n * 32 + nt * 8 + tid4 * 2;
            *(float2*)&C[(size_t)row0 * N + col] = make_float2(acc[mt][nt][0], acc[mt][nt][1]);
            *(float2*)&C[(size_t)(row0 + 8) * N + col] = make_float2(acc[mt][nt][2], acc[mt][nt][3]);
        }
    }
}

// ---------------- c1 split-K reduce + bias + relu ----------------
__global__ void k_c1red(const float* __restrict__ kcb1, const float* __restrict__ vcb1) {
    int u4 = blockIdx.x * 256 + threadIdx.x;
    int comp = u4 >> 17;
    int loc = u4 & 131071;
    int col4 = loc & 1023;
    const float* P = g_scratch + OFF_PART + (size_t)comp * 2097152 + (size_t)loc * 4;
    float4 s0 = *(const float4*)(P);
    float4 s1 = *(const float4*)(P + 524288);
    float4 s2 = *(const float4*)(P + 1048576);
    float4 s3 = *(const float4*)(P + 1572864);
    const float* bias = comp ? vcb1 : kcb1;
    float4 b = *(const float4*)&bias[col4 * 4];
    float4 o;
    o.x = fmaxf(s0.x + s1.x + s2.x + s3.x + b.x, 0.f);
    o.y = fmaxf(s0.y + s1.y + s2.y + s3.y + b.y, 0.f);
    o.z = fmaxf(s0.z + s1.z + s2.z + s3.z + b.z, 0.f);
    o.w = fmaxf(s0.w + s1.w + s2.w + s3.w + b.w, 0.f);
    float* O = g_scratch + (comp ? OFF_VHID : OFF_KHID) + (size_t)loc * 4;
    *(float4*)O = o;
}

// ---------------- pos block means ----------------
__global__ void k_posmean(const float* __restrict__ pos) {
    int blk = blockIdx.x;
    int t = threadIdx.x;
    __shared__ float s[64 * 3];
    s[t * 3 + 0] = pos[(blk * 64 + t) * 3 + 0];
    s[t * 3 + 1] = pos[(blk * 64 + t) * 3 + 1];
    s[t * 3 + 2] = pos[(blk * 64 + t) * 3 + 2];
    __syncthreads();
    if (t < 3) {
        float sum = 0.f;
        for (int i = 0; i < 64; i++) sum += s[i * 3 + t];
        g_scratch[OFF_PM + blk * 3 + t] = sum / 64.f;
    }
}

// ---------------- PE add + RMSNorm (+ bf16 hi/lo output) ----------------
__global__ void k_pe_norm(const float* __restrict__ x, const float* __restrict__ pos,
                          const float* __restrict__ peW, const float* __restrict__ peb,
                          const float* __restrict__ nsc) {
    int r = blockIdx.x;
    int t = threadIdx.x;
    int blk = r >> 6;
    float r0 = pos[r * 3 + 0] - g_scratch[OFF_PM + blk * 3 + 0];
    float r1 = pos[r * 3 + 1] - g_scratch[OFF_PM + blk * 3 + 1];
    float r2 = pos[r * 3 + 2] - g_scratch[OFF_PM + blk * 3 + 2];
    int c0 = t * 2, c1 = c0 + 1;
    float v0 = x[(size_t)r * 512 + c0] + r0 * peW[c0] + r1 * peW[512 + c0] + r2 * peW[1024 + c0] + peb[c0];
    float v1 = x[(size_t)r * 512 + c1] + r0 * peW[c1] + r1 * peW[512 + c1] + r2 * peW[1024 + c1] + peb[c1];
    __shared__ float red[256];
    red[t] = v0 * v0 + v1 * v1;
    __syncthreads();
    for (int s = 128; s > 0; s >>= 1) {
        if (t < s) red[t] += red[t + s];
        __syncthreads();
    }
    float rms = rsqrtf(red[0] / 512.f + 1e-6f);
    float s0 = v0 * rms * nsc[c0];
    float s1 = v1 * rms * nsc[c1];
    g_scratch[OFF_INP + (size_t)r * 512 + c0] = s0;
    g_scratch[OFF_INP + (size_t)r * 512 + c1] = s1;
    uint32_t hp, lp;
    bf_split_pack(s0, s1, hp, lp);
    ((uint32_t*)(g_scratch + OFF_INP_HI))[(size_t)r * 256 + t] = hp;
    ((uint32_t*)(g_scratch + OFF_INP_LO))[(size_t)r * 256 + t] = lp;
}

// ---------------- c2: 4 rows per block (64 blocks) ----------------
#define C2_SMEM ((16384 + 1024) * 4)
extern __shared__ float c2sm[];
__global__ void k_c2(const float* __restrict__ kcW2, const float* __restrict__ kcb2,
                     const float* __restrict__ vcW2, const float* __restrict__ vcb2) {
    float* sa = c2sm;
    float* red = c2sm + 16384;
    int blk = blockIdx.x;
    int comp = blk >> 5, rg = blk & 31;
    const float* A = g_scratch + (comp ? OFF_VHID : OFF_KHID) + (size_t)(rg * 4) * 4096;
    const float* W = comp ? vcW2 : kcW2;
    const float* bias = comp ? vcb2 : kcb2;
    float* Cout = g_scratch + (comp ? OFF_CVRAW : OFF_CKRAW) + (size_t)(rg * 4) * 64;
    int t = threadIdx.x;
    for (int u = t; u < 16384; u += 256) {
        int r = u >> 12, kk = u & 4095;
        sa[kk * 4 + r] = A[(size_t)r * 4096 + kk];
    }
    __syncthreads();
    int o = t & 63, sub = t >> 6;
    const float* Wp = W + (size_t)(sub * 1024) * 64 + o;
    float acc0 = 0.f, acc1 = 0.f, acc2 = 0.f, acc3 = 0.f;
    const float* ap = sa + sub * 1024 * 4;
#pragma unroll 4
    for (int kk = 0; kk < 1024; kk++) {
        float w = Wp[(size_t)kk * 64];
        float4 a = *(const float4*)(ap + kk * 4);
        acc0 += a.x * w; acc1 += a.y * w; acc2 += a.z * w; acc3 += a.w * w;
    }
    red[t * 4 + 0] = acc0; red[t * 4 + 1] = acc1;
    red[t * 4 + 2] = acc2; red[t * 4 + 3] = acc3;
    __syncthreads();
    if (t < 64) {
        float b = bias[t];
#pragma unroll
        for (int r = 0; r < 4; r++) {
            float v = red[t * 4 + r] + red[(64 + t) * 4 + r] + red[(128 + t) * 4 + r] +
                      red[(192 + t) * 4 + r] + b;
            Cout[r * 64 + t] = v;
        }
    }
}

// ---------------- split qkv + rope (+ half Q) ----------------
__global__ void k_split_rope() {
    int r = blockIdx.x;
    int b = r >> 11;
    int i = r & 2047;
    int t = threadIdx.x;          // 384
    const float* qkv = g_scratch + OFF_QKV + (size_t)r * 768;
    if (t < 256) {
        int col = t * 2;
        int head = col >> 6, d = col & 63, j = d >> 1;
        float inv = powf(10000.f, -(float)j / 32.f);
        float cs, sn;
        sincosf((float)i * inv, &sn, &cs);
        float a = qkv[col], bb = qkv[col + 1];
        float o0 = a * cs - bb * sn;
        float o1 = bb * cs + a * sn;
        size_t base = (((size_t)(b * 8 + head) * 2048 + i) * 64 + d);
        g_scratch[OFF_Q + base] = o0;
        g_scratch[OFF_Q + base + 1] = o1;
        ((__half2*)(g_scratch + OFF_QH))[base >> 1] = __floats2half2_rn(o0, o1);
    } else if (t < 320) {
        int ci = (t - 256) * 2;
        int g = ci >> 6, d = ci & 63, j = d >> 1;
        float inv = powf(10000.f, -(float)j / 32.f);
        float cs, sn;
        sincosf((float)i * inv, &sn, &cs);
        float a = qkv[512 + ci], bb = qkv[512 + ci + 1];
        size_t base = (((size_t)(b * 2 + g) * 2048 + i) * 64 + d);
        g_scratch[OFF_K + base] = a;
        g_scratch[OFF_K + base + 1] = bb;
        float kr0 = a * cs - bb * sn;
        float kr1 = bb * cs + a * sn;
        ((__half2*)(g_scratch + OFF_KRH))[base >> 1] = __floats2half2_rn(kr0, kr1);
    } else {
        int ci = (t - 320) * 2;
        int g = ci >> 6, d = ci & 63;
        size_t base = (((size_t)(b * 2 + g) * 2048 + i) * 64 + d);
        float v0 = qkv[640 + ci], v1 = qkv[640 + ci + 1];
        g_scratch[OFF_V + base] = v0;
        g_scratch[OFF_V + base + 1] = v1;
        ((__half2*)(g_scratch + OFF_VH))[base >> 1] = __floats2half2_rn(v0, v1);
    }
}

// ---------------- build compressor inputs (bf16 hi/lo) ----------------
__global__ void k_buildmats(const float* __restrict__ k_pos, const float* __restrict__ v_pos) {
    int pid = blockIdx.x * blockDim.x + threadIdx.x;
    if (pid >= 262144) return;
    int row = pid >> 11;
    int pcol = pid & 2047;
    int col0 = pcol * 2;
    int bg = row >> 5, wi = row & 31, g = bg & 1;
    int j = col0 >> 6, d = col0 & 63;
    size_t src = ((size_t)bg * 2048 + wi * 64 + j) * 64 + d;
    int poff = (g * 64 + j) * 64 + d;
    float k0 = g_scratch[OFF_K + src] + k_pos[poff];
    float k1 = g_scratch[OFF_K + src + 1] + k_pos[poff + 1];
    float w0 = g_scratch[OFF_V + src] + v_pos[poff];
    float w1 = g_scratch[OFF_V + src + 1] + v_pos[poff + 1];
    uint32_t hp, lp;
    bf_split_pack(k0, k1, hp, lp);
    ((uint32_t*)(g_scratch + OFF_KBM_HI))[pid] = hp;
    ((uint32_t*)(g_scratch + OFF_KBM_LO))[pid] = lp;
    bf_split_pack(w0, w1, hp, lp);
    ((uint32_t*)(g_scratch + OFF_VBM_HI))[pid] = hp;
    ((uint32_t*)(g_scratch + OFF_VBM_LO))[pid] = lp;
}

// ---------------- pack ck/cv with mem token ----------------
__global__ void k_pack(const float* __restrict__ mem_k, const float* __restrict__ mem_v) {
    int idx = blockIdx.x * blockDim.x + threadIdx.x;
    if (idx >= 2 * 2 * 33 * 64) return;
    int d = idx & 63;
    int rest = idx >> 6;
    int j = rest % 33;
    int bg = rest / 33;
    int g = bg & 1;
    float kv, vv;
    if (j == 0) {
        kv = mem_k[g * 64 + d];
        vv = mem_v[g * 64 + d];
    } else {
        size_t s = ((size_t)bg * 32 + (j - 1)) * 64 + d;
        kv = g_scratch[OFF_CKRAW + s];
        vv = g_scratch[OFF_CVRAW + s];
    }
    g_scratch[OFF_CK + idx] = kv;
    g_scratch[OFF_CV + idx] = vv;
}

// ---------------- coarse attention + importance (per-query) ----------
__global__ void k_coarse() {
    int bi = blockIdx.x;
    int bg = bi >> 11, i = bi & 2047;
    int b = bg >> 1, g = bg & 1;
    int t = threadIdx.x;          // 128
    __shared__ float sck[33 * 64], scv[33 * 64], sq[4 * 64], sp[4 * 36];
    for (int u = t; u < 528; u += 128) {
        *(float4*)&sck[u * 4] = *(const float4*)&g_scratch[OFF_CK + (size_t)bg * 2112 + u * 4];
        *(float4*)&scv[u * 4] = *(const float4*)&g_scratch[OFF_CV + (size_t)bg * 2112 + u * 4];
    }
    for (int u = t; u < 256; u += 128) {
        int hq = u >> 6, d = u & 63;
        sq[u] = g_scratch[OFF_Q + (((size_t)(b * 8 + g * 4 + hq) * 2048 + i) * 64 + d)];
    }
    __syncthreads();
    for (int u = t; u < 132; u += 128) {
        int hq = u / 33, j = u % 33;
        float s = -1e30f;
        if (j == 0 || j * 64 <= i) {
            float acc = 0.f;
            const float4* qv = (const float4*)&sq[hq * 64];
            const float4* kv = (const float4*)&sck[j * 64];
#pragma unroll
            for (int d4 = 0; d4 < 16; d4++) {
                float4 a = qv[d4], bb = kv[d4];
                acc += a.x * bb.x + a.y * bb.y + a.z * bb.z + a.w * bb.w;
            }
            s = acc * 0.125f;
        }
        sp[hq * 36 + j] = s;
    }
    __syncthreads();
    if (t < 4) {
        float m = -1e30f;
        for (int j = 0; j < 33; j++) m = fmaxf(m, sp[t * 36 + j]);
        float sum = 0.f;
        for (int j = 0; j < 33; j++) {
            float e = __expf(sp[t * 36 + j] - m);
            sp[t * 36 + j] = e;
            sum += e;
        }
        float inv = 1.f / sum;
        for (int j = 0; j < 33; j++) sp[t * 36 + j] *= inv;
    }
    __syncthreads();
    if (t < 32) {
        g_scratch[OFF_IMP + ((size_t)bg * 2048 + i) * 32 + t] =
            0.25f * (sp[t + 1] + sp[36 + t + 1] + sp[72 + t + 1] + sp[108 + t + 1]);
    }
    for (int u = t; u < 256; u += 128) {
        int hq = u >> 6, d = u & 63;
        float acc = 0.f;
#pragma unroll
        for (int j4 = 0; j4 < 8; j4++) {
            float4 p = *(const float4*)&sp[hq * 36 + j4 * 4];
            acc += p.x * scv[(j4 * 4 + 0) * 64 + d] + p.y * scv[(j4 * 4 + 1) * 64 + d] +
                   p.z * scv[(j4 * 4 + 2) * 64 + d] + p.w * scv[(j4 * 4 + 3) * 64 + d];
        }
        acc += sp[hq * 36 + 32] * scv[32 * 64 + d];
        g_scratch[OFF_COUT + (((size_t)(b * 8 + g * 4 + hq) * 2048 + i) * 64 + d)] = acc;
    }
}

// ---------------- top-k (k=2, stable) ----------------
__global__ void k_topk() {
    int idx = blockIdx.x * blockDim.x + threadIdx.x;
    if (idx >= 8192) return;
    const float* imp = g_scratch + OFF_IMP + (size_t)idx * 32;
    int i1 = 0;
    float v1 = imp[0];
    for (int j = 1; j < 32; j++)
        if (imp[j] > v1) { v1 = imp[j]; i1 = j; }
    int i2 = -1;
    float v2 = -1e30f;
    for (int j = 0; j < 32; j++) {
        if (j == i1) continue;
        if (imp[j] > v2) { v2 = imp[j]; i2 = j; }
    }
    g_scratch[OFF_SELVAL + idx * 2 + 0] = v1;
    g_scratch[OFF_SELVAL + idx * 2 + 1] = v2;
    g_selidx[idx * 2 + 0] = i1;
    g_selidx[idx * 2 + 1] = i2;
}

// ---------------- fine gathered attention (fp16 smem, reg-cached Q) ----------
#define FINE_SMEM (13824 * 4)
extern __shared__ float fsm[];
__global__ void __launch_bounds__(256, 2) k_fine() {
    __half* skh = (__half*)fsm;
    __half* svh = (__half*)(fsm + 6144);
    float* sq = fsm + 12288;
    float* sp = fsm + 12544;
    float* spart = fsm + 13312;
    int bi = blockIdx.x;
    int bg = bi >> 11, i = bi & 2047;
    int b = bg >> 1, g = bg & 1;
    int t = threadIdx.x;
    int own = i >> 6;
    __shared__ int blkid[3];
    __shared__ int okf[3];
    if (t < 2) {
        int si = g_selidx[bi * 2 + t];
        float sval = g_scratch[OFF_SELVAL + bi * 2 + t];
        blkid[t] = si;
        okf[t] = (sval > 0.f && si != own) ? 1 : 0;
    }
    if (t == 2) { blkid[2] = own; okf[2] = 1; }
    __syncthreads();
    size_t kbase = (size_t)bg * 2048 * 64;
    const uint4* KRH4 = (const uint4*)(g_scratch + OFF_KRH);
    const uint4* VH4 = (const uint4*)(g_scratch + OFF_VH);
#pragma unroll
    for (int u = t; u < 1536; u += 256) {
        int kk = u >> 3, d8 = u & 7;
        int kb = kk >> 6, j = kk & 63;
        size_t elem = kbase + (size_t)(blkid[kb] * 64 + j) * 64 + d8 * 8;
        ((uint4*)skh)[u] = KRH4[elem >> 3];
        ((uint4*)svh)[u] = VH4[elem >> 3];
    }
    {
        int hq = t >> 6, d = t & 63;
        sq[t] = g_scratch[OFF_Q + (((size_t)(b * 8 + g * 4 + hq) * 2048 + i) * 64 + d)];
    }
    __syncthreads();
    {
        int hq = t >> 6, j0 = t & 63;
        float4 qv[16];
        const float4* qsm = (const float4*)&sq[hq * 64];
#pragma unroll
        for (int p = 0; p < 16; p++) qv[p] = qsm[p];
        int ilocal = i & 63;
#pragma unroll
        for (int s = 0; s < 3; s++) {
            int kk = s * 64 + j0;
            bool valid = (s < 2) ? (okf[s] != 0) : (j0 <= ilocal);
            float score = -1e30f;
            if (valid) {
                float acc = 0.f;
                const uint4* kp = (const uint4*)(skh + kk * 64);
#pragma unroll
                for (int p = 0; p < 8; p++) {
                    uint4 raw = kp[p];
                    float2 f0 = __half22float2(*(__half2*)&raw.x);
                    float2 f1 = __half22float2(*(__half2*)&raw.y);
                    float2 f2 = __half22float2(*(__half2*)&raw.z);
                    float2 f3 = __half22float2(*(__half2*)&raw.w);
                    float4 q0 = qv[p * 2], q1 = qv[p * 2 + 1];
                    acc += q0.x * f0.x + q0.y * f0.y + q0.z * f1.x + q0.w * f1.y;
                    acc += q1.x * f2.x + q1.y * f2.y + q1.z * f3.x + q1.w * f3.y;
                }
                score = acc * 0.125f;
            }
            sp[hq * 192 + kk] = score;
        }
    }
    __syncthreads();
    {
        int w = t >> 5, lane = t & 31;
        if (w < 4) {
            float m = -1e30f;
            for (int kk = lane; kk < 192; kk += 32) m = fmaxf(m, sp[w * 192 + kk]);
            for (int o = 16; o; o >>= 1) m = fmaxf(m, __shfl_xor_sync(~0u, m, o));
            float sum = 0.f;
            for (int kk = lane; kk < 192; kk += 32) {
                float e = __expf(sp[w * 192 + kk] - m);
                sp[w * 192 + kk] = e;
                sum += e;
            }
            for (int o = 16; o; o >>= 1) sum += __shfl_xor_sync(~0u, sum, o);
            float inv = 1.f / sum;
            for (int kk = lane; kk < 192; kk += 32) sp[w * 192 + kk] *= inv;
        }
    }
    __syncthreads();
    {
        int part = t >> 7, r = t & 127;
        int hq = r >> 5, d2 = r & 31;
        float ax = 0.f, ay = 0.f;
        const __half2* vp = (const __half2*)svh;
        const float* pr = sp + hq * 192 + part * 96;
#pragma unroll 4
        for (int kk = 0; kk < 96; kk += 4) {
            float4 p = *(const float4*)&pr[kk];
            int kbase2 = (part * 96 + kk) * 32 + d2;
            float2 v0 = __half22float2(vp[kbase2]);
            float2 v1 = __half22float2(vp[kbase2 + 32]);
            float2 v2 = __half22float2(vp[kbase2 + 64]);
            float2 v3 = __half22float2(vp[kbase2 + 96]);
            ax += p.x * v0.x + p.y * v1.x + p.z * v2.x + p.w * v3.x;
            ay += p.x * v0.y + p.y * v1.y + p.z * v2.y + p.w * v3.y;
        }
        spart[(part * 128 + r) * 2] = ax;
        spart[(part * 128 + r) * 2 + 1] = ay;
    }
    __syncthreads();
    if (t < 128) {
        int hq = t >> 5, d2 = t & 31;
        float ox = spart[t * 2] + spart[(128 + t) * 2];
        float oy = spart[t * 2 + 1] + spart[(128 + t) * 2 + 1];
        *(float2*)&g_scratch[OFF_FOUT + (((size_t)(b * 8 + g * 4 + hq) * 2048 + i) * 64 + d2 * 2)] =
            make_float2(ox, oy);
    }
}

// ---------------- sliding attention: fp16 mma, registers-resident scores ------
#define SLIDE_SMEM 83456
extern __shared__ char ssm3[];
__global__ void __launch_bounds__(256, 2) k_slide() {
    const int PH = 0, KV = 34816, QS = 71680, RED = 80896, GMX = 82944, GSM = 83200;
    uint32_t sb = smem_u32(ssm3);
    __half* sKV = (__half*)(ssm3 + KV);
    __half* sQh = (__half*)(ssm3 + QS);
    __half* sPh = (__half*)(ssm3 + PH);
    float* red = (float*)(ssm3 + RED);
    float* gmax = (float*)(ssm3 + GMX);
    float* gsum = (float*)(ssm3 + GSM);
    int id = blockIdx.x;
    int qc = id & 3;
    int tile = (id >> 2) & 7;
    int hh = (id >> 5) & 7;
    int b = id >> 8;
    int g = hh >> 2;
    int t = threadIdx.x, wid = t >> 5, lane = t & 31;
    size_t kbase = ((size_t)(b * 2 + g) * 2048 + (size_t)tile * 256) * 64;
    size_t qbase = (((size_t)(b * 8 + hh) * 2048) + tile * 256 + qc * 64) * 64;
    const uint4* QH4 = (const uint4*)(g_scratch + OFF_QH);
    const uint4* KRH4 = (const uint4*)(g_scratch + OFF_KRH);
    const uint4* VH4 = (const uint4*)(g_scratch + OFF_VH);
    for (int u = t; u < 512; u += 256) {
        int row = u >> 3, d8 = u & 7;
        *(uint4*)(sQh + row * 72 + d8 * 8) = QH4[(qbase >> 3) + u];
    }
    for (int u = t; u < 2048; u += 256) {
        int row = u >> 3, d8 = u & 7;
        *(uint4*)(sKV + row * 72 + d8 * 8) = KRH4[(kbase >> 3) + u];
    }
    __syncthreads();
    float acc[4][4][4];
#pragma unroll
    for (int mt = 0; mt < 4; mt++)
#pragma unroll
        for (int nt = 0; nt < 4; nt++)
#pragma unroll
            for (int e = 0; e < 4; e++) acc[mt][nt][e] = 0.f;
    {
        int a_row = lane & 15, a_kc8 = 8 * (lane >> 4);
        int row_in = lane & 7, khalf = (lane >> 3) & 1, ntl = lane >> 4;
#pragma unroll
        for (int ks = 0; ks < 4; ks++) {
            uint32_t af[4][4], bf[4][2];
#pragma unroll
            for (int mt = 0; mt < 4; mt++)
                ldsm_x4(af[mt][0], af[mt][1], af[mt][2], af[mt][3],
                        sb + QS + ((mt * 16 + a_row) * 72 + ks * 16 + a_kc8) * 2);
#pragma unroll
            for (int n2 = 0; n2 < 2; n2++) {
                uint32_t addr = sb + KV +
                    ((wid * 32 + n2 * 16 + ntl * 8 + row_in) * 72 + ks * 16 + khalf * 8) * 2;
                ldsm_x4(bf[n2 * 2][0], bf[n2 * 2][1], bf[n2 * 2 + 1][0], bf[n2 * 2 + 1][1], addr);
            }
#pragma unroll
            for (int mt = 0; mt < 4; mt++)
#pragma unroll
                for (int nt = 0; nt < 4; nt++)
                    mma16816h(acc[mt][nt], af[mt][0], af[mt][1], af[mt][2], af[mt][3],
                              bf[nt][0], bf[nt][1]);
        }
    }
    int r0 = lane >> 2, c0 = (lane & 3) * 2;
#pragma unroll
    for (int mt = 0; mt < 4; mt++) {
        float ma = -1e30f, mb = -1e30f;
#pragma unroll
        for (int nt = 0; nt < 4; nt++) {
            ma = fmaxf(ma, fmaxf(acc[mt][nt][0], acc[mt][nt][1]));
            mb = fmaxf(mb, fmaxf(acc[mt][nt][2], acc[mt][nt][3]));
        }
        ma = fmaxf(ma, __shfl_xor_sync(~0u, ma, 1));
        ma = fmaxf(ma, __shfl_xor_sync(~0u, ma, 2));
        mb = fmaxf(mb, __shfl_xor_sync(~0u, mb, 1));
        mb = fmaxf(mb, __shfl_xor_sync(~0u, mb, 2));
        if ((lane & 3) == 0) {
            red[(mt * 16 + r0) * 8 + wid] = ma;
            red[(mt * 16 + 8 + r0) * 8 + wid] = mb;
        }
    }
    __syncthreads();
    if (t < 64) {
        float m = -1e30f;
#pragma unroll
        for (int w = 0; w < 8; w++) m = fmaxf(m, red[t * 8 + w]);
        gmax[t] = m;
    }
    __syncthreads();
#pragma unroll
    for (int mt = 0; mt < 4; mt++) {
        int qa = mt * 16 + r0, qb = qa + 8;
        float ma = gmax[qa], mb = gmax[qb];
        float sa = 0.f, sb2 = 0.f;
#pragma unroll
        for (int nt = 0; nt < 4; nt++) {
            int kk0 = wid * 32 + nt * 8 + c0;
            float e0 = __expf((acc[mt][nt][0] - ma) * 0.125f);
            float e1 = __expf((acc[mt][nt][1] - ma) * 0.125f);
            float e2 = __expf((acc[mt][nt][2] - mb) * 0.125f);
            float e3 = __expf((acc[mt][nt][3] - mb) * 0.125f);
            sa += e0 + e1;
            sb2 += e2 + e3;
            *(__half2*)&sPh[qa * 272 + kk0] = __floats2half2_rn(e0, e1);
            *(__half2*)&sPh[qb * 272 + kk0] = __floats2half2_rn(e2, e3);
        }
        sa += __shfl_xor_sync(~0u, sa, 1);
        sa += __shfl_xor_sync(~0u, sa, 2);
        sb2 += __shfl_xor_sync(~0u, sb2, 1);
        sb2 += __shfl_xor_sync(~0u, sb2, 2);
        if ((lane & 3) == 0) {
            red[qa * 8 + wid] = sa;
            red[qb * 8 + wid] = sb2;
        }
    }
    __syncthreads();
    if (t < 64) {
        float s = 0.f;
#pragma unroll
        for (int w = 0; w < 8; w++) s += red[t * 8 + w];
        gsum[t] = 1.f / s;
    }
    for (int u = t; u < 2048; u += 256) {
        int row = u >> 3, d8 = u & 7;
        *(uint4*)(sKV + row * 72 + d8 * 8) = VH4[(kbase >> 3) + u];
    }
    __syncthreads();
    {
        int warp_m = wid >> 2, warp_n = wid & 3;
        int a_row = lane & 15, a_kc8 = 8 * (lane >> 4);
        int b_krow = lane & 15, b_n8 = 8 * (lane >> 4);
        float acc2[2][2][4];
#pragma unroll
        for (int mt = 0; mt < 2; mt++)
#pragma unroll
            for (int nt = 0; nt < 2; nt++)
#pragma unroll
                for (int e = 0; e < 4; e++) acc2[mt][nt][e] = 0.f;
#pragma unroll
        for (int kc = 0; kc < 16; kc++) {
            uint32_t afr[2][4], bfr[2][2];
#pragma unroll
            for (int mt = 0; mt < 2; mt++)
                ldsm_x4(afr[mt][0], afr[mt][1], afr[mt][2], afr[mt][3],
                        sb + PH + (((warp_m * 2 + mt) * 16 + a_row) * 272 + kc * 16 + a_kc8) * 2);
            ldsm_x4t(bfr[0][0], bfr[0][1], bfr[1][0], bfr[1][1],
                     sb + KV + ((kc * 16 + b_krow) * 72 + warp_n * 16 + b_n8) * 2);
#pragma unroll
            for (int mt = 0; mt < 2; mt++)
#pragma unroll
                for (int nt = 0; nt < 2; nt++)
                    mma16816h(acc2[mt][nt], afr[mt][0], afr[mt][1], afr[mt][2], afr[mt][3],
                              bfr[nt][0], bfr[nt][1]);
        }
#pragma unroll
        for (int mt = 0; mt < 2; mt++) {
            int q = (warp_m * 2 + mt) * 16 + r0;
            float inv_a = gsum[q], inv_b = gsum[q + 8];
#pragma unroll
            for (int nt = 0; nt < 2; nt++) {
                int d = warp_n * 16 + nt * 8 + c0;
                *(float2*)&g_scratch[OFF_SOUT + qbase + (size_t)q * 64 + d] =
                    make_float2(acc2[mt][nt][0] * inv_a, acc2[mt][nt][1] * inv_a);
                *(float2*)&g_scratch[OFF_SOUT + qbase + (size_t)(q + 8) * 64 + d] =
                    make_float2(acc2[mt][nt][2] * inv_b, acc2[mt][nt][3] * inv_b);
            }
        }
    }
}

// ---------------- gates: 16 rows per block, Wg register-cached ----------------
__global__ void __launch_bounds__(256) k_gates(const float* __restrict__ Wg,
                                               const float* __restrict__ bgv) {
    __shared__ float sx[16 * 512];
    int r0 = blockIdx.x * 16;
    int t = threadIdx.x;
    for (int u = t; u < 8192; u += 256)
        sx[u] = g_scratch[OFF_INP + (size_t)r0 * 512 + u];
    __syncthreads();
    int w = t >> 5, lane = t & 31;
    for (int o = w; o < 24; o += 8) {
        float wreg[16];
#pragma unroll
        for (int j = 0; j < 16; j++) wreg[j] = Wg[(size_t)(lane + j * 32) * 24 + o];
        float bo = bgv[o];
#pragma unroll
        for (int row = 0; row < 16; row++) {
            float acc = 0.f;
            const float* xr = sx + row * 512 + lane;
#pragma unroll
            for (int j = 0; j < 16; j++) acc += wreg[j] * xr[j * 32];
            for (int off = 16; off; off >>= 1) acc += __shfl_xor_sync(~0u, acc, off);
            if (lane == 0)
                g_scratch[OFF_GATES + (size_t)(r0 + row) * 24 + o] =
                    1.f / (1.f + __expf(-(acc + bo)));
        }
    }
}

// ---------------- combine (bf16 hi/lo output) ----------------
__global__ void k_combine() {
    int pid = blockIdx.x * blockDim.x + threadIdx.x;
    if (pid >= 1048576) return;
    int idx0 = pid * 2;
    int d = idx0 & 63;
    int hh = (idx0 >> 6) & 7;
    int ri = idx0 >> 9;
    int b = ri >> 11, i = ri & 2047;
    size_t hidx = (((size_t)(b * 8 + hh) * 2048 + i) * 64 + d);
    const float* gg = g_scratch + OFF_GATES + (size_t)ri * 24 + hh * 3;
    float o0 = gg[0] * g_scratch[OFF_COUT + hidx] + gg[1] * g_scratch[OFF_FOUT + hidx] +
               gg[2] * g_scratch[OFF_SOUT + hidx];
    float o1 = gg[0] * g_scratch[OFF_COUT + hidx + 1] + gg[1] * g_scratch[OFF_FOUT + hidx + 1] +
               gg[2] * g_scratch[OFF_SOUT + hidx + 1];
    uint32_t hp, lp;
    bf_split_pack(o0, o1, hp, lp);
    ((uint32_t*)(g_scratch + OFF_COMB_HI))[pid] = hp;
    ((uint32_t*)(g_scratch + OFF_COMB_LO))[pid] = lp;
}

// ---------------- host ----------------
extern "C" void kernel_launch(void* const* d_in, const int* in_sizes, int n_in,
                              void* d_out, int out_size) {
    const float* x     = (const float*)d_in[0];
    const float* pos   = (const float*)d_in[1];
    const float* pe_W  = (const float*)d_in[2];
    const float* pe_b  = (const float*)d_in[3];
    const float* nsc   = (const float*)d_in[4];
    const float* Wqkv  = (const float*)d_in[5];
    const float* k_pos = (const float*)d_in[6];
    const float* v_pos = (const float*)d_in[7];
    const float* kcW1  = (const float*)d_in[8];
    const float* kcb1  = (const float*)d_in[9];
    const float* kcW2  = (const float*)d_in[10];
    const float* kcb2  = (const float*)d_in[11];
    const float* vcW1  = (const float*)d_in[12];
    const float* vcb1  = (const float*)d_in[13];
    const float* vcW2  = (const float*)d_in[14];
    const float* vcb2  = (const float*)d_in[15];
    const float* mem_k = (const float*)d_in[16];
    const float* mem_v = (const float*)d_in[17];
    const float* Wg    = (const float*)d_in[18];
    const float* bgv   = (const float*)d_in[19];
    const float* Wo    = (const float*)d_in[20];
    float* out = (float*)d_out;

    float* S = nullptr;
    cudaGetSymbolAddress((void**)&S, g_scratch);
    const uint16_t* WQKV_HI = (const uint16_t*)(S + OFF_WQKV_HI);
    const uint16_t* WQKV_LO = (const uint16_t*)(S + OFF_WQKV_LO);
    const uint16_t* WOHI    = (const uint16_t*)(S + OFF_WO_HI);
    const uint16_t* WOLO    = (const uint16_t*)(S + OFF_WO_LO);
    const uint16_t* INP_HI  = (const uint16_t*)(S + OFF_INP_HI);
    const uint16_t* INP_LO  = (const uint16_t*)(S + OFF_INP_LO);
    const uint16_t* KBM_HI  = (const uint16_t*)(S + OFF_KBM_HI);
    const uint16_t* KBM_LO  = (const uint16_t*)(S + OFF_KBM_LO);
    const uint16_t* VBM_HI  = (const uint16_t*)(S + OFF_VBM_HI);
    const uint16_t* VBM_LO  = (const uint16_t*)(S + OFF_VBM_LO);
    const uint16_t* COMB_HI = (const uint16_t*)(S + OFF_COMB_HI);
    const uint16_t* COMB_LO = (const uint16_t*)(S + OFF_COMB_LO);

    cudaFuncSetAttribute(k_fine, cudaFuncAttributeMaxDynamicSharedMemorySize, FINE_SMEM);
    cudaFuncSetAttribute(k_slide, cudaFuncAttributeMaxDynamicSharedMemorySize, SLIDE_SMEM);
    cudaFuncSetAttribute(k_c2, cudaFuncAttributeMaxDynamicSharedMemorySize, C2_SMEM);
    cudaFuncSetAttribute(k_mgemm<2>, cudaFuncAttributeMaxDynamicSharedMemorySize, MG_SMEM2);
    cudaFuncSetAttribute(k_wgemm, cudaFuncAttributeMaxDynamicSharedMemorySize, WG_SMEM);

    k_cvtw<<<640, 256>>>(Wqkv, Wo);
    k_posmean<<<64, 64>>>(pos);
    k_pe_norm<<<4096, 256>>>(x, pos, pe_W, pe_b, nsc);

    // qkv = inp @ Wqkv : M=4096 N=768 K=512  (launch #4 -> ncu capture)
    k_mgemm<2><<<dim3(12, 32, 1), 256, MG_SMEM2>>>(INP_HI, INP_LO, WQKV_HI, WQKV_LO, S + OFF_QKV,
                                                   768, 512, 512, 1);
    k_split_rope<<<4096, 384>>>();
    k_buildmats<<<1024, 256>>>(k_pos, v_pos);

    // fused kc1+vc1, split-K 4, fp32 weights converted in-kernel
    k_wgemm<<<dim3(32, 1, 8), 256, WG_SMEM>>>(KBM_HI, KBM_LO, kcW1, S + OFF_PART,
                                              VBM_HI, VBM_LO, vcW1, S + OFF_PART + 2097152,
                                              4096, 4096, 1024, 4);
    k_c1red<<<1024, 256>>>(kcb1, vcb1);
    k_c2<<<64, 256, C2_SMEM>>>(kcW2, kcb2, vcW2, vcb2);
    k_pack<<<(8448 + 255) / 256, 256>>>(mem_k, mem_v);

    k_coarse<<<8192, 128>>>();
    k_topk<<<32, 256>>>();
    k_fine<<<8192, 256, FINE_SMEM>>>();
    k_slide<<<512, 256, SLIDE_SMEM>>>();
    k_gates<<<256, 256>>>(Wg, bgv);
    k_combine<<<4096, 256>>>();

    // out = comb @ Wo : M=4096 N=512 K=512
    k_mgemm<2><<<dim3(8, 32, 1), 256, MG_SMEM2>>>(COMB_HI, COMB_LO, WOHI, WOLO, out,
                                                  512, 512, 512, 1);
}